// round 4
// baseline (speedup 1.0000x reference)
#include <cuda_runtime.h>

#define NB 4
#define NS 2048
#define NF 512
#define NH 8
#define ND 64
#define NFILT 512
#define NM (NB*NS)

typedef unsigned long long u64;

// Scratch (device globals). q,k stored transposed: [B,H,D,S]. v natural: [B,H,S,D].
__device__ float g_q[(size_t)NB*NH*NS*ND];
__device__ float g_k[(size_t)NB*NH*NS*ND];
__device__ float g_v[(size_t)NB*NH*NS*ND];
__device__ float g_concat[(size_t)NB*NS*NH*ND];

// ---- packed f32x2 helpers (FFMA2 path: only reachable via PTX) -------------
__device__ __forceinline__ u64 bc2(float x) {
    u64 r; unsigned xi = __float_as_uint(x);
    asm("mov.b64 %0, {%1, %1};" : "=l"(r) : "r"(xi));
    return r;
}
__device__ __forceinline__ u64 f2(u64 a, u64 b, u64 c) {
    u64 d; asm("fma.rn.f32x2 %0, %1, %2, %3;" : "=l"(d) : "l"(a), "l"(b), "l"(c));
    return d;
}
__device__ __forceinline__ u64 m2(u64 a, u64 b) {
    u64 d; asm("mul.rn.f32x2 %0, %1, %2;" : "=l"(d) : "l"(a), "l"(b));
    return d;
}
__device__ __forceinline__ float2 up2(u64 p) {
    unsigned lo, hi;
    asm("mov.b64 {%0, %1}, %2;" : "=r"(lo), "=r"(hi) : "l"(p));
    return make_float2(__uint_as_float(lo), __uint_as_float(hi));
}

// ---------------------------------------------------------------------------
// Per-head projection GEMM: out = X @ W[h] + bias[h]  (double-buffered smem)
// TRANS=1: write [B,H,D,S] (q,k). TRANS=0: write [B,H,S,D] (v).
// CTA tile 128(M) x 128(N = 2 heads) x 16(K). grid: (NM/128, H/2), block 256
// ---------------------------------------------------------------------------
template<int TRANS>
__global__ __launch_bounds__(256, 2) void proj_kernel(
    const float* __restrict__ X, const float* __restrict__ W,
    const float* __restrict__ bias, float* __restrict__ out)
{
    __shared__ float As[2][16 * 128];
    __shared__ float Bs[2][16 * 128];
    const int tid = threadIdx.x;
    const int w = tid >> 5, lane = tid & 31;
    const int wr = w & 3, wc = w >> 2;
    const int lr = lane >> 3, lc = lane & 7;
    const int row0 = wr * 32 + lr * 8;
    const int col0 = wc * 64 + lc * 8;
    const int m0 = blockIdx.x * 128;
    const int h0 = blockIdx.y * 2;

    const int am = tid & 127;
    const int ak = (tid >> 7) * 8;
    const float* Aptr = X + (size_t)(m0 + am) * NF + ak;
    const int bk = tid >> 4;
    const int bn = (tid & 15) * 8;
    const int bhead = h0 + (bn >> 6);
    const float* Bptr = W + (size_t)bhead * NF * ND + (size_t)bk * ND + (bn & 63);

    float4 a0 = *(const float4*)(Aptr);
    float4 a1 = *(const float4*)(Aptr + 4);
    float4 b0 = *(const float4*)(Bptr);
    float4 b1 = *(const float4*)(Bptr + 4);
    {
        float* A0 = As[0];
        A0[(ak + 0) * 128 + am] = a0.x; A0[(ak + 1) * 128 + am] = a0.y;
        A0[(ak + 2) * 128 + am] = a0.z; A0[(ak + 3) * 128 + am] = a0.w;
        A0[(ak + 4) * 128 + am] = a1.x; A0[(ak + 5) * 128 + am] = a1.y;
        A0[(ak + 6) * 128 + am] = a1.z; A0[(ak + 7) * 128 + am] = a1.w;
        *(float4*)&Bs[0][bk * 128 + bn] = b0;
        *(float4*)&Bs[0][bk * 128 + bn + 4] = b1;
    }
    __syncthreads();

    u64 acc2[8][4] = {};
    int pb = 0;
    for (int k0 = 0; k0 < NF; k0 += 16) {
        const bool more = (k0 + 16 < NF);
        if (more) {
            a0 = *(const float4*)(Aptr + k0 + 16);
            a1 = *(const float4*)(Aptr + k0 + 20);
            b0 = *(const float4*)(Bptr + (size_t)(k0 + 16) * ND);
            b1 = *(const float4*)(Bptr + (size_t)(k0 + 16) * ND + 4);
        }
        const float* Ab = As[pb];
        const float* Bb = Bs[pb];
        #pragma unroll
        for (int kk = 0; kk < 16; kk++) {
            float4 x0 = *(const float4*)&Ab[kk * 128 + row0];
            float4 x1 = *(const float4*)&Ab[kk * 128 + row0 + 4];
            ulonglong2 yA = *(const ulonglong2*)&Bb[kk * 128 + col0];
            ulonglong2 yB = *(const ulonglong2*)&Bb[kk * 128 + col0 + 4];
            u64 yb2[4] = {yA.x, yA.y, yB.x, yB.y};
            float xa[8] = {x0.x, x0.y, x0.z, x0.w, x1.x, x1.y, x1.z, x1.w};
            #pragma unroll
            for (int i = 0; i < 8; i++) {
                u64 xb = bc2(xa[i]);
                #pragma unroll
                for (int jp = 0; jp < 4; jp++)
                    acc2[i][jp] = f2(xb, yb2[jp], acc2[i][jp]);
            }
        }
        if (more) {
            float* An = As[pb ^ 1];
            An[(ak + 0) * 128 + am] = a0.x; An[(ak + 1) * 128 + am] = a0.y;
            An[(ak + 2) * 128 + am] = a0.z; An[(ak + 3) * 128 + am] = a0.w;
            An[(ak + 4) * 128 + am] = a1.x; An[(ak + 5) * 128 + am] = a1.y;
            An[(ak + 6) * 128 + am] = a1.z; An[(ak + 7) * 128 + am] = a1.w;
            *(float4*)&Bs[pb ^ 1][bk * 128 + bn] = b0;
            *(float4*)&Bs[pb ^ 1][bk * 128 + bn + 4] = b1;
            __syncthreads();
            pb ^= 1;
        }
    }
    // unpack + bias
    const int head = h0 + wc;
    const float* bi = bias + head * ND + lc * 8;
    float4 bv0 = *(const float4*)bi;
    float4 bv1 = *(const float4*)(bi + 4);
    float bv[8] = {bv0.x, bv0.y, bv0.z, bv0.w, bv1.x, bv1.y, bv1.z, bv1.w};
    float o[8][8];
    #pragma unroll
    for (int i = 0; i < 8; i++)
        #pragma unroll
        for (int jp = 0; jp < 4; jp++) {
            float2 f = up2(acc2[i][jp]);
            o[i][2 * jp]     = f.x + bv[2 * jp];
            o[i][2 * jp + 1] = f.y + bv[2 * jp + 1];
        }
    const int mm = m0 + row0;
    const int bb = mm / NS, ss = mm % NS;
    if (TRANS) {
        float* ob = out + ((size_t)(bb * NH + head) * ND + lc * 8) * NS + ss;
        #pragma unroll
        for (int j = 0; j < 8; j++) {
            float* oc = ob + (size_t)j * NS;
            *(float4*)(oc)     = make_float4(o[0][j], o[1][j], o[2][j], o[3][j]);
            *(float4*)(oc + 4) = make_float4(o[4][j], o[5][j], o[6][j], o[7][j]);
        }
    } else {
        float* ob = out + ((size_t)(bb * NH + head) * NS + ss) * ND + lc * 8;
        #pragma unroll
        for (int i = 0; i < 8; i++) {
            *(float4*)(ob + (size_t)i * ND) =
                make_float4(o[i][0], o[i][1], o[i][2], o[i][3]);
            *(float4*)(ob + (size_t)i * ND + 4) =
                make_float4(o[i][4], o[i][5], o[i][6], o[i][7]);
        }
    }
}

// ---------------------------------------------------------------------------
// Output GEMM: C = A[NM,512] @ W[512,512] + bias. Tile 128x128x16, dbl-buffered
// ---------------------------------------------------------------------------
__global__ __launch_bounds__(256, 2) void out_gemm(
    const float* __restrict__ A, const float* __restrict__ W,
    const float* __restrict__ bias, float* __restrict__ C)
{
    __shared__ float As[2][16 * 128];
    __shared__ float Bs[2][16 * 128];
    const int tid = threadIdx.x;
    const int w = tid >> 5, lane = tid & 31;
    const int wr = w & 3, wc = w >> 2;
    const int lr = lane >> 3, lc = lane & 7;
    const int row0 = wr * 32 + lr * 8;
    const int col0 = wc * 64 + lc * 8;
    const int m0 = blockIdx.x * 128;
    const int n0 = blockIdx.y * 128;

    const int am = tid & 127;
    const int ak = (tid >> 7) * 8;
    const float* Aptr = A + (size_t)(m0 + am) * NFILT + ak;
    const int bk = tid >> 4;
    const int bn = (tid & 15) * 8;
    const float* Bptr = W + (size_t)bk * NFILT + n0 + bn;

    float4 a0 = *(const float4*)(Aptr);
    float4 a1 = *(const float4*)(Aptr + 4);
    float4 b0 = *(const float4*)(Bptr);
    float4 b1 = *(const float4*)(Bptr + 4);
    {
        float* A0 = As[0];
        A0[(ak + 0) * 128 + am] = a0.x; A0[(ak + 1) * 128 + am] = a0.y;
        A0[(ak + 2) * 128 + am] = a0.z; A0[(ak + 3) * 128 + am] = a0.w;
        A0[(ak + 4) * 128 + am] = a1.x; A0[(ak + 5) * 128 + am] = a1.y;
        A0[(ak + 6) * 128 + am] = a1.z; A0[(ak + 7) * 128 + am] = a1.w;
        *(float4*)&Bs[0][bk * 128 + bn] = b0;
        *(float4*)&Bs[0][bk * 128 + bn + 4] = b1;
    }
    __syncthreads();

    u64 acc2[8][4] = {};
    int pb = 0;
    for (int k0 = 0; k0 < NFILT; k0 += 16) {
        const bool more = (k0 + 16 < NFILT);
        if (more) {
            a0 = *(const float4*)(Aptr + k0 + 16);
            a1 = *(const float4*)(Aptr + k0 + 20);
            b0 = *(const float4*)(Bptr + (size_t)(k0 + 16) * NFILT);
            b1 = *(const float4*)(Bptr + (size_t)(k0 + 16) * NFILT + 4);
        }
        const float* Ab = As[pb];
        const float* Bb = Bs[pb];
        #pragma unroll
        for (int kk = 0; kk < 16; kk++) {
            float4 x0 = *(const float4*)&Ab[kk * 128 + row0];
            float4 x1 = *(const float4*)&Ab[kk * 128 + row0 + 4];
            ulonglong2 yA = *(const ulonglong2*)&Bb[kk * 128 + col0];
            ulonglong2 yB = *(const ulonglong2*)&Bb[kk * 128 + col0 + 4];
            u64 yb2[4] = {yA.x, yA.y, yB.x, yB.y};
            float xa[8] = {x0.x, x0.y, x0.z, x0.w, x1.x, x1.y, x1.z, x1.w};
            #pragma unroll
            for (int i = 0; i < 8; i++) {
                u64 xb = bc2(xa[i]);
                #pragma unroll
                for (int jp = 0; jp < 4; jp++)
                    acc2[i][jp] = f2(xb, yb2[jp], acc2[i][jp]);
            }
        }
        if (more) {
            float* An = As[pb ^ 1];
            An[(ak + 0) * 128 + am] = a0.x; An[(ak + 1) * 128 + am] = a0.y;
            An[(ak + 2) * 128 + am] = a0.z; An[(ak + 3) * 128 + am] = a0.w;
            An[(ak + 4) * 128 + am] = a1.x; An[(ak + 5) * 128 + am] = a1.y;
            An[(ak + 6) * 128 + am] = a1.z; An[(ak + 7) * 128 + am] = a1.w;
            *(float4*)&Bs[pb ^ 1][bk * 128 + bn] = b0;
            *(float4*)&Bs[pb ^ 1][bk * 128 + bn + 4] = b1;
            __syncthreads();
            pb ^= 1;
        }
    }
    const float* bi = bias + n0 + col0;
    float4 bv0 = *(const float4*)bi;
    float4 bv1 = *(const float4*)(bi + 4);
    float bv[8] = {bv0.x, bv0.y, bv0.z, bv0.w, bv1.x, bv1.y, bv1.z, bv1.w};
    float* cb = C + (size_t)(m0 + row0) * NFILT + n0 + col0;
    #pragma unroll
    for (int i = 0; i < 8; i++) {
        float o[8];
        #pragma unroll
        for (int jp = 0; jp < 4; jp++) {
            float2 f = up2(acc2[i][jp]);
            o[2 * jp] = f.x + bv[2 * jp];
            o[2 * jp + 1] = f.y + bv[2 * jp + 1];
        }
        *(float4*)(cb + (size_t)i * NFILT) = make_float4(o[0], o[1], o[2], o[3]);
        *(float4*)(cb + (size_t)i * NFILT + 4) = make_float4(o[4], o[5], o[6], o[7]);
    }
}

// ---------------------------------------------------------------------------
// Flash attention, 512 threads (16 warps, 4x4), 128x128 tiles.
// QK frag: 8 rows x 4 cols (row-packed FFMA2). PV frag: 4 rows x 4 cols
// (col-packed). Softmax row state in parity-buffered smem (Ms/Ls) + Al.
// P stored row-major with swizzle ((r>>2)&7)<<2 -> conflict-free PV loads.
// grid: (NS/128, B*H), block 512
// ---------------------------------------------------------------------------
__global__ __launch_bounds__(512, 1) void attn_kernel(
    const float* __restrict__ qt, const float* __restrict__ kt_,
    const float* __restrict__ v, float* __restrict__ concat)
{
    extern __shared__ float sm[];
    float* Qs   = sm;               // 8192
    float* KP   = sm + 8192;        // 16384
    float* Vs   = sm + 24576;       // 8192
    float* Ms   = sm + 32768;       // 2*128
    float* Ls   = Ms + 256;         // 2*128
    float* Al   = Ls + 256;         // 128
    float* redm = Al + 128;         // 4*128
    float* reds = redm + 512;       // 4*128  (total 34432 floats)

    const int tid = threadIdx.x;
    const int w = tid >> 5, lane = tid & 31;
    const int wr = w & 3, wc = w >> 2;          // 4x4 warps
    const int lr = lane >> 3, lc = lane & 7;    // QK lane map
    const int row0 = wr * 32 + lr * 8;          // 8 QK rows
    const int colS = wc * 32 + lc * 4;          // 4 QK cols
    const int lr2 = lane >> 2, lc2 = lane & 3;  // PV lane map
    const int rowv = wr * 32 + lr2 * 4;         // 4 PV rows
    const int colO = wc * 16 + lc2 * 4;         // 4 PV cols
    const int swzA = lr * 8;                    // P-store swizzle rows i<4
    const int swzB = lr * 8 + 4;                // rows i>=4
    const int swzv = lr2 * 4;                   // P-load swizzle

    const int bh = blockIdx.y, bb = bh >> 3, hh = bh & 7;
    const int s0 = blockIdx.x * 128;
    const float* qb = qt  + (size_t)bh * ND * NS;   // [d][s]
    const float* kb = kt_ + (size_t)bh * ND * NS;   // [d][s]
    const float* vb = v   + (size_t)bh * NS * ND;   // [s][d]

    if (tid < 128) { Ms[tid] = -1e30f; Ls[tid] = 0.0f; }

    // Q tile [64][128], pre-scaled
    #pragma unroll
    for (int u = 0; u < 4; u++) {
        int f4 = u * 512 + tid;
        int row = f4 >> 5, c4 = (f4 & 31) << 2;
        float4 a = *(const float4*)(qb + (size_t)row * NS + s0 + c4);
        *(float4*)&Qs[row * 128 + c4] =
            make_float4(a.x * 0.125f, a.y * 0.125f, a.z * 0.125f, a.w * 0.125f);
    }

    u64 O2[4][2] = {};
    int p = 0;

    for (int ktile = 0; ktile < NS; ktile += 128) {
        __syncthreads();   // prior PV done (and Q/Ms init on iter 0)
        #pragma unroll
        for (int u = 0; u < 4; u++) {
            int f4 = u * 512 + tid;
            int row = f4 >> 5, c4 = (f4 & 31) << 2;
            *(float4*)&KP[row * 128 + c4] =
                *(const float4*)(kb + (size_t)row * NS + ktile + c4);
        }
        {
            const float4* src = (const float4*)(vb + (size_t)ktile * ND);
            float4* dst = (float4*)Vs;
            #pragma unroll
            for (int u = 0; u < 4; u++) dst[tid + u * 512] = src[tid + u * 512];
        }
        __syncthreads();

        // ---- QK: rows packed in pairs ----
        u64 acc2[4][4] = {};
        #pragma unroll 8
        for (int d = 0; d < 64; d++) {
            ulonglong2 xA = *(const ulonglong2*)&Qs[d * 128 + row0];
            ulonglong2 xB = *(const ulonglong2*)&Qs[d * 128 + row0 + 4];
            float4 y = *(const float4*)&KP[d * 128 + colS];
            u64 xa[4] = {xA.x, xA.y, xB.x, xB.y};
            u64 yb[4] = {bc2(y.x), bc2(y.y), bc2(y.z), bc2(y.w)};
            #pragma unroll
            for (int rp = 0; rp < 4; rp++)
                #pragma unroll
                for (int j = 0; j < 4; j++)
                    acc2[rp][j] = f2(xa[rp], yb[j], acc2[rp][j]);
        }
        float sacc[8][4];
        #pragma unroll
        for (int rp = 0; rp < 4; rp++)
            #pragma unroll
            for (int j = 0; j < 4; j++) {
                float2 f = up2(acc2[rp][j]);
                sacc[2 * rp][j] = f.x; sacc[2 * rp + 1][j] = f.y;
            }

        // ---- phase A: tile row-max partials ----
        #pragma unroll
        for (int i = 0; i < 8; i++) {
            float r = fmaxf(fmaxf(sacc[i][0], sacc[i][1]),
                            fmaxf(sacc[i][2], sacc[i][3]));
            r = fmaxf(r, __shfl_xor_sync(0xffffffffu, r, 1));
            r = fmaxf(r, __shfl_xor_sync(0xffffffffu, r, 2));
            r = fmaxf(r, __shfl_xor_sync(0xffffffffu, r, 4));
            if (lc == 0) redm[wc * 128 + row0 + i] = r;
        }
        __syncthreads();

        // ---- phase B: exp + sums + P store; owners update Ms/Al ----
        float mn[8];
        #pragma unroll
        for (int i = 0; i < 8; i++) {
            int r = row0 + i;
            float tm = fmaxf(fmaxf(redm[r], redm[128 + r]),
                             fmaxf(redm[256 + r], redm[384 + r]));
            float mo = Ms[p * 128 + r];
            mn[i] = fmaxf(mo, tm);
            if (wc == 0 && lc == 0) {
                Al[r] = __expf(mo - mn[i]);
                Ms[(p ^ 1) * 128 + r] = mn[i];
            }
        }
        #pragma unroll
        for (int i = 0; i < 8; i++) {
            float s = 0.0f;
            #pragma unroll
            for (int j = 0; j < 4; j++) {
                float e = __expf(sacc[i][j] - mn[i]);
                sacc[i][j] = e;
                s += e;
            }
            s += __shfl_xor_sync(0xffffffffu, s, 1);
            s += __shfl_xor_sync(0xffffffffu, s, 2);
            s += __shfl_xor_sync(0xffffffffu, s, 4);
            if (lc == 0) reds[wc * 128 + row0 + i] = s;
        }
        #pragma unroll
        for (int i = 0; i < 8; i++) {
            int r = row0 + i;
            int sw = (i < 4) ? swzA : swzB;
            *(float4*)&KP[r * 128 + (colS ^ sw)] =
                make_float4(sacc[i][0], sacc[i][1], sacc[i][2], sacc[i][3]);
        }
        __syncthreads();

        // ---- phase C: owners update Ls; all rescale O and accumulate PV ----
        if (wc == 0 && lc == 0) {
            #pragma unroll
            for (int i = 0; i < 8; i++) {
                int r = row0 + i;
                float ts = reds[r] + reds[128 + r] + reds[256 + r] + reds[384 + r];
                Ls[(p ^ 1) * 128 + r] = Ls[p * 128 + r] * Al[r] + ts;
            }
        }
        #pragma unroll
        for (int i = 0; i < 4; i++) {
            u64 a2 = bc2(Al[rowv + i]);
            O2[i][0] = m2(a2, O2[i][0]);
            O2[i][1] = m2(a2, O2[i][1]);
        }
        #pragma unroll 4
        for (int t0 = 0; t0 < 128; t0 += 4) {
            const int tx = t0 ^ swzv;
            float4 p4[4];
            #pragma unroll
            for (int i = 0; i < 4; i++)
                p4[i] = *(const float4*)&KP[(rowv + i) * 128 + tx];
            #pragma unroll
            for (int tt = 0; tt < 4; tt++) {
                ulonglong2 v2 = *(const ulonglong2*)&Vs[(t0 + tt) * 64 + colO];
                float pv[4] = {0, 0, 0, 0};
                pv[0] = ((const float*)&p4[0])[tt];
                pv[1] = ((const float*)&p4[1])[tt];
                pv[2] = ((const float*)&p4[2])[tt];
                pv[3] = ((const float*)&p4[3])[tt];
                #pragma unroll
                for (int i = 0; i < 4; i++) {
                    u64 pb2 = bc2(pv[i]);
                    O2[i][0] = f2(pb2, v2.x, O2[i][0]);
                    O2[i][1] = f2(pb2, v2.y, O2[i][1]);
                }
            }
        }
        p ^= 1;
    }

    __syncthreads();   // last Ls writes visible
    float* ob = concat + ((size_t)bb * NS + s0 + rowv) * (NH * ND) + hh * ND + colO;
    #pragma unroll
    for (int i = 0; i < 4; i++) {
        float inv = 1.0f / Ls[p * 128 + rowv + i];
        float2 f0 = up2(O2[i][0]);
        float2 f1 = up2(O2[i][1]);
        *(float4*)(ob + (size_t)i * (NH * ND)) =
            make_float4(f0.x * inv, f0.y * inv, f1.x * inv, f1.y * inv);
    }
}

// ---------------------------------------------------------------------------
#define ATTN_SMEM (34432 * 4)

extern "C" void kernel_launch(void* const* d_in, const int* in_sizes, int n_in,
                              void* d_out, int out_size)
{
    (void)in_sizes; (void)n_in; (void)out_size;
    const float* x_q = (const float*)d_in[0];
    const float* x_k = (const float*)d_in[1];
    const float* x_v = (const float*)d_in[2];
    const float* Wq  = (const float*)d_in[3];
    const float* bq  = (const float*)d_in[4];
    const float* Wk  = (const float*)d_in[5];
    const float* bk  = (const float*)d_in[6];
    const float* Wv  = (const float*)d_in[7];
    const float* bv  = (const float*)d_in[8];
    const float* Wo  = (const float*)d_in[9];
    const float* bo  = (const float*)d_in[10];
    float* out = (float*)d_out;

    float *qp, *kp, *vp, *cp;
    cudaGetSymbolAddress((void**)&qp, g_q);
    cudaGetSymbolAddress((void**)&kp, g_k);
    cudaGetSymbolAddress((void**)&vp, g_v);
    cudaGetSymbolAddress((void**)&cp, g_concat);

    static int smem_set = 0;
    if (!smem_set) {
        cudaFuncSetAttribute(attn_kernel,
                             cudaFuncAttributeMaxDynamicSharedMemorySize, ATTN_SMEM);
        smem_set = 1;
    }

    dim3 pgrid(NM / 128, NH / 2);
    proj_kernel<1><<<pgrid, 256>>>(x_q, Wq, bq, qp);
    proj_kernel<1><<<pgrid, 256>>>(x_k, Wk, bk, kp);
    proj_kernel<0><<<pgrid, 256>>>(x_v, Wv, bv, vp);

    attn_kernel<<<dim3(NS / 128, NB * NH), 512, ATTN_SMEM>>>(qp, kp, vp, cp);

    out_gemm<<<dim3(NM / 128, NFILT / 128), 256>>>(cp, Wo, bo, out);
}

// round 6
// speedup vs baseline: 1.1015x; 1.1015x over previous
#include <cuda_runtime.h>
#include <cuda_bf16.h>
#include <mma.h>

using namespace nvcuda;

typedef unsigned long long u64;
typedef unsigned int u32;

#define NB 4
#define NS 2048
#define NF 512
#define NH 8
#define ND 64
#define NFILT 512
#define NM (NB*NS)

// ---------------- scratch (device globals; no allocation allowed) ----------
__device__ float g_q[(size_t)NB*NH*NS*ND];       // [B,H,D,S]
__device__ float g_k[(size_t)NB*NH*NS*ND];       // [B,H,D,S]
__device__ float g_v[(size_t)NB*NH*NS*ND];       // [B,H,S,D]
__device__ float g_concat[(size_t)NB*NS*NH*ND];  // [B,S,H*D]
__device__ __nv_bfloat16 g_ahi[(size_t)NM*NF];   // activations hi
__device__ __nv_bfloat16 g_alo[(size_t)NM*NF];   // activations lo
__device__ __nv_bfloat16 g_whi[(size_t)512*512]; // weights hi ([k][n] layout)
__device__ __nv_bfloat16 g_wlo[(size_t)512*512]; // weights lo

// ---- packed f32x2 helpers (attention SIMT path) ----------------------------
__device__ __forceinline__ u64 bc2(float x) {
    u64 r; unsigned xi = __float_as_uint(x);
    asm("mov.b64 %0, {%1, %1};" : "=l"(r) : "r"(xi));
    return r;
}
__device__ __forceinline__ u64 f2(u64 a, u64 b, u64 c) {
    u64 d; asm("fma.rn.f32x2 %0, %1, %2, %3;" : "=l"(d) : "l"(a), "l"(b), "l"(c));
    return d;
}
__device__ __forceinline__ u64 m2(u64 a, u64 b) {
    u64 d; asm("mul.rn.f32x2 %0, %1, %2;" : "=l"(d) : "l"(a), "l"(b));
    return d;
}
__device__ __forceinline__ float2 up2(u64 p) {
    unsigned lo, hi;
    asm("mov.b64 {%0, %1}, %2;" : "=r"(lo), "=r"(hi) : "l"(p));
    return make_float2(__uint_as_float(lo), __uint_as_float(hi));
}

// ---------------------------------------------------------------------------
// split_f: elementwise fp32 -> (hi, lo) bf16. n4 = element count / 4.
// ---------------------------------------------------------------------------
__global__ __launch_bounds__(256) void split_f(
    const float* __restrict__ src,
    __nv_bfloat16* __restrict__ hi, __nv_bfloat16* __restrict__ lo, int n4)
{
    int i = blockIdx.x * 256 + threadIdx.x;
    if (i >= n4) return;
    float4 x = ((const float4*)src)[i];
    float xv[4] = {x.x, x.y, x.z, x.w};
    unsigned short hw[4], lw[4];
    #pragma unroll
    for (int j = 0; j < 4; j++) {
        __nv_bfloat16 h = __float2bfloat16(xv[j]);
        __nv_bfloat16 l = __float2bfloat16(xv[j] - __bfloat162float(h));
        hw[j] = __bfloat16_as_ushort(h);
        lw[j] = __bfloat16_as_ushort(l);
    }
    ((uint2*)hi)[i] = make_uint2((u32)hw[0] | ((u32)hw[1] << 16),
                                 (u32)hw[2] | ((u32)hw[3] << 16));
    ((uint2*)lo)[i] = make_uint2((u32)lw[0] | ((u32)lw[1] << 16),
                                 (u32)lw[2] | ((u32)lw[3] << 16));
}

// ---------------------------------------------------------------------------
// mma_gemm: C[128,64] = A[128,512] @ B[512,64-slice] + bias, via wmma bf16x3.
// A: [NM,512] hi/lo. B element [kk][n] at Whi + ny*wstride + kk*ldw + n.
//   proj GEMMs: ldw=64,  wstride=512*64 (per-head weight block)
//   out GEMM:   ldw=512, wstride=64     (column slice)
// MODE 0: out[b,h,s,64] (v)   MODE 1: out[b,h,64,s] (q/k, col-major store)
// MODE 2: out[m, ng0+64] (final C)
// grid (NM/128, 8), block 256 (8 warps = 4x2; warp tile 32x32 = 2x2 wmma).
// ---------------------------------------------------------------------------
#define ALD 24            // A smem ld (bf16)
#define BLD 72            // B smem ld (bf16)
#define CLD 72            // C smem ld (f32, row-major modes)
#define CLDT 132          // C smem ld (f32, col-major mode)
#define SB_OFF (36864/4)  // bias cache offset (floats)

template<int MODE>
__global__ __launch_bounds__(256) void mma_gemm(
    const __nv_bfloat16* __restrict__ Ahi, const __nv_bfloat16* __restrict__ Alo,
    const __nv_bfloat16* __restrict__ Whi, const __nv_bfloat16* __restrict__ Wlo,
    const float* __restrict__ bias, float* __restrict__ out,
    int ldw, size_t wstride)
{
    __shared__ char smraw[37120];
    __nv_bfloat16* Ah = (__nv_bfloat16*)smraw;          // [128][ALD]
    __nv_bfloat16* Al = Ah + 128 * ALD;
    __nv_bfloat16* Bh = Al + 128 * ALD;                 // [16][BLD]
    __nv_bfloat16* Bl = Bh + 16 * BLD;
    float* Csm = (float*)smraw;                          // epilogue (reused)
    float* sB  = (float*)smraw + SB_OFF;                 // bias cache

    const int tid = threadIdx.x;
    const int w = tid >> 5;
    const int wr = w & 3, wc = w >> 2;                   // 4x2 warp grid
    const int m0 = blockIdx.x * 128;
    const int ny = blockIdx.y;
    const int ng0 = ny * 64;

    if (tid < 64) sB[tid] = bias[ng0 + tid];

    const __nv_bfloat16* Ab_hi = Ahi + (size_t)m0 * NF;
    const __nv_bfloat16* Ab_lo = Alo + (size_t)m0 * NF;
    const __nv_bfloat16* Wb_hi = Whi + (size_t)ny * wstride;
    const __nv_bfloat16* Wb_lo = Wlo + (size_t)ny * wstride;

    wmma::fragment<wmma::accumulator, 16, 16, 16, float> acc[2][2];
    #pragma unroll
    for (int i = 0; i < 2; i++)
        #pragma unroll
        for (int j = 0; j < 2; j++) wmma::fill_fragment(acc[i][j], 0.0f);

    const int ar = tid >> 1, ah = tid & 1;               // A: row, 16B half
    const int bk = tid >> 3, bg = (tid & 7) * 8;         // B: k-row, col group

    for (int k0 = 0; k0 < NF; k0 += 16) {
        __syncthreads();
        *(uint4*)(Ah + ar * ALD + ah * 8) =
            *(const uint4*)(Ab_hi + (size_t)ar * NF + k0 + ah * 8);
        *(uint4*)(Al + ar * ALD + ah * 8) =
            *(const uint4*)(Ab_lo + (size_t)ar * NF + k0 + ah * 8);
        if (tid < 128) {
            *(uint4*)(Bh + bk * BLD + bg) =
                *(const uint4*)(Wb_hi + (size_t)(k0 + bk) * ldw + bg);
            *(uint4*)(Bl + bk * BLD + bg) =
                *(const uint4*)(Wb_lo + (size_t)(k0 + bk) * ldw + bg);
        }
        __syncthreads();

        wmma::fragment<wmma::matrix_a, 16, 16, 16, __nv_bfloat16, wmma::row_major> a_hi[2], a_lo[2];
        wmma::fragment<wmma::matrix_b, 16, 16, 16, __nv_bfloat16, wmma::row_major> b_hi[2], b_lo[2];
        #pragma unroll
        for (int i = 0; i < 2; i++) {
            wmma::load_matrix_sync(a_hi[i], Ah + (wr * 32 + i * 16) * ALD, ALD);
            wmma::load_matrix_sync(a_lo[i], Al + (wr * 32 + i * 16) * ALD, ALD);
            wmma::load_matrix_sync(b_hi[i], Bh + wc * 32 + i * 16, BLD);
            wmma::load_matrix_sync(b_lo[i], Bl + wc * 32 + i * 16, BLD);
        }
        #pragma unroll
        for (int i = 0; i < 2; i++)
            #pragma unroll
            for (int j = 0; j < 2; j++) {
                wmma::mma_sync(acc[i][j], a_hi[i], b_hi[j], acc[i][j]);
                wmma::mma_sync(acc[i][j], a_hi[i], b_lo[j], acc[i][j]);
                wmma::mma_sync(acc[i][j], a_lo[i], b_hi[j], acc[i][j]);
            }
    }
    __syncthreads();

    // Store fragments to smem
    if (MODE == 1) {
        #pragma unroll
        for (int i = 0; i < 2; i++)
            #pragma unroll
            for (int j = 0; j < 2; j++)
                wmma::store_matrix_sync(
                    Csm + (wr * 32 + i * 16) + (wc * 32 + j * 16) * CLDT,
                    acc[i][j], CLDT, wmma::mem_col_major);
    } else {
        #pragma unroll
        for (int i = 0; i < 2; i++)
            #pragma unroll
            for (int j = 0; j < 2; j++)
                wmma::store_matrix_sync(
                    Csm + (wr * 32 + i * 16) * CLD + (wc * 32 + j * 16),
                    acc[i][j], CLD, wmma::mem_row_major);
    }
    __syncthreads();

    const int bb = m0 >> 11, ss0 = m0 & (NS - 1);
    if (MODE == 1) {
        // out[b,h,d,s]: Csm col-major = [d][s] rows of 128 (ld CLDT)
        float* ob = out + ((size_t)(bb * NH + ny) * ND) * NS + ss0;
        #pragma unroll
        for (int r = 0; r < 8; r++) {
            int u = r * 256 + tid;              // 2048 float4 units
            int d = u >> 5, s4 = (u & 31) << 2;
            float bi = sB[d];
            const float* cs = Csm + d * CLDT + s4;
            *(float4*)(ob + (size_t)d * NS + s4) =
                make_float4(cs[0] + bi, cs[1] + bi, cs[2] + bi, cs[3] + bi);
        }
    } else if (MODE == 0) {
        float* ob = out + ((size_t)(bb * NH + ny) * NS + ss0) * ND;
        #pragma unroll
        for (int r = 0; r < 8; r++) {
            int u = r * 256 + tid;
            int row = u >> 4, c4 = (u & 15) << 2;
            const float* cs = Csm + row * CLD + c4;
            const float* bi = sB + c4;
            *(float4*)(ob + (size_t)row * ND + c4) =
                make_float4(cs[0] + bi[0], cs[1] + bi[1], cs[2] + bi[2], cs[3] + bi[3]);
        }
    } else {
        float* ob = out + (size_t)m0 * NFILT + ng0;
        #pragma unroll
        for (int r = 0; r < 8; r++) {
            int u = r * 256 + tid;
            int row = u >> 4, c4 = (u & 15) << 2;
            const float* cs = Csm + row * CLD + c4;
            const float* bi = sB + c4;
            *(float4*)(ob + (size_t)row * NFILT + c4) =
                make_float4(cs[0] + bi[0], cs[1] + bi[1], cs[2] + bi[2], cs[3] + bi[3]);
        }
    }
}

// ---------------------------------------------------------------------------
// Flash attention (round-3 best: 256 threads, 8x8 frags, FFMA2, d-major q/k)
// ---------------------------------------------------------------------------
__global__ __launch_bounds__(256, 1) void attn_kernel(
    const float* __restrict__ qt, const float* __restrict__ kt_,
    const float* __restrict__ v, float* __restrict__ concat)
{
    extern __shared__ float sm[];
    float* Qs   = sm;                    // 8192
    float* KP   = sm + 8192;             // 16384
    float* Vs   = sm + 8192 + 16384;     // 8192
    float* redm = Vs + 8192;             // 256
    float* reds = redm + 256;            // 256

    const int tid = threadIdx.x;
    const int w = tid >> 5, lane = tid & 31;
    const int wr = w & 3, wc = w >> 2;
    const int lr = lane >> 3, lc = lane & 7;
    const int row0 = wr * 32 + lr * 8;
    const int colS = wc * 64 + lc * 8;
    const int colO = wc * 32 + lc * 4;
    const int swz = lr << 2;

    const int bh = blockIdx.y, bb = bh >> 3, hh = bh & 7;
    const int s0 = blockIdx.x * 128;
    const float* qb = qt  + (size_t)bh * ND * NS;
    const float* kb = kt_ + (size_t)bh * ND * NS;
    const float* vb = v   + (size_t)bh * NS * ND;

    #pragma unroll
    for (int u = 0; u < 8; u++) {
        int f4 = u * 256 + tid;
        int row = f4 >> 5, c4 = (f4 & 31) << 2;
        float4 a = *(const float4*)(qb + (size_t)row * NS + s0 + c4);
        *(float4*)&Qs[row * 128 + c4] =
            make_float4(a.x * 0.125f, a.y * 0.125f, a.z * 0.125f, a.w * 0.125f);
    }

    float m_i[8], l_i[8];
    u64 O2[8][2] = {};
    #pragma unroll
    for (int i = 0; i < 8; i++) { m_i[i] = -1e30f; l_i[i] = 0.0f; }

    for (int ktile = 0; ktile < NS; ktile += 128) {
        __syncthreads();
        #pragma unroll
        for (int u = 0; u < 8; u++) {
            int f4 = u * 256 + tid;
            int row = f4 >> 5, c4 = (f4 & 31) << 2;
            *(float4*)&KP[row * 128 + c4] =
                *(const float4*)(kb + (size_t)row * NS + ktile + c4);
        }
        {
            const float4* src = (const float4*)(vb + (size_t)ktile * ND);
            float4* dst = (float4*)Vs;
            #pragma unroll
            for (int i2 = 0; i2 < 8; i2++) dst[tid + i2 * 256] = src[tid + i2 * 256];
        }
        __syncthreads();

        u64 sacc2[8][4] = {};
        #pragma unroll 8
        for (int d = 0; d < 64; d++) {
            float4 x0 = *(const float4*)&Qs[d * 128 + row0];
            float4 x1 = *(const float4*)&Qs[d * 128 + row0 + 4];
            ulonglong2 yA = *(const ulonglong2*)&KP[d * 128 + colS];
            ulonglong2 yB = *(const ulonglong2*)&KP[d * 128 + colS + 4];
            u64 yb2[4] = {yA.x, yA.y, yB.x, yB.y};
            float xa[8] = {x0.x, x0.y, x0.z, x0.w, x1.x, x1.y, x1.z, x1.w};
            #pragma unroll
            for (int i = 0; i < 8; i++) {
                u64 xb = bc2(xa[i]);
                #pragma unroll
                for (int jp = 0; jp < 4; jp++)
                    sacc2[i][jp] = f2(xb, yb2[jp], sacc2[i][jp]);
            }
        }
        float sacc[8][8];
        #pragma unroll
        for (int i = 0; i < 8; i++)
            #pragma unroll
            for (int jp = 0; jp < 4; jp++) {
                float2 f = up2(sacc2[i][jp]);
                sacc[i][2 * jp] = f.x; sacc[i][2 * jp + 1] = f.y;
            }

        float pm[8];
        #pragma unroll
        for (int i = 0; i < 8; i++) {
            float r = fmaxf(fmaxf(fmaxf(sacc[i][0], sacc[i][1]),
                                  fmaxf(sacc[i][2], sacc[i][3])),
                            fmaxf(fmaxf(sacc[i][4], sacc[i][5]),
                                  fmaxf(sacc[i][6], sacc[i][7])));
            r = fmaxf(r, __shfl_xor_sync(0xffffffffu, r, 1));
            r = fmaxf(r, __shfl_xor_sync(0xffffffffu, r, 2));
            r = fmaxf(r, __shfl_xor_sync(0xffffffffu, r, 4));
            pm[i] = r;
        }
        if (lc == 0) {
            #pragma unroll
            for (int i = 0; i < 8; i++) redm[wc * 128 + row0 + i] = pm[i];
        }
        __syncthreads();

        float alpha[8];
        #pragma unroll
        for (int i = 0; i < 8; i++) {
            float mt = fmaxf(redm[row0 + i], redm[128 + row0 + i]);
            float mn = fmaxf(m_i[i], mt);
            alpha[i] = __expf(m_i[i] - mn);
            m_i[i] = mn;
        }
        float ps[8];
        #pragma unroll
        for (int i = 0; i < 8; i++) {
            float s = 0.0f;
            #pragma unroll
            for (int j = 0; j < 8; j++) {
                float p = __expf(sacc[i][j] - m_i[i]);
                sacc[i][j] = p;
                s += p;
            }
            s += __shfl_xor_sync(0xffffffffu, s, 1);
            s += __shfl_xor_sync(0xffffffffu, s, 2);
            s += __shfl_xor_sync(0xffffffffu, s, 4);
            ps[i] = s;
        }
        if (lc == 0) {
            #pragma unroll
            for (int i = 0; i < 8; i++) reds[wc * 128 + row0 + i] = ps[i];
        }
        #pragma unroll
        for (int i = 0; i < 8; i++) {
            int r = row0 + i;
            *(float4*)&KP[r * 128 + ((colS) ^ swz)] =
                make_float4(sacc[i][0], sacc[i][1], sacc[i][2], sacc[i][3]);
            *(float4*)&KP[r * 128 + ((colS + 4) ^ swz)] =
                make_float4(sacc[i][4], sacc[i][5], sacc[i][6], sacc[i][7]);
        }
        #pragma unroll
        for (int i = 0; i < 8; i++) {
            u64 a2 = bc2(alpha[i]);
            O2[i][0] = m2(a2, O2[i][0]);
            O2[i][1] = m2(a2, O2[i][1]);
        }
        __syncthreads();
        #pragma unroll
        for (int i = 0; i < 8; i++)
            l_i[i] = l_i[i] * alpha[i] + reds[row0 + i] + reds[128 + row0 + i];

        #pragma unroll 4
        for (int t0 = 0; t0 < 128; t0 += 4) {
            const int tx = t0 ^ swz;
            float pa[8][4];
            #pragma unroll
            for (int i = 0; i < 8; i++) {
                float4 p4 = *(const float4*)&KP[(row0 + i) * 128 + tx];
                pa[i][0] = p4.x; pa[i][1] = p4.y; pa[i][2] = p4.z; pa[i][3] = p4.w;
            }
            #pragma unroll
            for (int tt = 0; tt < 4; tt++) {
                ulonglong2 v2 = *(const ulonglong2*)&Vs[(t0 + tt) * 64 + colO];
                #pragma unroll
                for (int i = 0; i < 8; i++) {
                    u64 pb = bc2(pa[i][tt]);
                    O2[i][0] = f2(pb, v2.x, O2[i][0]);
                    O2[i][1] = f2(pb, v2.y, O2[i][1]);
                }
            }
        }
    }

    float* ob = concat + ((size_t)bb * NS + s0 + row0) * (NH * ND) + hh * ND + colO;
    #pragma unroll
    for (int i = 0; i < 8; i++) {
        float inv = 1.0f / l_i[i];
        float2 f0 = up2(O2[i][0]);
        float2 f1 = up2(O2[i][1]);
        *(float4*)(ob + (size_t)i * (NH * ND)) =
            make_float4(f0.x * inv, f0.y * inv, f1.x * inv, f1.y * inv);
    }
}

// ---------------------------------------------------------------------------
#define ATTN_SMEM ((8192 + 16384 + 8192 + 512) * 4)

extern "C" void kernel_launch(void* const* d_in, const int* in_sizes, int n_in,
                              void* d_out, int out_size)
{
    (void)in_sizes; (void)n_in; (void)out_size;
    const float* x_q = (const float*)d_in[0];
    const float* x_k = (const float*)d_in[1];
    const float* x_v = (const float*)d_in[2];
    const float* Wq  = (const float*)d_in[3];
    const float* bq  = (const float*)d_in[4];
    const float* Wk  = (const float*)d_in[5];
    const float* bk  = (const float*)d_in[6];
    const float* Wv  = (const float*)d_in[7];
    const float* bv  = (const float*)d_in[8];
    const float* Wo  = (const float*)d_in[9];
    const float* bo  = (const float*)d_in[10];
    float* out = (float*)d_out;

    float *qp, *kp, *vp, *cp;
    __nv_bfloat16 *ahi, *alo, *whi, *wlo;
    cudaGetSymbolAddress((void**)&qp, g_q);
    cudaGetSymbolAddress((void**)&kp, g_k);
    cudaGetSymbolAddress((void**)&vp, g_v);
    cudaGetSymbolAddress((void**)&cp, g_concat);
    cudaGetSymbolAddress((void**)&ahi, g_ahi);
    cudaGetSymbolAddress((void**)&alo, g_alo);
    cudaGetSymbolAddress((void**)&whi, g_whi);
    cudaGetSymbolAddress((void**)&wlo, g_wlo);

    static int once = 0;
    if (!once) {
        cudaFuncSetAttribute(attn_kernel,
                             cudaFuncAttributeMaxDynamicSharedMemorySize, ATTN_SMEM);
        once = 1;
    }

    const int NW4 = (512 * 512) / 4;   // weight float4 units
    const int NX4 = (NM * NF) / 4;     // activation float4 units
    dim3 ggrid(NM / 128, 8);
    const size_t WSTRIDE_PROJ = (size_t)512 * 64;

    split_f<<<NW4 / 256, 256>>>(Wq, whi, wlo, NW4);
    split_f<<<NX4 / 256, 256>>>(x_q, ahi, alo, NX4);
    mma_gemm<1><<<ggrid, 256>>>(ahi, alo, whi, wlo, bq, qp, 64, WSTRIDE_PROJ);

    split_f<<<NW4 / 256, 256>>>(Wk, whi, wlo, NW4);
    split_f<<<NX4 / 256, 256>>>(x_k, ahi, alo, NX4);
    mma_gemm<1><<<ggrid, 256>>>(ahi, alo, whi, wlo, bk, kp, 64, WSTRIDE_PROJ);

    split_f<<<NW4 / 256, 256>>>(Wv, whi, wlo, NW4);
    split_f<<<NX4 / 256, 256>>>(x_v, ahi, alo, NX4);
    mma_gemm<0><<<ggrid, 256>>>(ahi, alo, whi, wlo, bv, vp, 64, WSTRIDE_PROJ);

    attn_kernel<<<dim3(NS / 128, NB * NH), 256, ATTN_SMEM>>>(qp, kp, vp, cp);

    split_f<<<NW4 / 256, 256>>>(Wo, whi, wlo, NW4);
    split_f<<<NX4 / 256, 256>>>(cp, ahi, alo, NX4);
    mma_gemm<2><<<ggrid, 256>>>(ahi, alo, whi, wlo, bo, out, 512, (size_t)64);
}

// round 7
// speedup vs baseline: 1.2068x; 1.0956x over previous
#include <cuda_runtime.h>
#include <cuda_bf16.h>
#include <mma.h>

using namespace nvcuda;

typedef unsigned long long u64;
typedef unsigned int u32;

#define NB 4
#define NS 2048
#define NF 512
#define NH 8
#define ND 64
#define NFILT 512
#define NM (NB*NS)

// ---------------- scratch (device globals; no allocation allowed) ----------
__device__ __nv_bfloat16 g_qh[(size_t)NB*NH*NS*ND];  // q hi [B,H,S,D] (pre-scaled 1/8)
__device__ __nv_bfloat16 g_ql[(size_t)NB*NH*NS*ND];
__device__ __nv_bfloat16 g_kh[(size_t)NB*NH*NS*ND];
__device__ __nv_bfloat16 g_kl[(size_t)NB*NH*NS*ND];
__device__ __nv_bfloat16 g_vh[(size_t)NB*NH*NS*ND];
__device__ __nv_bfloat16 g_vl[(size_t)NB*NH*NS*ND];
__device__ __nv_bfloat16 g_chi[(size_t)NM*NFILT];    // concat hi [B,S,H*D]
__device__ __nv_bfloat16 g_clo[(size_t)NM*NFILT];
__device__ __nv_bfloat16 g_ahi[(size_t)NM*NF];       // split x inputs
__device__ __nv_bfloat16 g_alo[(size_t)NM*NF];
__device__ __nv_bfloat16 g_whi[(size_t)512*512];
__device__ __nv_bfloat16 g_wlo[(size_t)512*512];

__device__ __forceinline__ u32 pack_bf2(float a, float b) {
    __nv_bfloat16 ha = __float2bfloat16(a), hb = __float2bfloat16(b);
    return (u32)__bfloat16_as_ushort(ha) | ((u32)__bfloat16_as_ushort(hb) << 16);
}

// ---------------------------------------------------------------------------
// split_f: elementwise fp32 -> (hi, lo) bf16. n4 = element count / 4.
// ---------------------------------------------------------------------------
__global__ __launch_bounds__(256) void split_f(
    const float* __restrict__ src,
    __nv_bfloat16* __restrict__ hi, __nv_bfloat16* __restrict__ lo, int n4)
{
    int i = blockIdx.x * 256 + threadIdx.x;
    if (i >= n4) return;
    float4 x = ((const float4*)src)[i];
    float xv[4] = {x.x, x.y, x.z, x.w};
    unsigned short hw[4], lw[4];
    #pragma unroll
    for (int j = 0; j < 4; j++) {
        __nv_bfloat16 h = __float2bfloat16(xv[j]);
        __nv_bfloat16 l = __float2bfloat16(xv[j] - __bfloat162float(h));
        hw[j] = __bfloat16_as_ushort(h);
        lw[j] = __bfloat16_as_ushort(l);
    }
    ((uint2*)hi)[i] = make_uint2((u32)hw[0] | ((u32)hw[1] << 16),
                                 (u32)hw[2] | ((u32)hw[3] << 16));
    ((uint2*)lo)[i] = make_uint2((u32)lw[0] | ((u32)lw[1] << 16),
                                 (u32)lw[2] | ((u32)lw[3] << 16));
}

// ---------------------------------------------------------------------------
// mma_gemm: C[128,64] = A[128,512] @ B[512,64-slice] + bias, wmma bf16x3.
// MODE 0: proj, write bf16 hi/lo [b,h,s,64]
// MODE 1: proj + 0.125 scale (q), write bf16 hi/lo [b,h,s,64]
// MODE 2: final GEMM, write fp32 out[m, ng0+64]
// grid (NM/128, 8), block 256 (warps 4x2, warp tile 32x32).
// ---------------------------------------------------------------------------
#define ALD 24
#define BLD 72
#define CLD 72
#define SB_OFF (36864/4)

template<int MODE>
__global__ __launch_bounds__(256) void mma_gemm(
    const __nv_bfloat16* __restrict__ Ahi, const __nv_bfloat16* __restrict__ Alo,
    const __nv_bfloat16* __restrict__ Whi, const __nv_bfloat16* __restrict__ Wlo,
    const float* __restrict__ bias,
    __nv_bfloat16* __restrict__ ohi, __nv_bfloat16* __restrict__ olo,
    float* __restrict__ out32, int ldw, size_t wstride)
{
    __shared__ char smraw[37120];
    __nv_bfloat16* Ah = (__nv_bfloat16*)smraw;
    __nv_bfloat16* Al = Ah + 128 * ALD;
    __nv_bfloat16* Bh = Al + 128 * ALD;
    __nv_bfloat16* Bl = Bh + 16 * BLD;
    float* Csm = (float*)smraw;
    float* sB  = (float*)smraw + SB_OFF;

    const int tid = threadIdx.x;
    const int w = tid >> 5;
    const int wr = w & 3, wc = w >> 2;
    const int m0 = blockIdx.x * 128;
    const int ny = blockIdx.y;
    const int ng0 = ny * 64;

    if (tid < 64) sB[tid] = bias[ng0 + tid];

    const __nv_bfloat16* Ab_hi = Ahi + (size_t)m0 * NF;
    const __nv_bfloat16* Ab_lo = Alo + (size_t)m0 * NF;
    const __nv_bfloat16* Wb_hi = Whi + (size_t)ny * wstride;
    const __nv_bfloat16* Wb_lo = Wlo + (size_t)ny * wstride;

    wmma::fragment<wmma::accumulator, 16, 16, 16, float> acc[2][2];
    #pragma unroll
    for (int i = 0; i < 2; i++)
        #pragma unroll
        for (int j = 0; j < 2; j++) wmma::fill_fragment(acc[i][j], 0.0f);

    const int ar = tid >> 1, ah = tid & 1;
    const int bk = tid >> 3, bg = (tid & 7) * 8;

    for (int k0 = 0; k0 < NF; k0 += 16) {
        __syncthreads();
        *(uint4*)(Ah + ar * ALD + ah * 8) =
            *(const uint4*)(Ab_hi + (size_t)ar * NF + k0 + ah * 8);
        *(uint4*)(Al + ar * ALD + ah * 8) =
            *(const uint4*)(Ab_lo + (size_t)ar * NF + k0 + ah * 8);
        if (tid < 128) {
            *(uint4*)(Bh + bk * BLD + bg) =
                *(const uint4*)(Wb_hi + (size_t)(k0 + bk) * ldw + bg);
            *(uint4*)(Bl + bk * BLD + bg) =
                *(const uint4*)(Wb_lo + (size_t)(k0 + bk) * ldw + bg);
        }
        __syncthreads();

        wmma::fragment<wmma::matrix_a, 16, 16, 16, __nv_bfloat16, wmma::row_major> a_hi[2], a_lo[2];
        wmma::fragment<wmma::matrix_b, 16, 16, 16, __nv_bfloat16, wmma::row_major> b_hi[2], b_lo[2];
        #pragma unroll
        for (int i = 0; i < 2; i++) {
            wmma::load_matrix_sync(a_hi[i], Ah + (wr * 32 + i * 16) * ALD, ALD);
            wmma::load_matrix_sync(a_lo[i], Al + (wr * 32 + i * 16) * ALD, ALD);
            wmma::load_matrix_sync(b_hi[i], Bh + wc * 32 + i * 16, BLD);
            wmma::load_matrix_sync(b_lo[i], Bl + wc * 32 + i * 16, BLD);
        }
        #pragma unroll
        for (int i = 0; i < 2; i++)
            #pragma unroll
            for (int j = 0; j < 2; j++) {
                wmma::mma_sync(acc[i][j], a_hi[i], b_hi[j], acc[i][j]);
                wmma::mma_sync(acc[i][j], a_hi[i], b_lo[j], acc[i][j]);
                wmma::mma_sync(acc[i][j], a_lo[i], b_hi[j], acc[i][j]);
            }
    }
    __syncthreads();
    #pragma unroll
    for (int i = 0; i < 2; i++)
        #pragma unroll
        for (int j = 0; j < 2; j++)
            wmma::store_matrix_sync(
                Csm + (wr * 32 + i * 16) * CLD + (wc * 32 + j * 16),
                acc[i][j], CLD, wmma::mem_row_major);
    __syncthreads();

    const int bb = m0 >> 11, ss0 = m0 & (NS - 1);
    if (MODE == 2) {
        float* ob = out32 + (size_t)m0 * NFILT + ng0;
        #pragma unroll
        for (int r = 0; r < 8; r++) {
            int u = r * 256 + tid;
            int row = u >> 4, c4 = (u & 15) << 2;
            const float* cs = Csm + row * CLD + c4;
            const float* bi = sB + c4;
            *(float4*)(ob + (size_t)row * NFILT + c4) =
                make_float4(cs[0] + bi[0], cs[1] + bi[1], cs[2] + bi[2], cs[3] + bi[3]);
        }
    } else {
        __nv_bfloat16* oh = ohi + ((size_t)(bb * NH + ny) * NS + ss0) * ND;
        __nv_bfloat16* ol = olo + ((size_t)(bb * NH + ny) * NS + ss0) * ND;
        #pragma unroll
        for (int r = 0; r < 8; r++) {
            int u = r * 256 + tid;
            int row = u >> 4, c4 = (u & 15) << 2;
            const float* cs = Csm + row * CLD + c4;
            const float* bi = sB + c4;
            float vv[4];
            #pragma unroll
            for (int i = 0; i < 4; i++) {
                vv[i] = cs[i] + bi[i];
                if (MODE == 1) vv[i] *= 0.125f;
            }
            unsigned short hw[4], lw[4];
            #pragma unroll
            for (int i = 0; i < 4; i++) {
                __nv_bfloat16 h = __float2bfloat16(vv[i]);
                __nv_bfloat16 l = __float2bfloat16(vv[i] - __bfloat162float(h));
                hw[i] = __bfloat16_as_ushort(h);
                lw[i] = __bfloat16_as_ushort(l);
            }
            *(uint2*)(oh + (size_t)row * ND + c4) =
                make_uint2((u32)hw[0] | ((u32)hw[1] << 16), (u32)hw[2] | ((u32)hw[3] << 16));
            *(uint2*)(ol + (size_t)row * ND + c4) =
                make_uint2((u32)lw[0] | ((u32)lw[1] << 16), (u32)lw[2] | ((u32)lw[3] << 16));
        }
    }
}

// ---------------------------------------------------------------------------
// attn_mma: flash attention via wmma bf16x3. 128 q-rows/CTA, 64-key tiles.
// smem (bytes): Qh/Ql [128][72]bf16, KP hi/lo (K tile then P) [128][72]bf16,
//   Vh/Vl [64][72]bf16, S [128][68]f32 (S, then PV result), O [128][68]f32,
//   Al/Ms/Ls [128]f32.
// grid (NS/128, B*H), block 256 (warps 4x2).
// ---------------------------------------------------------------------------
#define AQH 0
#define AQL 18432
#define AKH 36864
#define AKL 55296
#define AVH 73728
#define AVL 82944
#define ASM 92160
#define AOS 126976
#define AAL 161792
#define AMS 162304
#define ALS 162816
#define ATTN_BYTES 163328

__global__ __launch_bounds__(256, 1) void attn_mma(
    const __nv_bfloat16* __restrict__ qh, const __nv_bfloat16* __restrict__ ql,
    const __nv_bfloat16* __restrict__ kh, const __nv_bfloat16* __restrict__ kl,
    const __nv_bfloat16* __restrict__ vh, const __nv_bfloat16* __restrict__ vl,
    __nv_bfloat16* __restrict__ chi, __nv_bfloat16* __restrict__ clo)
{
    extern __shared__ char smc[];
    float* Ssm = (float*)(smc + ASM);
    float* Osm = (float*)(smc + AOS);
    float* Al  = (float*)(smc + AAL);
    float* Ms  = (float*)(smc + AMS);
    float* Ls  = (float*)(smc + ALS);

    const int tid = threadIdx.x;
    const int w = tid >> 5;
    const int wr = w & 3, wc = w >> 2;
    const int bh = blockIdx.y, bb = bh >> 3, hh = bh & 7;
    const int s0 = blockIdx.x * 128;

    const char* qhb = (const char*)(qh + ((size_t)bh * NS + s0) * ND);
    const char* qlb = (const char*)(ql + ((size_t)bh * NS + s0) * ND);
    const char* khb = (const char*)(kh + (size_t)bh * NS * ND);
    const char* klb = (const char*)(kl + (size_t)bh * NS * ND);
    const char* vhb = (const char*)(vh + (size_t)bh * NS * ND);
    const char* vlb = (const char*)(vl + (size_t)bh * NS * ND);

    // Load Q tile (128 rows x 128B per buffer)
    #pragma unroll
    for (int u = 0; u < 4; u++) {
        int i = u * 256 + tid;             // 1024 units per buffer
        int row = i >> 3, c = (i & 7) * 16;
        *(uint4*)(smc + AQH + row * 144 + c) = *(const uint4*)(qhb + (size_t)row * 128 + c);
        *(uint4*)(smc + AQL + row * 144 + c) = *(const uint4*)(qlb + (size_t)row * 128 + c);
    }
    // Init O, Ms, Ls
    {
        int row = tid >> 1, b32 = (tid & 1) * 32;
        float4 z = make_float4(0.f, 0.f, 0.f, 0.f);
        #pragma unroll
        for (int j = 0; j < 8; j++) *(float4*)(Osm + row * 68 + b32 + j * 4) = z;
    }
    if (tid < 128) { Ms[tid] = -1e30f; Ls[tid] = 0.0f; }

    const int row = tid >> 1, b32 = (tid & 1) * 32;

    for (int kt = 0; kt < NS; kt += 64) {
        __syncthreads();   // prev blend done; prev PV reads of KP/V done
        // Load K and V tiles (64 rows x 128B per buffer)
        #pragma unroll
        for (int u = 0; u < 2; u++) {
            int i = u * 256 + tid;        // 512 units per buffer
            int r = i >> 3, c = (i & 7) * 16;
            size_t g = (size_t)(kt + r) * 128 + c;
            *(uint4*)(smc + AKH + r * 144 + c) = *(const uint4*)(khb + g);
            *(uint4*)(smc + AKL + r * 144 + c) = *(const uint4*)(klb + g);
            *(uint4*)(smc + AVH + r * 144 + c) = *(const uint4*)(vhb + g);
            *(uint4*)(smc + AVL + r * 144 + c) = *(const uint4*)(vlb + g);
        }
        __syncthreads();

        // ---- S = Q @ K^T (bf16x3), warp tile 32(M) x 32(N) ----
        {
            wmma::fragment<wmma::accumulator, 16, 16, 16, float> sacc[2][2];
            #pragma unroll
            for (int i = 0; i < 2; i++)
                #pragma unroll
                for (int j = 0; j < 2; j++) wmma::fill_fragment(sacc[i][j], 0.0f);
            #pragma unroll
            for (int k = 0; k < 4; k++) {
                wmma::fragment<wmma::matrix_a, 16, 16, 16, __nv_bfloat16, wmma::row_major> a_h[2], a_l[2];
                wmma::fragment<wmma::matrix_b, 16, 16, 16, __nv_bfloat16, wmma::col_major> b_h[2], b_l[2];
                #pragma unroll
                for (int i = 0; i < 2; i++) {
                    const __nv_bfloat16* qa = (const __nv_bfloat16*)(smc + AQH) + (wr * 32 + i * 16) * 72 + k * 16;
                    const __nv_bfloat16* qb2 = (const __nv_bfloat16*)(smc + AQL) + (wr * 32 + i * 16) * 72 + k * 16;
                    wmma::load_matrix_sync(a_h[i], qa, 72);
                    wmma::load_matrix_sync(a_l[i], qb2, 72);
                    const __nv_bfloat16* ka = (const __nv_bfloat16*)(smc + AKH) + (wc * 32 + i * 16) * 72 + k * 16;
                    const __nv_bfloat16* kb2 = (const __nv_bfloat16*)(smc + AKL) + (wc * 32 + i * 16) * 72 + k * 16;
                    wmma::load_matrix_sync(b_h[i], ka, 72);
                    wmma::load_matrix_sync(b_l[i], kb2, 72);
                }
                #pragma unroll
                for (int i = 0; i < 2; i++)
                    #pragma unroll
                    for (int j = 0; j < 2; j++) {
                        wmma::mma_sync(sacc[i][j], a_h[i], b_h[j], sacc[i][j]);
                        wmma::mma_sync(sacc[i][j], a_h[i], b_l[j], sacc[i][j]);
                        wmma::mma_sync(sacc[i][j], a_l[i], b_h[j], sacc[i][j]);
                    }
            }
            #pragma unroll
            for (int i = 0; i < 2; i++)
                #pragma unroll
                for (int j = 0; j < 2; j++)
                    wmma::store_matrix_sync(Ssm + (wr * 32 + i * 16) * 68 + wc * 32 + j * 16,
                                            sacc[i][j], 68, wmma::mem_row_major);
        }
        __syncthreads();

        // ---- softmax: 2 threads per row, 32 cols each ----
        {
            float xv[32];
            #pragma unroll
            for (int j = 0; j < 8; j++)
                *(float4*)&xv[j * 4] = *(const float4*)(Ssm + row * 68 + b32 + j * 4);
            float mx = xv[0];
            #pragma unroll
            for (int j = 1; j < 32; j++) mx = fmaxf(mx, xv[j]);
            mx = fmaxf(mx, __shfl_xor_sync(0xffffffffu, mx, 1));
            float mo = Ms[row];
            float mn = fmaxf(mo, mx);
            float alpha = __expf(mo - mn);
            float s = 0.0f;
            #pragma unroll
            for (int j = 0; j < 32; j++) { xv[j] = __expf(xv[j] - mn); s += xv[j]; }
            // store P hi/lo bf16
            #pragma unroll
            for (int g = 0; g < 4; g++) {
                u32 hw[4], lw[4];
                #pragma unroll
                for (int q2 = 0; q2 < 4; q2++) {
                    float a = xv[g * 8 + q2 * 2], b = xv[g * 8 + q2 * 2 + 1];
                    __nv_bfloat16 ha = __float2bfloat16(a), hb2 = __float2bfloat16(b);
                    hw[q2] = (u32)__bfloat16_as_ushort(ha) | ((u32)__bfloat16_as_ushort(hb2) << 16);
                    lw[q2] = pack_bf2(a - __bfloat162float(ha), b - __bfloat162float(hb2));
                }
                *(uint4*)(smc + AKH + row * 144 + b32 * 2 + g * 16) = make_uint4(hw[0], hw[1], hw[2], hw[3]);
                *(uint4*)(smc + AKL + row * 144 + b32 * 2 + g * 16) = make_uint4(lw[0], lw[1], lw[2], lw[3]);
            }
            s += __shfl_xor_sync(0xffffffffu, s, 1);
            if (!(tid & 1)) {
                Ms[row] = mn;
                Ls[row] = Ls[row] * alpha + s;
                Al[row] = alpha;
            }
        }
        __syncthreads();

        // ---- PV = P @ V (bf16x3), warp tile 32(M) x 32(N over 64 d) ----
        {
            wmma::fragment<wmma::accumulator, 16, 16, 16, float> pacc[2][2];
            #pragma unroll
            for (int i = 0; i < 2; i++)
                #pragma unroll
                for (int j = 0; j < 2; j++) wmma::fill_fragment(pacc[i][j], 0.0f);
            #pragma unroll
            for (int k = 0; k < 4; k++) {
                wmma::fragment<wmma::matrix_a, 16, 16, 16, __nv_bfloat16, wmma::row_major> p_h[2], p_l[2];
                wmma::fragment<wmma::matrix_b, 16, 16, 16, __nv_bfloat16, wmma::row_major> v_h[2], v_l[2];
                #pragma unroll
                for (int i = 0; i < 2; i++) {
                    const __nv_bfloat16* pa = (const __nv_bfloat16*)(smc + AKH) + (wr * 32 + i * 16) * 72 + k * 16;
                    const __nv_bfloat16* pb = (const __nv_bfloat16*)(smc + AKL) + (wr * 32 + i * 16) * 72 + k * 16;
                    wmma::load_matrix_sync(p_h[i], pa, 72);
                    wmma::load_matrix_sync(p_l[i], pb, 72);
                    const __nv_bfloat16* va = (const __nv_bfloat16*)(smc + AVH) + (k * 16) * 72 + wc * 32 + i * 16;
                    const __nv_bfloat16* vb2 = (const __nv_bfloat16*)(smc + AVL) + (k * 16) * 72 + wc * 32 + i * 16;
                    wmma::load_matrix_sync(v_h[i], va, 72);
                    wmma::load_matrix_sync(v_l[i], vb2, 72);
                }
                #pragma unroll
                for (int i = 0; i < 2; i++)
                    #pragma unroll
                    for (int j = 0; j < 2; j++) {
                        wmma::mma_sync(pacc[i][j], p_h[i], v_h[j], pacc[i][j]);
                        wmma::mma_sync(pacc[i][j], p_h[i], v_l[j], pacc[i][j]);
                        wmma::mma_sync(pacc[i][j], p_l[i], v_h[j], pacc[i][j]);
                    }
            }
            #pragma unroll
            for (int i = 0; i < 2; i++)
                #pragma unroll
                for (int j = 0; j < 2; j++)
                    wmma::store_matrix_sync(Ssm + (wr * 32 + i * 16) * 68 + wc * 32 + j * 16,
                                            pacc[i][j], 68, wmma::mem_row_major);
        }
        __syncthreads();

        // ---- blend: O = O*alpha + PV ----
        {
            float alpha = Al[row];
            #pragma unroll
            for (int j = 0; j < 8; j++) {
                float4 o = *(float4*)(Osm + row * 68 + b32 + j * 4);
                float4 pq = *(const float4*)(Ssm + row * 68 + b32 + j * 4);
                o.x = o.x * alpha + pq.x; o.y = o.y * alpha + pq.y;
                o.z = o.z * alpha + pq.z; o.w = o.w * alpha + pq.w;
                *(float4*)(Osm + row * 68 + b32 + j * 4) = o;
            }
        }
    }

    // ---- epilogue: normalize, write concat bf16 hi/lo [B,S,H*D] ----
    {
        float inv = 1.0f / Ls[row];
        size_t gr = ((size_t)bb * NS + s0 + row) * NFILT + hh * ND + b32;
        #pragma unroll
        for (int g = 0; g < 4; g++) {
            float vv[8];
            *(float4*)&vv[0] = *(const float4*)(Osm + row * 68 + b32 + g * 8);
            *(float4*)&vv[4] = *(const float4*)(Osm + row * 68 + b32 + g * 8 + 4);
            u32 hw[4], lw[4];
            #pragma unroll
            for (int q2 = 0; q2 < 4; q2++) {
                float a = vv[q2 * 2] * inv, b = vv[q2 * 2 + 1] * inv;
                __nv_bfloat16 ha = __float2bfloat16(a), hb2 = __float2bfloat16(b);
                hw[q2] = (u32)__bfloat16_as_ushort(ha) | ((u32)__bfloat16_as_ushort(hb2) << 16);
                lw[q2] = pack_bf2(a - __bfloat162float(ha), b - __bfloat162float(hb2));
            }
            *(uint4*)(chi + gr + g * 8) = make_uint4(hw[0], hw[1], hw[2], hw[3]);
            *(uint4*)(clo + gr + g * 8) = make_uint4(lw[0], lw[1], lw[2], lw[3]);
        }
    }
}

// ---------------------------------------------------------------------------
extern "C" void kernel_launch(void* const* d_in, const int* in_sizes, int n_in,
                              void* d_out, int out_size)
{
    (void)in_sizes; (void)n_in; (void)out_size;
    const float* x_q = (const float*)d_in[0];
    const float* x_k = (const float*)d_in[1];
    const float* x_v = (const float*)d_in[2];
    const float* Wq  = (const float*)d_in[3];
    const float* bq  = (const float*)d_in[4];
    const float* Wk  = (const float*)d_in[5];
    const float* bk  = (const float*)d_in[6];
    const float* Wv  = (const float*)d_in[7];
    const float* bv  = (const float*)d_in[8];
    const float* Wo  = (const float*)d_in[9];
    const float* bo  = (const float*)d_in[10];
    float* out = (float*)d_out;

    __nv_bfloat16 *qh, *ql, *kh, *kl, *vh, *vl, *chi, *clo, *ahi, *alo, *whi, *wlo;
    cudaGetSymbolAddress((void**)&qh, g_qh);
    cudaGetSymbolAddress((void**)&ql, g_ql);
    cudaGetSymbolAddress((void**)&kh, g_kh);
    cudaGetSymbolAddress((void**)&kl, g_kl);
    cudaGetSymbolAddress((void**)&vh, g_vh);
    cudaGetSymbolAddress((void**)&vl, g_vl);
    cudaGetSymbolAddress((void**)&chi, g_chi);
    cudaGetSymbolAddress((void**)&clo, g_clo);
    cudaGetSymbolAddress((void**)&ahi, g_ahi);
    cudaGetSymbolAddress((void**)&alo, g_alo);
    cudaGetSymbolAddress((void**)&whi, g_whi);
    cudaGetSymbolAddress((void**)&wlo, g_wlo);

    static int once = 0;
    if (!once) {
        cudaFuncSetAttribute(attn_mma,
                             cudaFuncAttributeMaxDynamicSharedMemorySize, ATTN_BYTES);
        once = 1;
    }

    const int NW4 = (512 * 512) / 4;
    const int NX4 = (NM * NF) / 4;
    dim3 ggrid(NM / 128, 8);
    const size_t WSTRIDE_PROJ = (size_t)512 * 64;

    split_f<<<NW4 / 256, 256>>>(Wq, whi, wlo, NW4);
    split_f<<<NX4 / 256, 256>>>(x_q, ahi, alo, NX4);
    mma_gemm<1><<<ggrid, 256>>>(ahi, alo, whi, wlo, bq, qh, ql, nullptr, 64, WSTRIDE_PROJ);

    split_f<<<NW4 / 256, 256>>>(Wk, whi, wlo, NW4);
    split_f<<<NX4 / 256, 256>>>(x_k, ahi, alo, NX4);
    mma_gemm<0><<<ggrid, 256>>>(ahi, alo, whi, wlo, bk, kh, kl, nullptr, 64, WSTRIDE_PROJ);

    split_f<<<NW4 / 256, 256>>>(Wv, whi, wlo, NW4);
    split_f<<<NX4 / 256, 256>>>(x_v, ahi, alo, NX4);
    mma_gemm<0><<<ggrid, 256>>>(ahi, alo, whi, wlo, bv, vh, vl, nullptr, 64, WSTRIDE_PROJ);

    attn_mma<<<dim3(NS / 128, NB * NH), 256, ATTN_BYTES>>>(qh, ql, kh, kl, vh, vl, chi, clo);

    split_f<<<NW4 / 256, 256>>>(Wo, whi, wlo, NW4);
    mma_gemm<2><<<ggrid, 256>>>(chi, clo, whi, wlo, bo, nullptr, nullptr, out, 512, (size_t)64);
}

// round 8
// speedup vs baseline: 1.8295x; 1.5160x over previous
#include <cuda_runtime.h>
#include <cuda_bf16.h>
#include <mma.h>

using namespace nvcuda;

typedef unsigned long long u64;
typedef unsigned int u32;

#define NB 4
#define NS 2048
#define NF 512
#define NH 8
#define ND 64
#define NFILT 512
#define NM (NB*NS)

// ---------------- scratch (device globals; no allocation allowed) ----------
__device__ __nv_bfloat16 g_qh[(size_t)NB*NH*NS*ND];  // q hi [B,H,S,D] (pre-scaled 1/8)
__device__ __nv_bfloat16 g_ql[(size_t)NB*NH*NS*ND];
__device__ __nv_bfloat16 g_kh[(size_t)NB*NH*NS*ND];  // k hi [B,H,S,D]
__device__ __nv_bfloat16 g_kl[(size_t)NB*NH*NS*ND];
__device__ __nv_bfloat16 g_vth[(size_t)NB*NH*NS*ND]; // v hi TRANSPOSED [B,H,D,S]
__device__ __nv_bfloat16 g_vtl[(size_t)NB*NH*NS*ND];
__device__ __nv_bfloat16 g_chi[(size_t)NM*NFILT];    // concat hi [B,S,H*D]
__device__ __nv_bfloat16 g_clo[(size_t)NM*NFILT];
__device__ __nv_bfloat16 g_ahi[(size_t)NM*NF];       // split x inputs
__device__ __nv_bfloat16 g_alo[(size_t)NM*NF];
__device__ __nv_bfloat16 g_whi[(size_t)512*512];
__device__ __nv_bfloat16 g_wlo[(size_t)512*512];

__device__ __forceinline__ u32 pack_bf2(float a, float b) {
    __nv_bfloat16 ha = __float2bfloat16(a), hb = __float2bfloat16(b);
    return (u32)__bfloat16_as_ushort(ha) | ((u32)__bfloat16_as_ushort(hb) << 16);
}

// mma.m16n8k16 row.col f32 += bf16*bf16
__device__ __forceinline__ void mma16816(float* c, const u32* a, u32 b0, u32 b1) {
    asm volatile(
        "mma.sync.aligned.m16n8k16.row.col.f32.bf16.bf16.f32 "
        "{%0,%1,%2,%3}, {%4,%5,%6,%7}, {%8,%9}, {%0,%1,%2,%3};"
        : "+f"(c[0]), "+f"(c[1]), "+f"(c[2]), "+f"(c[3])
        : "r"(a[0]), "r"(a[1]), "r"(a[2]), "r"(a[3]), "r"(b0), "r"(b1));
}

// ---------------------------------------------------------------------------
// split_f: elementwise fp32 -> (hi, lo) bf16. n4 = element count / 4.
// ---------------------------------------------------------------------------
__global__ __launch_bounds__(256) void split_f(
    const float* __restrict__ src,
    __nv_bfloat16* __restrict__ hi, __nv_bfloat16* __restrict__ lo, int n4)
{
    int i = blockIdx.x * 256 + threadIdx.x;
    if (i >= n4) return;
    float4 x = ((const float4*)src)[i];
    float xv[4] = {x.x, x.y, x.z, x.w};
    unsigned short hw[4], lw[4];
    #pragma unroll
    for (int j = 0; j < 4; j++) {
        __nv_bfloat16 h = __float2bfloat16(xv[j]);
        __nv_bfloat16 l = __float2bfloat16(xv[j] - __bfloat162float(h));
        hw[j] = __bfloat16_as_ushort(h);
        lw[j] = __bfloat16_as_ushort(l);
    }
    ((uint2*)hi)[i] = make_uint2((u32)hw[0] | ((u32)hw[1] << 16),
                                 (u32)hw[2] | ((u32)hw[3] << 16));
    ((uint2*)lo)[i] = make_uint2((u32)lw[0] | ((u32)lw[1] << 16),
                                 (u32)lw[2] | ((u32)lw[3] << 16));
}

// ---------------------------------------------------------------------------
// mma_gemm: C[128,64] = A[128,512] @ B[512,64-slice] + bias, wmma bf16x3.
// MODE 0: bf16 hi/lo out [b,h,s,64]        (k)
// MODE 1: MODE 0 + 0.125 scale             (q)
// MODE 2: fp32 out[m, ng0+64]              (final)
// MODE 3: bf16 hi/lo out TRANSPOSED [b,h,64,s]  (v)
// grid (NM/128, 8), block 256 (warps 4x2, warp tile 32x32).
// ---------------------------------------------------------------------------
#define ALD 24
#define BLD 72
#define CLD 72
#define CLDT 132
#define SB_OFF (36864/4)

template<int MODE>
__global__ __launch_bounds__(256) void mma_gemm(
    const __nv_bfloat16* __restrict__ Ahi, const __nv_bfloat16* __restrict__ Alo,
    const __nv_bfloat16* __restrict__ Whi, const __nv_bfloat16* __restrict__ Wlo,
    const float* __restrict__ bias,
    __nv_bfloat16* __restrict__ ohi, __nv_bfloat16* __restrict__ olo,
    float* __restrict__ out32, int ldw, size_t wstride)
{
    __shared__ char smraw[37120];
    __nv_bfloat16* Ah = (__nv_bfloat16*)smraw;
    __nv_bfloat16* Al = Ah + 128 * ALD;
    __nv_bfloat16* Bh = Al + 128 * ALD;
    __nv_bfloat16* Bl = Bh + 16 * BLD;
    float* Csm = (float*)smraw;
    float* sB  = (float*)smraw + SB_OFF;

    const int tid = threadIdx.x;
    const int w = tid >> 5;
    const int wr = w & 3, wc = w >> 2;
    const int m0 = blockIdx.x * 128;
    const int ny = blockIdx.y;
    const int ng0 = ny * 64;

    if (tid < 64) sB[tid] = bias[ng0 + tid];

    const __nv_bfloat16* Ab_hi = Ahi + (size_t)m0 * NF;
    const __nv_bfloat16* Ab_lo = Alo + (size_t)m0 * NF;
    const __nv_bfloat16* Wb_hi = Whi + (size_t)ny * wstride;
    const __nv_bfloat16* Wb_lo = Wlo + (size_t)ny * wstride;

    wmma::fragment<wmma::accumulator, 16, 16, 16, float> acc[2][2];
    #pragma unroll
    for (int i = 0; i < 2; i++)
        #pragma unroll
        for (int j = 0; j < 2; j++) wmma::fill_fragment(acc[i][j], 0.0f);

    const int ar = tid >> 1, ah = tid & 1;
    const int bk = tid >> 3, bg = (tid & 7) * 8;

    for (int k0 = 0; k0 < NF; k0 += 16) {
        __syncthreads();
        *(uint4*)(Ah + ar * ALD + ah * 8) =
            *(const uint4*)(Ab_hi + (size_t)ar * NF + k0 + ah * 8);
        *(uint4*)(Al + ar * ALD + ah * 8) =
            *(const uint4*)(Ab_lo + (size_t)ar * NF + k0 + ah * 8);
        if (tid < 128) {
            *(uint4*)(Bh + bk * BLD + bg) =
                *(const uint4*)(Wb_hi + (size_t)(k0 + bk) * ldw + bg);
            *(uint4*)(Bl + bk * BLD + bg) =
                *(const uint4*)(Wb_lo + (size_t)(k0 + bk) * ldw + bg);
        }
        __syncthreads();

        wmma::fragment<wmma::matrix_a, 16, 16, 16, __nv_bfloat16, wmma::row_major> a_hi[2], a_lo[2];
        wmma::fragment<wmma::matrix_b, 16, 16, 16, __nv_bfloat16, wmma::row_major> b_hi[2], b_lo[2];
        #pragma unroll
        for (int i = 0; i < 2; i++) {
            wmma::load_matrix_sync(a_hi[i], Ah + (wr * 32 + i * 16) * ALD, ALD);
            wmma::load_matrix_sync(a_lo[i], Al + (wr * 32 + i * 16) * ALD, ALD);
            wmma::load_matrix_sync(b_hi[i], Bh + wc * 32 + i * 16, BLD);
            wmma::load_matrix_sync(b_lo[i], Bl + wc * 32 + i * 16, BLD);
        }
        #pragma unroll
        for (int i = 0; i < 2; i++)
            #pragma unroll
            for (int j = 0; j < 2; j++) {
                wmma::mma_sync(acc[i][j], a_hi[i], b_hi[j], acc[i][j]);
                wmma::mma_sync(acc[i][j], a_hi[i], b_lo[j], acc[i][j]);
                wmma::mma_sync(acc[i][j], a_lo[i], b_hi[j], acc[i][j]);
            }
    }
    __syncthreads();

    if (MODE == 3) {
        #pragma unroll
        for (int i = 0; i < 2; i++)
            #pragma unroll
            for (int j = 0; j < 2; j++)
                wmma::store_matrix_sync(
                    Csm + (wr * 32 + i * 16) + (wc * 32 + j * 16) * CLDT,
                    acc[i][j], CLDT, wmma::mem_col_major);
    } else {
        #pragma unroll
        for (int i = 0; i < 2; i++)
            #pragma unroll
            for (int j = 0; j < 2; j++)
                wmma::store_matrix_sync(
                    Csm + (wr * 32 + i * 16) * CLD + (wc * 32 + j * 16),
                    acc[i][j], CLD, wmma::mem_row_major);
    }
    __syncthreads();

    const int bb = m0 >> 11, ss0 = m0 & (NS - 1);
    if (MODE == 2) {
        float* ob = out32 + (size_t)m0 * NFILT + ng0;
        #pragma unroll
        for (int r = 0; r < 8; r++) {
            int u = r * 256 + tid;
            int row = u >> 4, c4 = (u & 15) << 2;
            const float* cs = Csm + row * CLD + c4;
            const float* bi = sB + c4;
            *(float4*)(ob + (size_t)row * NFILT + c4) =
                make_float4(cs[0] + bi[0], cs[1] + bi[1], cs[2] + bi[2], cs[3] + bi[3]);
        }
    } else if (MODE == 3) {
        // transposed write: rows d=0..63, cols s=0..127. 4 threads per d row.
        const int d = tid >> 2, sseg = (tid & 3) * 32;
        float bi = sB[d];
        const float* cs = Csm + d * CLDT + sseg;
        __nv_bfloat16* oh = ohi + ((size_t)(bb * NH + ny) * ND + d) * NS + ss0 + sseg;
        __nv_bfloat16* ol = olo + ((size_t)(bb * NH + ny) * ND + d) * NS + ss0 + sseg;
        #pragma unroll
        for (int g = 0; g < 4; g++) {
            u32 hw[4], lw[4];
            #pragma unroll
            for (int q2 = 0; q2 < 4; q2++) {
                float a = cs[g * 8 + q2 * 2] + bi;
                float b = cs[g * 8 + q2 * 2 + 1] + bi;
                __nv_bfloat16 ha = __float2bfloat16(a), hb2 = __float2bfloat16(b);
                hw[q2] = (u32)__bfloat16_as_ushort(ha) | ((u32)__bfloat16_as_ushort(hb2) << 16);
                lw[q2] = pack_bf2(a - __bfloat162float(ha), b - __bfloat162float(hb2));
            }
            *(uint4*)(oh + g * 8) = make_uint4(hw[0], hw[1], hw[2], hw[3]);
            *(uint4*)(ol + g * 8) = make_uint4(lw[0], lw[1], lw[2], lw[3]);
        }
    } else {
        __nv_bfloat16* oh = ohi + ((size_t)(bb * NH + ny) * NS + ss0) * ND;
        __nv_bfloat16* ol = olo + ((size_t)(bb * NH + ny) * NS + ss0) * ND;
        #pragma unroll
        for (int r = 0; r < 8; r++) {
            int u = r * 256 + tid;
            int row = u >> 4, c4 = (u & 15) << 2;
            const float* cs = Csm + row * CLD + c4;
            const float* bi = sB + c4;
            float vv[4];
            #pragma unroll
            for (int i = 0; i < 4; i++) {
                vv[i] = cs[i] + bi[i];
                if (MODE == 1) vv[i] *= 0.125f;
            }
            unsigned short hw[4], lw[4];
            #pragma unroll
            for (int i = 0; i < 4; i++) {
                __nv_bfloat16 h = __float2bfloat16(vv[i]);
                __nv_bfloat16 l = __float2bfloat16(vv[i] - __bfloat162float(h));
                hw[i] = __bfloat16_as_ushort(h);
                lw[i] = __bfloat16_as_ushort(l);
            }
            *(uint2*)(oh + (size_t)row * ND + c4) =
                make_uint2((u32)hw[0] | ((u32)hw[1] << 16), (u32)hw[2] | ((u32)hw[3] << 16));
            *(uint2*)(ol + (size_t)row * ND + c4) =
                make_uint2((u32)lw[0] | ((u32)lw[1] << 16), (u32)lw[2] | ((u32)lw[3] << 16));
        }
    }
}

// ---------------------------------------------------------------------------
// attn_fa2: FlashAttention-2 with raw mma.m16n8k16, register-resident P & O.
// 8 warps x 16 q-rows = 128 q-rows/CTA; 64-key tiles; per-warp softmax.
// smem: K hi/lo [64][72] + Vt hi/lo [64][72] = 36864 B. 2 CTAs/SM.
// grid (NS/128, B*H), block 256.
// ---------------------------------------------------------------------------
__global__ __launch_bounds__(256, 2) void attn_fa2(
    const __nv_bfloat16* __restrict__ qh, const __nv_bfloat16* __restrict__ ql,
    const __nv_bfloat16* __restrict__ kh, const __nv_bfloat16* __restrict__ kl,
    const __nv_bfloat16* __restrict__ vth, const __nv_bfloat16* __restrict__ vtl,
    __nv_bfloat16* __restrict__ chi, __nv_bfloat16* __restrict__ clo)
{
    __shared__ __nv_bfloat16 sKh[64 * 72];
    __shared__ __nv_bfloat16 sKl[64 * 72];
    __shared__ __nv_bfloat16 sVh[64 * 72];   // transposed: [d][key]
    __shared__ __nv_bfloat16 sVl[64 * 72];

    const int tid = threadIdx.x;
    const int w = tid >> 5, lane = tid & 31;
    const int g = lane >> 2, t = lane & 3;
    const int bh = blockIdx.y, bb = bh >> 3, hh = bh & 7;
    const int s0 = blockIdx.x * 128;
    const int qr0 = s0 + w * 16;

    const __nv_bfloat16* khb = kh + (size_t)bh * NS * ND;
    const __nv_bfloat16* klb = kl + (size_t)bh * NS * ND;
    const __nv_bfloat16* vhb = vth + (size_t)bh * ND * NS;  // [d][s]
    const __nv_bfloat16* vlb = vtl + (size_t)bh * ND * NS;

    // ---- load Q fragments once (rows g, g+8 of this warp's 16) ----
    u32 aqh[4][4], aql[4][4];
    {
        const __nv_bfloat16* q0h = qh + ((size_t)bh * NS + qr0 + g) * ND;
        const __nv_bfloat16* q8h = q0h + (size_t)8 * ND;
        const __nv_bfloat16* q0l = ql + ((size_t)bh * NS + qr0 + g) * ND;
        const __nv_bfloat16* q8l = q0l + (size_t)8 * ND;
        #pragma unroll
        for (int s = 0; s < 4; s++) {
            int c0 = 16 * s + 2 * t;
            aqh[s][0] = *(const u32*)(q0h + c0);
            aqh[s][1] = *(const u32*)(q8h + c0);
            aqh[s][2] = *(const u32*)(q0h + c0 + 8);
            aqh[s][3] = *(const u32*)(q8h + c0 + 8);
            aql[s][0] = *(const u32*)(q0l + c0);
            aql[s][1] = *(const u32*)(q8l + c0);
            aql[s][2] = *(const u32*)(q0l + c0 + 8);
            aql[s][3] = *(const u32*)(q8l + c0 + 8);
        }
    }

    float O[8][4];
    #pragma unroll
    for (int j = 0; j < 8; j++) { O[j][0] = O[j][1] = O[j][2] = O[j][3] = 0.0f; }
    float m0 = -1e30f, m1 = -1e30f, l0 = 0.0f, l1 = 0.0f;

    for (int kt = 0; kt < NS; kt += 64) {
        __syncthreads();
        // load K tile [key][d] and Vt tile [d][key], 128B rows, padded 144B
        #pragma unroll
        for (int u = 0; u < 2; u++) {
            int i = u * 256 + tid;           // 512 uint4 per buffer
            int r = i >> 3, c = (i & 7) * 8; // c in bf16 elems (16B units)
            *(uint4*)(sKh + r * 72 + c) = *(const uint4*)(khb + (size_t)(kt + r) * ND + c);
            *(uint4*)(sKl + r * 72 + c) = *(const uint4*)(klb + (size_t)(kt + r) * ND + c);
            *(uint4*)(sVh + r * 72 + c) = *(const uint4*)(vhb + (size_t)r * NS + kt + c);
            *(uint4*)(sVl + r * 72 + c) = *(const uint4*)(vlb + (size_t)r * NS + kt + c);
        }
        __syncthreads();

        // ---- S = Q @ K^T (bf16x3): 8 n8-tiles (keys), 4 k16 steps (d) ----
        float c[8][4];
        #pragma unroll
        for (int j = 0; j < 8; j++) { c[j][0] = c[j][1] = c[j][2] = c[j][3] = 0.0f; }
        #pragma unroll
        for (int j = 0; j < 8; j++) {
            const __nv_bfloat16* krh = sKh + (8 * j + g) * 72;
            const __nv_bfloat16* krl = sKl + (8 * j + g) * 72;
            #pragma unroll
            for (int s = 0; s < 4; s++) {
                int c0 = 16 * s + 2 * t;
                u32 bh0 = *(const u32*)(krh + c0);
                u32 bh1 = *(const u32*)(krh + c0 + 8);
                u32 bl0 = *(const u32*)(krl + c0);
                u32 bl1 = *(const u32*)(krl + c0 + 8);
                mma16816(c[j], aqh[s], bh0, bh1);
                mma16816(c[j], aqh[s], bl0, bl1);
                mma16816(c[j], aql[s], bh0, bh1);
            }
        }

        // ---- softmax in registers (rows g, g+8; quad reduce) ----
        float mx0 = c[0][0], mx1 = c[0][2];
        #pragma unroll
        for (int j = 0; j < 8; j++) {
            mx0 = fmaxf(mx0, fmaxf(c[j][0], c[j][1]));
            mx1 = fmaxf(mx1, fmaxf(c[j][2], c[j][3]));
        }
        mx0 = fmaxf(mx0, __shfl_xor_sync(0xffffffffu, mx0, 1));
        mx0 = fmaxf(mx0, __shfl_xor_sync(0xffffffffu, mx0, 2));
        mx1 = fmaxf(mx1, __shfl_xor_sync(0xffffffffu, mx1, 1));
        mx1 = fmaxf(mx1, __shfl_xor_sync(0xffffffffu, mx1, 2));
        float mn0 = fmaxf(m0, mx0), mn1 = fmaxf(m1, mx1);
        float al0 = __expf(m0 - mn0), al1 = __expf(m1 - mn1);
        m0 = mn0; m1 = mn1;
        float s0r = 0.0f, s1r = 0.0f;
        #pragma unroll
        for (int j = 0; j < 8; j++) {
            c[j][0] = __expf(c[j][0] - mn0); s0r += c[j][0];
            c[j][1] = __expf(c[j][1] - mn0); s0r += c[j][1];
            c[j][2] = __expf(c[j][2] - mn1); s1r += c[j][2];
            c[j][3] = __expf(c[j][3] - mn1); s1r += c[j][3];
        }
        s0r += __shfl_xor_sync(0xffffffffu, s0r, 1);
        s0r += __shfl_xor_sync(0xffffffffu, s0r, 2);
        s1r += __shfl_xor_sync(0xffffffffu, s1r, 1);
        s1r += __shfl_xor_sync(0xffffffffu, s1r, 2);
        l0 = l0 * al0 + s0r;
        l1 = l1 * al1 + s1r;
        #pragma unroll
        for (int j = 0; j < 8; j++) {
            O[j][0] *= al0; O[j][1] *= al0; O[j][2] *= al1; O[j][3] *= al1;
        }

        // ---- P fragments from C registers (A-layout == C-layout) ----
        u32 ph[4][4], pl[4][4];
        #pragma unroll
        for (int s = 0; s < 4; s++) {
            #pragma unroll
            for (int hcell = 0; hcell < 2; hcell++) {
                int j = 2 * s + hcell;
                float p0 = c[j][0], p1 = c[j][1], p2 = c[j][2], p3 = c[j][3];
                __nv_bfloat16 h0 = __float2bfloat16(p0), h1 = __float2bfloat16(p1);
                __nv_bfloat16 h2 = __float2bfloat16(p2), h3 = __float2bfloat16(p3);
                ph[s][2 * hcell]     = (u32)__bfloat16_as_ushort(h0) | ((u32)__bfloat16_as_ushort(h1) << 16);
                ph[s][2 * hcell + 1] = (u32)__bfloat16_as_ushort(h2) | ((u32)__bfloat16_as_ushort(h3) << 16);
                pl[s][2 * hcell]     = pack_bf2(p0 - __bfloat162float(h0), p1 - __bfloat162float(h1));
                pl[s][2 * hcell + 1] = pack_bf2(p2 - __bfloat162float(h2), p3 - __bfloat162float(h3));
            }
        }

        // ---- O += P @ V (bf16x3): 8 d-tiles, 4 k16 steps (keys) ----
        #pragma unroll
        for (int j = 0; j < 8; j++) {
            const __nv_bfloat16* vrh = sVh + (8 * j + g) * 72;
            const __nv_bfloat16* vrl = sVl + (8 * j + g) * 72;
            #pragma unroll
            for (int s = 0; s < 4; s++) {
                int c0 = 16 * s + 2 * t;
                u32 vh0 = *(const u32*)(vrh + c0);
                u32 vh1 = *(const u32*)(vrh + c0 + 8);
                u32 vl0 = *(const u32*)(vrl + c0);
                u32 vl1 = *(const u32*)(vrl + c0 + 8);
                mma16816(O[j], ph[s], vh0, vh1);
                mma16816(O[j], ph[s], vl0, vl1);
                mma16816(O[j], pl[s], vh0, vh1);
            }
        }
    }

    // ---- epilogue: normalize, split hi/lo, write concat [B,S,H*D] ----
    float inv0 = 1.0f / l0, inv1 = 1.0f / l1;
    size_t r0off = ((size_t)bb * NS + qr0 + g) * NFILT + hh * ND;
    size_t r8off = r0off + (size_t)8 * NFILT;
    #pragma unroll
    for (int j = 0; j < 8; j++) {
        int col = 8 * j + 2 * t;
        float v0 = O[j][0] * inv0, v1 = O[j][1] * inv0;
        float v2 = O[j][2] * inv1, v3 = O[j][3] * inv1;
        __nv_bfloat16 h0 = __float2bfloat16(v0), h1 = __float2bfloat16(v1);
        __nv_bfloat16 h2 = __float2bfloat16(v2), h3 = __float2bfloat16(v3);
        *(u32*)(chi + r0off + col) = (u32)__bfloat16_as_ushort(h0) | ((u32)__bfloat16_as_ushort(h1) << 16);
        *(u32*)(chi + r8off + col) = (u32)__bfloat16_as_ushort(h2) | ((u32)__bfloat16_as_ushort(h3) << 16);
        *(u32*)(clo + r0off + col) = pack_bf2(v0 - __bfloat162float(h0), v1 - __bfloat162float(h1));
        *(u32*)(clo + r8off + col) = pack_bf2(v2 - __bfloat162float(h2), v3 - __bfloat162float(h3));
    }
}

// ---------------------------------------------------------------------------
extern "C" void kernel_launch(void* const* d_in, const int* in_sizes, int n_in,
                              void* d_out, int out_size)
{
    (void)in_sizes; (void)n_in; (void)out_size;
    const float* x_q = (const float*)d_in[0];
    const float* x_k = (const float*)d_in[1];
    const float* x_v = (const float*)d_in[2];
    const float* Wq  = (const float*)d_in[3];
    const float* bq  = (const float*)d_in[4];
    const float* Wk  = (const float*)d_in[5];
    const float* bk  = (const float*)d_in[6];
    const float* Wv  = (const float*)d_in[7];
    const float* bv  = (const float*)d_in[8];
    const float* Wo  = (const float*)d_in[9];
    const float* bo  = (const float*)d_in[10];
    float* out = (float*)d_out;

    __nv_bfloat16 *qh, *ql, *kh, *kl, *vth, *vtl, *chi, *clo, *ahi, *alo, *whi, *wlo;
    cudaGetSymbolAddress((void**)&qh, g_qh);
    cudaGetSymbolAddress((void**)&ql, g_ql);
    cudaGetSymbolAddress((void**)&kh, g_kh);
    cudaGetSymbolAddress((void**)&kl, g_kl);
    cudaGetSymbolAddress((void**)&vth, g_vth);
    cudaGetSymbolAddress((void**)&vtl, g_vtl);
    cudaGetSymbolAddress((void**)&chi, g_chi);
    cudaGetSymbolAddress((void**)&clo, g_clo);
    cudaGetSymbolAddress((void**)&ahi, g_ahi);
    cudaGetSymbolAddress((void**)&alo, g_alo);
    cudaGetSymbolAddress((void**)&whi, g_whi);
    cudaGetSymbolAddress((void**)&wlo, g_wlo);

    const int NW4 = (512 * 512) / 4;
    const int NX4 = (NM * NF) / 4;
    dim3 ggrid(NM / 128, 8);
    const size_t WSTRIDE_PROJ = (size_t)512 * 64;

    split_f<<<NW4 / 256, 256>>>(Wq, whi, wlo, NW4);
    split_f<<<NX4 / 256, 256>>>(x_q, ahi, alo, NX4);
    mma_gemm<1><<<ggrid, 256>>>(ahi, alo, whi, wlo, bq, qh, ql, nullptr, 64, WSTRIDE_PROJ);

    split_f<<<NW4 / 256, 256>>>(Wk, whi, wlo, NW4);
    split_f<<<NX4 / 256, 256>>>(x_k, ahi, alo, NX4);
    mma_gemm<0><<<ggrid, 256>>>(ahi, alo, whi, wlo, bk, kh, kl, nullptr, 64, WSTRIDE_PROJ);

    split_f<<<NW4 / 256, 256>>>(Wv, whi, wlo, NW4);
    split_f<<<NX4 / 256, 256>>>(x_v, ahi, alo, NX4);
    mma_gemm<3><<<ggrid, 256>>>(ahi, alo, whi, wlo, bv, vth, vtl, nullptr, 64, WSTRIDE_PROJ);

    attn_fa2<<<dim3(NS / 128, NB * NH), 256>>>(qh, ql, kh, kl, vth, vtl, chi, clo);

    split_f<<<NW4 / 256, 256>>>(Wo, whi, wlo, NW4);
    mma_gemm<2><<<ggrid, 256>>>(chi, clo, whi, wlo, bo, nullptr, nullptr, out, 512, (size_t)64);
}

// round 9
// speedup vs baseline: 2.0051x; 1.0960x over previous
#include <cuda_runtime.h>
#include <cuda_bf16.h>
#include <mma.h>

using namespace nvcuda;

typedef unsigned long long u64;
typedef unsigned int u32;

#define NB 4
#define NS 2048
#define NF 512
#define NH 8
#define ND 64
#define NFILT 512
#define NM (NB*NS)

// ---------------- scratch (device globals; no allocation allowed) ----------
__device__ __nv_bfloat16 g_qh[(size_t)NB*NH*NS*ND];  // q hi [B,H,S,D] (pre-scaled 1/8)
__device__ __nv_bfloat16 g_ql[(size_t)NB*NH*NS*ND];
__device__ __nv_bfloat16 g_kh[(size_t)NB*NH*NS*ND];  // k hi [B,H,S,D]
__device__ __nv_bfloat16 g_kl[(size_t)NB*NH*NS*ND];
__device__ __nv_bfloat16 g_vth[(size_t)NB*NH*NS*ND]; // v hi TRANSPOSED [B,H,D,S]
__device__ __nv_bfloat16 g_vtl[(size_t)NB*NH*NS*ND];
__device__ __nv_bfloat16 g_chi[(size_t)NM*NFILT];    // concat hi [B,S,H*D]
__device__ __nv_bfloat16 g_clo[(size_t)NM*NFILT];
__device__ __nv_bfloat16 g_ahi[(size_t)NM*NF];       // split x inputs
__device__ __nv_bfloat16 g_alo[(size_t)NM*NF];
__device__ __nv_bfloat16 g_whi[(size_t)512*512];
__device__ __nv_bfloat16 g_wlo[(size_t)512*512];

__device__ __forceinline__ u32 pack_bf2(float a, float b) {
    __nv_bfloat16 ha = __float2bfloat16(a), hb = __float2bfloat16(b);
    return (u32)__bfloat16_as_ushort(ha) | ((u32)__bfloat16_as_ushort(hb) << 16);
}

// mma.m16n8k16 row.col f32 += bf16*bf16
__device__ __forceinline__ void mma16816(float* c, const u32* a, u32 b0, u32 b1) {
    asm volatile(
        "mma.sync.aligned.m16n8k16.row.col.f32.bf16.bf16.f32 "
        "{%0,%1,%2,%3}, {%4,%5,%6,%7}, {%8,%9}, {%0,%1,%2,%3};"
        : "+f"(c[0]), "+f"(c[1]), "+f"(c[2]), "+f"(c[3])
        : "r"(a[0]), "r"(a[1]), "r"(a[2]), "r"(a[3]), "r"(b0), "r"(b1));
}

// cp.async 16B
__device__ __forceinline__ void cp16(void* sm, const void* gm) {
    u32 sa = (u32)__cvta_generic_to_shared(sm);
    asm volatile("cp.async.cg.shared.global [%0], [%1], 16;" :: "r"(sa), "l"(gm));
}
#define CP_COMMIT() asm volatile("cp.async.commit_group;" ::: "memory")
#define CP_WAIT0()  asm volatile("cp.async.wait_group 0;" ::: "memory")

// ---------------------------------------------------------------------------
// split_f: elementwise fp32 -> (hi, lo) bf16. n4 = element count / 4.
// ---------------------------------------------------------------------------
__global__ __launch_bounds__(256) void split_f(
    const float* __restrict__ src,
    __nv_bfloat16* __restrict__ hi, __nv_bfloat16* __restrict__ lo, int n4)
{
    int i = blockIdx.x * 256 + threadIdx.x;
    if (i >= n4) return;
    float4 x = ((const float4*)src)[i];
    float xv[4] = {x.x, x.y, x.z, x.w};
    unsigned short hw[4], lw[4];
    #pragma unroll
    for (int j = 0; j < 4; j++) {
        __nv_bfloat16 h = __float2bfloat16(xv[j]);
        __nv_bfloat16 l = __float2bfloat16(xv[j] - __bfloat162float(h));
        hw[j] = __bfloat16_as_ushort(h);
        lw[j] = __bfloat16_as_ushort(l);
    }
    ((uint2*)hi)[i] = make_uint2((u32)hw[0] | ((u32)hw[1] << 16),
                                 (u32)hw[2] | ((u32)hw[3] << 16));
    ((uint2*)lo)[i] = make_uint2((u32)lw[0] | ((u32)lw[1] << 16),
                                 (u32)lw[2] | ((u32)lw[3] << 16));
}

// ---------------------------------------------------------------------------
// mma_gemm: C[128,64] = A[128,512] @ B[512,64-slice] + bias, wmma bf16x3,
// cp.async double-buffered (1 sync per k-step).
// MODE 0: bf16 hi/lo out [b,h,s,64] (k)   MODE 1: +0.125 scale (q)
// MODE 2: fp32 out (final)                MODE 3: transposed [b,h,64,s] (v)
// grid (NM/128, 8), block 256 (warps 4x2, warp tile 32x32).
// ---------------------------------------------------------------------------
#define ALD 24
#define BLD 72
#define CLD 72
#define CLDT 132
#define STG_EL 8448      // bf16 elems per stage: 2*128*24 + 2*16*72
#define SB_OFF (36864/4)

template<int MODE>
__global__ __launch_bounds__(256) void mma_gemm(
    const __nv_bfloat16* __restrict__ Ahi, const __nv_bfloat16* __restrict__ Alo,
    const __nv_bfloat16* __restrict__ Whi, const __nv_bfloat16* __restrict__ Wlo,
    const float* __restrict__ bias,
    __nv_bfloat16* __restrict__ ohi, __nv_bfloat16* __restrict__ olo,
    float* __restrict__ out32, int ldw, size_t wstride)
{
    __shared__ char smraw[37120];
    float* Csm = (float*)smraw;
    float* sB  = (float*)smraw + SB_OFF;

    const int tid = threadIdx.x;
    const int w = tid >> 5;
    const int wr = w & 3, wc = w >> 2;
    const int m0 = blockIdx.x * 128;
    const int ny = blockIdx.y;
    const int ng0 = ny * 64;

    if (tid < 64) sB[tid] = bias[ng0 + tid];

    const __nv_bfloat16* Ab_hi = Ahi + (size_t)m0 * NF;
    const __nv_bfloat16* Ab_lo = Alo + (size_t)m0 * NF;
    const __nv_bfloat16* Wb_hi = Whi + (size_t)ny * wstride;
    const __nv_bfloat16* Wb_lo = Wlo + (size_t)ny * wstride;

    wmma::fragment<wmma::accumulator, 16, 16, 16, float> acc[2][2];
    #pragma unroll
    for (int i = 0; i < 2; i++)
        #pragma unroll
        for (int j = 0; j < 2; j++) wmma::fill_fragment(acc[i][j], 0.0f);

    const int ar = tid >> 1, ah = tid & 1;
    const int bk = tid >> 3, bg = (tid & 7) * 8;

    __nv_bfloat16* stg = (__nv_bfloat16*)smraw;
    // prefetch stage 0 (k0 = 0)
    {
        __nv_bfloat16* Ah = stg; __nv_bfloat16* Al = stg + 3072;
        __nv_bfloat16* Bh = stg + 6144; __nv_bfloat16* Bl = stg + 7296;
        cp16(Ah + ar * ALD + ah * 8, Ab_hi + (size_t)ar * NF + ah * 8);
        cp16(Al + ar * ALD + ah * 8, Ab_lo + (size_t)ar * NF + ah * 8);
        if (tid < 128) {
            cp16(Bh + bk * BLD + bg, Wb_hi + (size_t)bk * ldw + bg);
            cp16(Bl + bk * BLD + bg, Wb_lo + (size_t)bk * ldw + bg);
        }
        CP_COMMIT();
    }

    for (int k0 = 0; k0 < NF; k0 += 16) {
        const int st = (k0 >> 4) & 1;
        CP_WAIT0();
        __syncthreads();
        if (k0 + 16 < NF) {
            __nv_bfloat16* nb = stg + (st ^ 1) * STG_EL;
            __nv_bfloat16* Ah = nb; __nv_bfloat16* Al = nb + 3072;
            __nv_bfloat16* Bh = nb + 6144; __nv_bfloat16* Bl = nb + 7296;
            cp16(Ah + ar * ALD + ah * 8, Ab_hi + (size_t)ar * NF + k0 + 16 + ah * 8);
            cp16(Al + ar * ALD + ah * 8, Ab_lo + (size_t)ar * NF + k0 + 16 + ah * 8);
            if (tid < 128) {
                cp16(Bh + bk * BLD + bg, Wb_hi + (size_t)(k0 + 16 + bk) * ldw + bg);
                cp16(Bl + bk * BLD + bg, Wb_lo + (size_t)(k0 + 16 + bk) * ldw + bg);
            }
            CP_COMMIT();
        }
        const __nv_bfloat16* cb = stg + st * STG_EL;
        const __nv_bfloat16* Ah = cb; const __nv_bfloat16* Al = cb + 3072;
        const __nv_bfloat16* Bh = cb + 6144; const __nv_bfloat16* Bl = cb + 7296;

        wmma::fragment<wmma::matrix_a, 16, 16, 16, __nv_bfloat16, wmma::row_major> a_hi[2], a_lo[2];
        wmma::fragment<wmma::matrix_b, 16, 16, 16, __nv_bfloat16, wmma::row_major> b_hi[2], b_lo[2];
        #pragma unroll
        for (int i = 0; i < 2; i++) {
            wmma::load_matrix_sync(a_hi[i], Ah + (wr * 32 + i * 16) * ALD, ALD);
            wmma::load_matrix_sync(a_lo[i], Al + (wr * 32 + i * 16) * ALD, ALD);
            wmma::load_matrix_sync(b_hi[i], Bh + wc * 32 + i * 16, BLD);
            wmma::load_matrix_sync(b_lo[i], Bl + wc * 32 + i * 16, BLD);
        }
        #pragma unroll
        for (int i = 0; i < 2; i++)
            #pragma unroll
            for (int j = 0; j < 2; j++) {
                wmma::mma_sync(acc[i][j], a_hi[i], b_hi[j], acc[i][j]);
                wmma::mma_sync(acc[i][j], a_hi[i], b_lo[j], acc[i][j]);
                wmma::mma_sync(acc[i][j], a_lo[i], b_hi[j], acc[i][j]);
            }
        __syncthreads();
    }

    if (MODE == 3) {
        #pragma unroll
        for (int i = 0; i < 2; i++)
            #pragma unroll
            for (int j = 0; j < 2; j++)
                wmma::store_matrix_sync(
                    Csm + (wr * 32 + i * 16) + (wc * 32 + j * 16) * CLDT,
                    acc[i][j], CLDT, wmma::mem_col_major);
    } else {
        #pragma unroll
        for (int i = 0; i < 2; i++)
            #pragma unroll
            for (int j = 0; j < 2; j++)
                wmma::store_matrix_sync(
                    Csm + (wr * 32 + i * 16) * CLD + (wc * 32 + j * 16),
                    acc[i][j], CLD, wmma::mem_row_major);
    }
    __syncthreads();

    const int bb = m0 >> 11, ss0 = m0 & (NS - 1);
    if (MODE == 2) {
        float* ob = out32 + (size_t)m0 * NFILT + ng0;
        #pragma unroll
        for (int r = 0; r < 8; r++) {
            int u = r * 256 + tid;
            int row = u >> 4, c4 = (u & 15) << 2;
            const float* cs = Csm + row * CLD + c4;
            const float* bi = sB + c4;
            *(float4*)(ob + (size_t)row * NFILT + c4) =
                make_float4(cs[0] + bi[0], cs[1] + bi[1], cs[2] + bi[2], cs[3] + bi[3]);
        }
    } else if (MODE == 3) {
        const int d = tid >> 2, sseg = (tid & 3) * 32;
        float bi = sB[d];
        const float* cs = Csm + d * CLDT + sseg;
        __nv_bfloat16* oh = ohi + ((size_t)(bb * NH + ny) * ND + d) * NS + ss0 + sseg;
        __nv_bfloat16* ol = olo + ((size_t)(bb * NH + ny) * ND + d) * NS + ss0 + sseg;
        #pragma unroll
        for (int g = 0; g < 4; g++) {
            u32 hw[4], lw[4];
            #pragma unroll
            for (int q2 = 0; q2 < 4; q2++) {
                float a = cs[g * 8 + q2 * 2] + bi;
                float b = cs[g * 8 + q2 * 2 + 1] + bi;
                __nv_bfloat16 ha = __float2bfloat16(a), hb2 = __float2bfloat16(b);
                hw[q2] = (u32)__bfloat16_as_ushort(ha) | ((u32)__bfloat16_as_ushort(hb2) << 16);
                lw[q2] = pack_bf2(a - __bfloat162float(ha), b - __bfloat162float(hb2));
            }
            *(uint4*)(oh + g * 8) = make_uint4(hw[0], hw[1], hw[2], hw[3]);
            *(uint4*)(ol + g * 8) = make_uint4(lw[0], lw[1], lw[2], lw[3]);
        }
    } else {
        __nv_bfloat16* oh = ohi + ((size_t)(bb * NH + ny) * NS + ss0) * ND;
        __nv_bfloat16* ol = olo + ((size_t)(bb * NH + ny) * NS + ss0) * ND;
        #pragma unroll
        for (int r = 0; r < 8; r++) {
            int u = r * 256 + tid;
            int row = u >> 4, c4 = (u & 15) << 2;
            const float* cs = Csm + row * CLD + c4;
            const float* bi = sB + c4;
            float vv[4];
            #pragma unroll
            for (int i = 0; i < 4; i++) {
                vv[i] = cs[i] + bi[i];
                if (MODE == 1) vv[i] *= 0.125f;
            }
            unsigned short hw[4], lw[4];
            #pragma unroll
            for (int i = 0; i < 4; i++) {
                __nv_bfloat16 h = __float2bfloat16(vv[i]);
                __nv_bfloat16 l = __float2bfloat16(vv[i] - __bfloat162float(h));
                hw[i] = __bfloat16_as_ushort(h);
                lw[i] = __bfloat16_as_ushort(l);
            }
            *(uint2*)(oh + (size_t)row * ND + c4) =
                make_uint2((u32)hw[0] | ((u32)hw[1] << 16), (u32)hw[2] | ((u32)hw[3] << 16));
            *(uint2*)(ol + (size_t)row * ND + c4) =
                make_uint2((u32)lw[0] | ((u32)lw[1] << 16), (u32)lw[2] | ((u32)lw[3] << 16));
        }
    }
}

// ---------------------------------------------------------------------------
// attn_fa2: FlashAttention-2, raw mma.m16n8k16, register P & O, cp.async
// double-buffered K/V stages. 8 warps x 16 q-rows; 64-key tiles.
// dyn smem: 2 stages x (Kh,Kl,Vh,Vl)[64][72]bf16 = 73728 B. 2 CTAs/SM.
// ---------------------------------------------------------------------------
#define TSTG 18432   // bf16 elems per stage
#define ATTN_BYTES (2 * TSTG * 2)

__global__ __launch_bounds__(256, 2) void attn_fa2(
    const __nv_bfloat16* __restrict__ qh, const __nv_bfloat16* __restrict__ ql,
    const __nv_bfloat16* __restrict__ kh, const __nv_bfloat16* __restrict__ kl,
    const __nv_bfloat16* __restrict__ vth, const __nv_bfloat16* __restrict__ vtl,
    __nv_bfloat16* __restrict__ chi, __nv_bfloat16* __restrict__ clo)
{
    extern __shared__ __nv_bfloat16 smb[];

    const int tid = threadIdx.x;
    const int w = tid >> 5, lane = tid & 31;
    const int g = lane >> 2, t = lane & 3;
    const int bh = blockIdx.y, bb = bh >> 3, hh = bh & 7;
    const int s0 = blockIdx.x * 128;
    const int qr0 = s0 + w * 16;

    const __nv_bfloat16* khb = kh + (size_t)bh * NS * ND;
    const __nv_bfloat16* klb = kl + (size_t)bh * NS * ND;
    const __nv_bfloat16* vhb = vth + (size_t)bh * ND * NS;  // [d][s]
    const __nv_bfloat16* vlb = vtl + (size_t)bh * ND * NS;

    // per-thread copy coords (2 rows per thread per buffer)
    const int r1 = tid >> 3, c1 = (tid & 7) * 8;          // rows 0..31
    const int r2 = r1 + 32;                                // rows 32..63

    // ---- prefetch stage 0 (kt = 0) ----
    {
        __nv_bfloat16* sKh = smb; __nv_bfloat16* sKl = smb + 4608;
        __nv_bfloat16* sVh = smb + 9216; __nv_bfloat16* sVl = smb + 13824;
        cp16(sKh + r1 * 72 + c1, khb + (size_t)r1 * ND + c1);
        cp16(sKh + r2 * 72 + c1, khb + (size_t)r2 * ND + c1);
        cp16(sKl + r1 * 72 + c1, klb + (size_t)r1 * ND + c1);
        cp16(sKl + r2 * 72 + c1, klb + (size_t)r2 * ND + c1);
        cp16(sVh + r1 * 72 + c1, vhb + (size_t)r1 * NS + c1);
        cp16(sVh + r2 * 72 + c1, vhb + (size_t)r2 * NS + c1);
        cp16(sVl + r1 * 72 + c1, vlb + (size_t)r1 * NS + c1);
        cp16(sVl + r2 * 72 + c1, vlb + (size_t)r2 * NS + c1);
        CP_COMMIT();
    }

    // ---- load Q fragments once ----
    u32 aqh[4][4], aql[4][4];
    {
        const __nv_bfloat16* q0h = qh + ((size_t)bh * NS + qr0 + g) * ND;
        const __nv_bfloat16* q8h = q0h + (size_t)8 * ND;
        const __nv_bfloat16* q0l = ql + ((size_t)bh * NS + qr0 + g) * ND;
        const __nv_bfloat16* q8l = q0l + (size_t)8 * ND;
        #pragma unroll
        for (int s = 0; s < 4; s++) {
            int c0 = 16 * s + 2 * t;
            aqh[s][0] = *(const u32*)(q0h + c0);
            aqh[s][1] = *(const u32*)(q8h + c0);
            aqh[s][2] = *(const u32*)(q0h + c0 + 8);
            aqh[s][3] = *(const u32*)(q8h + c0 + 8);
            aql[s][0] = *(const u32*)(q0l + c0);
            aql[s][1] = *(const u32*)(q8l + c0);
            aql[s][2] = *(const u32*)(q0l + c0 + 8);
            aql[s][3] = *(const u32*)(q8l + c0 + 8);
        }
    }

    float O[8][4];
    #pragma unroll
    for (int j = 0; j < 8; j++) { O[j][0] = O[j][1] = O[j][2] = O[j][3] = 0.0f; }
    float m0 = -1e30f, m1 = -1e30f, l0 = 0.0f, l1 = 0.0f;

    for (int kt = 0; kt < NS; kt += 64) {
        const int st = (kt >> 6) & 1;
        CP_WAIT0();
        __syncthreads();
        if (kt + 64 < NS) {
            __nv_bfloat16* nb = smb + (st ^ 1) * TSTG;
            __nv_bfloat16* sKh = nb; __nv_bfloat16* sKl = nb + 4608;
            __nv_bfloat16* sVh = nb + 9216; __nv_bfloat16* sVl = nb + 13824;
            int kn = kt + 64;
            cp16(sKh + r1 * 72 + c1, khb + (size_t)(kn + r1) * ND + c1);
            cp16(sKh + r2 * 72 + c1, khb + (size_t)(kn + r2) * ND + c1);
            cp16(sKl + r1 * 72 + c1, klb + (size_t)(kn + r1) * ND + c1);
            cp16(sKl + r2 * 72 + c1, klb + (size_t)(kn + r2) * ND + c1);
            cp16(sVh + r1 * 72 + c1, vhb + (size_t)r1 * NS + kn + c1);
            cp16(sVh + r2 * 72 + c1, vhb + (size_t)r2 * NS + kn + c1);
            cp16(sVl + r1 * 72 + c1, vlb + (size_t)r1 * NS + kn + c1);
            cp16(sVl + r2 * 72 + c1, vlb + (size_t)r2 * NS + kn + c1);
            CP_COMMIT();
        }
        const __nv_bfloat16* cbs = smb + st * TSTG;
        const __nv_bfloat16* sKh = cbs; const __nv_bfloat16* sKl = cbs + 4608;
        const __nv_bfloat16* sVh = cbs + 9216; const __nv_bfloat16* sVl = cbs + 13824;

        // ---- S = Q @ K^T (bf16x3) ----
        float c[8][4];
        #pragma unroll
        for (int j = 0; j < 8; j++) { c[j][0] = c[j][1] = c[j][2] = c[j][3] = 0.0f; }
        #pragma unroll
        for (int j = 0; j < 8; j++) {
            const __nv_bfloat16* krh = sKh + (8 * j + g) * 72;
            const __nv_bfloat16* krl = sKl + (8 * j + g) * 72;
            #pragma unroll
            for (int s = 0; s < 4; s++) {
                int c0 = 16 * s + 2 * t;
                u32 bh0 = *(const u32*)(krh + c0);
                u32 bh1 = *(const u32*)(krh + c0 + 8);
                u32 bl0 = *(const u32*)(krl + c0);
                u32 bl1 = *(const u32*)(krl + c0 + 8);
                mma16816(c[j], aqh[s], bh0, bh1);
                mma16816(c[j], aqh[s], bl0, bl1);
                mma16816(c[j], aql[s], bh0, bh1);
            }
        }

        // ---- softmax in registers ----
        float mx0 = c[0][0], mx1 = c[0][2];
        #pragma unroll
        for (int j = 0; j < 8; j++) {
            mx0 = fmaxf(mx0, fmaxf(c[j][0], c[j][1]));
            mx1 = fmaxf(mx1, fmaxf(c[j][2], c[j][3]));
        }
        mx0 = fmaxf(mx0, __shfl_xor_sync(0xffffffffu, mx0, 1));
        mx0 = fmaxf(mx0, __shfl_xor_sync(0xffffffffu, mx0, 2));
        mx1 = fmaxf(mx1, __shfl_xor_sync(0xffffffffu, mx1, 1));
        mx1 = fmaxf(mx1, __shfl_xor_sync(0xffffffffu, mx1, 2));
        float mn0 = fmaxf(m0, mx0), mn1 = fmaxf(m1, mx1);
        float al0 = __expf(m0 - mn0), al1 = __expf(m1 - mn1);
        m0 = mn0; m1 = mn1;
        float s0r = 0.0f, s1r = 0.0f;
        #pragma unroll
        for (int j = 0; j < 8; j++) {
            c[j][0] = __expf(c[j][0] - mn0); s0r += c[j][0];
            c[j][1] = __expf(c[j][1] - mn0); s0r += c[j][1];
            c[j][2] = __expf(c[j][2] - mn1); s1r += c[j][2];
            c[j][3] = __expf(c[j][3] - mn1); s1r += c[j][3];
        }
        s0r += __shfl_xor_sync(0xffffffffu, s0r, 1);
        s0r += __shfl_xor_sync(0xffffffffu, s0r, 2);
        s1r += __shfl_xor_sync(0xffffffffu, s1r, 1);
        s1r += __shfl_xor_sync(0xffffffffu, s1r, 2);
        l0 = l0 * al0 + s0r;
        l1 = l1 * al1 + s1r;
        #pragma unroll
        for (int j = 0; j < 8; j++) {
            O[j][0] *= al0; O[j][1] *= al0; O[j][2] *= al1; O[j][3] *= al1;
        }

        // ---- P fragments (A-layout == C-layout) ----
        u32 ph[4][4], pl[4][4];
        #pragma unroll
        for (int s = 0; s < 4; s++) {
            #pragma unroll
            for (int hcell = 0; hcell < 2; hcell++) {
                int j = 2 * s + hcell;
                float p0 = c[j][0], p1 = c[j][1], p2 = c[j][2], p3 = c[j][3];
                __nv_bfloat16 h0 = __float2bfloat16(p0), h1 = __float2bfloat16(p1);
                __nv_bfloat16 h2 = __float2bfloat16(p2), h3 = __float2bfloat16(p3);
                ph[s][2 * hcell]     = (u32)__bfloat16_as_ushort(h0) | ((u32)__bfloat16_as_ushort(h1) << 16);
                ph[s][2 * hcell + 1] = (u32)__bfloat16_as_ushort(h2) | ((u32)__bfloat16_as_ushort(h3) << 16);
                pl[s][2 * hcell]     = pack_bf2(p0 - __bfloat162float(h0), p1 - __bfloat162float(h1));
                pl[s][2 * hcell + 1] = pack_bf2(p2 - __bfloat162float(h2), p3 - __bfloat162float(h3));
            }
        }

        // ---- O += P @ V (bf16x3) ----
        #pragma unroll
        for (int j = 0; j < 8; j++) {
            const __nv_bfloat16* vrh = sVh + (8 * j + g) * 72;
            const __nv_bfloat16* vrl = sVl + (8 * j + g) * 72;
            #pragma unroll
            for (int s = 0; s < 4; s++) {
                int c0 = 16 * s + 2 * t;
                u32 vh0 = *(const u32*)(vrh + c0);
                u32 vh1 = *(const u32*)(vrh + c0 + 8);
                u32 vl0 = *(const u32*)(vrl + c0);
                u32 vl1 = *(const u32*)(vrl + c0 + 8);
                mma16816(O[j], ph[s], vh0, vh1);
                mma16816(O[j], ph[s], vl0, vl1);
                mma16816(O[j], pl[s], vh0, vh1);
            }
        }
        __syncthreads();
    }

    // ---- epilogue ----
    float inv0 = 1.0f / l0, inv1 = 1.0f / l1;
    size_t r0off = ((size_t)bb * NS + qr0 + g) * NFILT + hh * ND;
    size_t r8off = r0off + (size_t)8 * NFILT;
    #pragma unroll
    for (int j = 0; j < 8; j++) {
        int col = 8 * j + 2 * t;
        float v0 = O[j][0] * inv0, v1 = O[j][1] * inv0;
        float v2 = O[j][2] * inv1, v3 = O[j][3] * inv1;
        __nv_bfloat16 h0 = __float2bfloat16(v0), h1 = __float2bfloat16(v1);
        __nv_bfloat16 h2 = __float2bfloat16(v2), h3 = __float2bfloat16(v3);
        *(u32*)(chi + r0off + col) = (u32)__bfloat16_as_ushort(h0) | ((u32)__bfloat16_as_ushort(h1) << 16);
        *(u32*)(chi + r8off + col) = (u32)__bfloat16_as_ushort(h2) | ((u32)__bfloat16_as_ushort(h3) << 16);
        *(u32*)(clo + r0off + col) = pack_bf2(v0 - __bfloat162float(h0), v1 - __bfloat162float(h1));
        *(u32*)(clo + r8off + col) = pack_bf2(v2 - __bfloat162float(h2), v3 - __bfloat162float(h3));
    }
}

// ---------------------------------------------------------------------------
extern "C" void kernel_launch(void* const* d_in, const int* in_sizes, int n_in,
                              void* d_out, int out_size)
{
    (void)in_sizes; (void)n_in; (void)out_size;
    const float* x_q = (const float*)d_in[0];
    const float* x_k = (const float*)d_in[1];
    const float* x_v = (const float*)d_in[2];
    const float* Wq  = (const float*)d_in[3];
    const float* bq  = (const float*)d_in[4];
    const float* Wk  = (const float*)d_in[5];
    const float* bk  = (const float*)d_in[6];
    const float* Wv  = (const float*)d_in[7];
    const float* bv  = (const float*)d_in[8];
    const float* Wo  = (const float*)d_in[9];
    const float* bo  = (const float*)d_in[10];
    float* out = (float*)d_out;

    __nv_bfloat16 *qh, *ql, *kh, *kl, *vth, *vtl, *chi, *clo, *ahi, *alo, *whi, *wlo;
    cudaGetSymbolAddress((void**)&qh, g_qh);
    cudaGetSymbolAddress((void**)&ql, g_ql);
    cudaGetSymbolAddress((void**)&kh, g_kh);
    cudaGetSymbolAddress((void**)&kl, g_kl);
    cudaGetSymbolAddress((void**)&vth, g_vth);
    cudaGetSymbolAddress((void**)&vtl, g_vtl);
    cudaGetSymbolAddress((void**)&chi, g_chi);
    cudaGetSymbolAddress((void**)&clo, g_clo);
    cudaGetSymbolAddress((void**)&ahi, g_ahi);
    cudaGetSymbolAddress((void**)&alo, g_alo);
    cudaGetSymbolAddress((void**)&whi, g_whi);
    cudaGetSymbolAddress((void**)&wlo, g_wlo);

    static int once = 0;
    if (!once) {
        cudaFuncSetAttribute(attn_fa2,
                             cudaFuncAttributeMaxDynamicSharedMemorySize, ATTN_BYTES);
        once = 1;
    }

    const int NW4 = (512 * 512) / 4;
    const int NX4 = (NM * NF) / 4;
    dim3 ggrid(NM / 128, 8);
    const size_t WSTRIDE_PROJ = (size_t)512 * 64;

    split_f<<<NW4 / 256, 256>>>(Wq, whi, wlo, NW4);
    split_f<<<NX4 / 256, 256>>>(x_q, ahi, alo, NX4);
    mma_gemm<1><<<ggrid, 256>>>(ahi, alo, whi, wlo, bq, qh, ql, nullptr, 64, WSTRIDE_PROJ);

    split_f<<<NW4 / 256, 256>>>(Wk, whi, wlo, NW4);
    split_f<<<NX4 / 256, 256>>>(x_k, ahi, alo, NX4);
    mma_gemm<0><<<ggrid, 256>>>(ahi, alo, whi, wlo, bk, kh, kl, nullptr, 64, WSTRIDE_PROJ);

    split_f<<<NW4 / 256, 256>>>(Wv, whi, wlo, NW4);
    split_f<<<NX4 / 256, 256>>>(x_v, ahi, alo, NX4);
    mma_gemm<3><<<ggrid, 256>>>(ahi, alo, whi, wlo, bv, vth, vtl, nullptr, 64, WSTRIDE_PROJ);

    attn_fa2<<<dim3(NS / 128, NB * NH), 256, ATTN_BYTES>>>(qh, ql, kh, kl, vth, vtl, chi, clo);

    split_f<<<NW4 / 256, 256>>>(Wo, whi, wlo, NW4);
    mma_gemm<2><<<ggrid, 256>>>(chi, clo, whi, wlo, bo, nullptr, nullptr, out, 512, (size_t)64);
}

// round 11
// speedup vs baseline: 2.1266x; 1.0606x over previous
#include <cuda_runtime.h>
#include <cuda_bf16.h>
#include <mma.h>

using namespace nvcuda;

typedef unsigned long long u64;
typedef unsigned int u32;

#define NB 4
#define NS 2048
#define NF 512
#define NH 8
#define ND 64
#define NFILT 512
#define NM (NB*NS)

// ---------------- scratch (device globals; no allocation allowed) ----------
__device__ __nv_bfloat16 g_qh[(size_t)NB*NH*NS*ND];  // q hi [B,H,S,D] (pre-scaled 1/8)
__device__ __nv_bfloat16 g_ql[(size_t)NB*NH*NS*ND];
__device__ __nv_bfloat16 g_kh[(size_t)NB*NH*NS*ND];  // k hi [B,H,S,D]
__device__ __nv_bfloat16 g_kl[(size_t)NB*NH*NS*ND];
__device__ __nv_bfloat16 g_vth[(size_t)NB*NH*NS*ND]; // v hi TRANSPOSED [B,H,D,S]
__device__ __nv_bfloat16 g_vtl[(size_t)NB*NH*NS*ND];
__device__ __nv_bfloat16 g_chi[(size_t)NM*NFILT];    // concat hi [B,S,H*D]
__device__ __nv_bfloat16 g_clo[(size_t)NM*NFILT];
__device__ __nv_bfloat16 g_xh[3][(size_t)NM*NF];     // x_q/x_k/x_v hi
__device__ __nv_bfloat16 g_xl[3][(size_t)NM*NF];
__device__ __nv_bfloat16 g_wh[4][(size_t)512*512];   // Wq/Wk/Wv/Wo hi
__device__ __nv_bfloat16 g_wl[4][(size_t)512*512];

__device__ __forceinline__ u32 pack_bf2(float a, float b) {
    __nv_bfloat16 ha = __float2bfloat16(a), hb = __float2bfloat16(b);
    return (u32)__bfloat16_as_ushort(ha) | ((u32)__bfloat16_as_ushort(hb) << 16);
}

// mma.m16n8k16 row.col f32 += bf16*bf16
__device__ __forceinline__ void mma16816(float* c, const u32* a, u32 b0, u32 b1) {
    asm volatile(
        "mma.sync.aligned.m16n8k16.row.col.f32.bf16.bf16.f32 "
        "{%0,%1,%2,%3}, {%4,%5,%6,%7}, {%8,%9}, {%0,%1,%2,%3};"
        : "+f"(c[0]), "+f"(c[1]), "+f"(c[2]), "+f"(c[3])
        : "r"(a[0]), "r"(a[1]), "r"(a[2]), "r"(a[3]), "r"(b0), "r"(b1));
}

// cp.async 16B
__device__ __forceinline__ void cp16(void* sm, const void* gm) {
    u32 sa = (u32)__cvta_generic_to_shared(sm);
    asm volatile("cp.async.cg.shared.global [%0], [%1], 16;" :: "r"(sa), "l"(gm));
}
#define CP_COMMIT() asm volatile("cp.async.commit_group;" ::: "memory")
#define CP_WAIT0()  asm volatile("cp.async.wait_group 0;" ::: "memory")

// ---------------------------------------------------------------------------
// split_all: one launch splits all 7 fp32 inputs into hi/lo bf16.
// segments 0..2: x (4096 blocks each, 1Mi float4), 3..6: W (256 blocks each).
// grid = 3*4096 + 4*256 = 13312.
// ---------------------------------------------------------------------------
struct SplitArgs {
    const float* src[7];
    __nv_bfloat16* hi[7];
    __nv_bfloat16* lo[7];
};

__global__ __launch_bounds__(256) void split_all(SplitArgs a)
{
    int b = blockIdx.x, seg, i;
    if (b < 12288) { seg = b >> 12; i = (b & 4095) * 256 + threadIdx.x; }
    else           { seg = 3 + ((b - 12288) >> 8); i = ((b - 12288) & 255) * 256 + threadIdx.x; }
    float4 x = ((const float4*)a.src[seg])[i];
    float xv[4] = {x.x, x.y, x.z, x.w};
    unsigned short hw[4], lw[4];
    #pragma unroll
    for (int j = 0; j < 4; j++) {
        __nv_bfloat16 h = __float2bfloat16(xv[j]);
        __nv_bfloat16 l = __float2bfloat16(xv[j] - __bfloat162float(h));
        hw[j] = __bfloat16_as_ushort(h);
        lw[j] = __bfloat16_as_ushort(l);
    }
    ((uint2*)a.hi[seg])[i] = make_uint2((u32)hw[0] | ((u32)hw[1] << 16),
                                        (u32)hw[2] | ((u32)hw[3] << 16));
    ((uint2*)a.lo[seg])[i] = make_uint2((u32)lw[0] | ((u32)lw[1] << 16),
                                        (u32)lw[2] | ((u32)lw[3] << 16));
}

// ---------------------------------------------------------------------------
// GEMM core constants: 128x64 CTA tile, K-chunk 32, double-buffered cp.async.
// dyn smem stage (bf16 elems): Ah[128][40], Al, Bh[32][72], Bl
// ---------------------------------------------------------------------------
#define ALD2 40
#define BLD 72
#define CLD 72
#define CLDT 132
#define S_AH 0
#define S_AL 5120
#define S_BH 10240
#define S_BL 12544
#define S_STG 14848                  // stage stride (elems)
#define GEMM_BYTES (2*S_STG*2 + 256) // 59648

// prefetch one K=32 stage
__device__ __forceinline__ void gemm_prefetch(
    __nv_bfloat16* stg, int tid,
    const __nv_bfloat16* Agh, const __nv_bfloat16* Agl,
    const __nv_bfloat16* Wbh, const __nv_bfloat16* Wbl,
    int k0, int ldw)
{
    int r = tid >> 1, off = (tid & 1) * 16;
    cp16(stg + S_AH + r * ALD2 + off,     Agh + (size_t)r * NF + k0 + off);
    cp16(stg + S_AH + r * ALD2 + off + 8, Agh + (size_t)r * NF + k0 + off + 8);
    cp16(stg + S_AL + r * ALD2 + off,     Agl + (size_t)r * NF + k0 + off);
    cp16(stg + S_AL + r * ALD2 + off + 8, Agl + (size_t)r * NF + k0 + off + 8);
    int rB = tid >> 3, u = (tid & 7) * 8;
    cp16(stg + S_BH + rB * BLD + u, Wbh + (size_t)(k0 + rB) * ldw + u);
    cp16(stg + S_BL + rB * BLD + u, Wbl + (size_t)(k0 + rB) * ldw + u);
    CP_COMMIT();
}

// mainloop: fills acc[2][2]; leaves smem free after final __syncthreads
__device__ __forceinline__ void gemm_mainloop(
    __nv_bfloat16* smb, int tid, int wr, int wc,
    const __nv_bfloat16* Agh, const __nv_bfloat16* Agl,
    const __nv_bfloat16* Wbh, const __nv_bfloat16* Wbl, int ldw,
    wmma::fragment<wmma::accumulator, 16, 16, 16, float> (&acc)[2][2])
{
    gemm_prefetch(smb, tid, Agh, Agl, Wbh, Wbl, 0, ldw);
    for (int k0 = 0; k0 < NF; k0 += 32) {
        const int st = (k0 >> 5) & 1;
        CP_WAIT0();
        __syncthreads();
        if (k0 + 32 < NF)
            gemm_prefetch(smb + (st ^ 1) * S_STG, tid, Agh, Agl, Wbh, Wbl, k0 + 32, ldw);
        const __nv_bfloat16* cb = smb + st * S_STG;
        #pragma unroll
        for (int kk = 0; kk < 2; kk++) {
            wmma::fragment<wmma::matrix_a, 16, 16, 16, __nv_bfloat16, wmma::row_major> a_hi[2], a_lo[2];
            wmma::fragment<wmma::matrix_b, 16, 16, 16, __nv_bfloat16, wmma::row_major> b_hi[2], b_lo[2];
            #pragma unroll
            for (int i = 0; i < 2; i++) {
                wmma::load_matrix_sync(a_hi[i], cb + S_AH + (wr * 32 + i * 16) * ALD2 + kk * 16, ALD2);
                wmma::load_matrix_sync(a_lo[i], cb + S_AL + (wr * 32 + i * 16) * ALD2 + kk * 16, ALD2);
                wmma::load_matrix_sync(b_hi[i], cb + S_BH + (kk * 16) * BLD + wc * 32 + i * 16, BLD);
                wmma::load_matrix_sync(b_lo[i], cb + S_BL + (kk * 16) * BLD + wc * 32 + i * 16, BLD);
            }
            #pragma unroll
            for (int i = 0; i < 2; i++)
                #pragma unroll
                for (int j = 0; j < 2; j++) {
                    wmma::mma_sync(acc[i][j], a_hi[i], b_hi[j], acc[i][j]);
                    wmma::mma_sync(acc[i][j], a_hi[i], b_lo[j], acc[i][j]);
                    wmma::mma_sync(acc[i][j], a_lo[i], b_hi[j], acc[i][j]);
                }
        }
    }
    __syncthreads();   // stages retire before Csm alias writes
}

// ---------------------------------------------------------------------------
// proj_gemm: merged q/k/v projections. grid (NM/128, 8, 3), block 256.
// z=0: q (scale 1/8, [b,h,s,64]); z=1: k ([b,h,s,64]); z=2: v transposed.
// ---------------------------------------------------------------------------
struct ProjArgs {
    const __nv_bfloat16 *xh[3], *xl[3], *wh[3], *wl[3];
    const float* bias[3];
    __nv_bfloat16 *oh[3], *ol[3];
};

__global__ __launch_bounds__(256, 2) void proj_gemm(ProjArgs pa)
{
    extern __shared__ __nv_bfloat16 smb[];
    float* Csm = (float*)smb;
    float* sB  = (float*)((char*)smb + 2 * S_STG * 2);

    const int tid = threadIdx.x;
    const int w = tid >> 5;
    const int wr = w & 3, wc = w >> 2;
    const int m0 = blockIdx.x * 128;
    const int ny = blockIdx.y;
    const int z  = blockIdx.z;
    const int ng0 = ny * 64;

    if (tid < 64) sB[tid] = pa.bias[z][ng0 + tid];

    const __nv_bfloat16* Agh = pa.xh[z] + (size_t)m0 * NF;
    const __nv_bfloat16* Agl = pa.xl[z] + (size_t)m0 * NF;
    const __nv_bfloat16* Wbh = pa.wh[z] + (size_t)ny * 512 * 64;
    const __nv_bfloat16* Wbl = pa.wl[z] + (size_t)ny * 512 * 64;

    wmma::fragment<wmma::accumulator, 16, 16, 16, float> acc[2][2];
    #pragma unroll
    for (int i = 0; i < 2; i++)
        #pragma unroll
        for (int j = 0; j < 2; j++) wmma::fill_fragment(acc[i][j], 0.0f);

    gemm_mainloop(smb, tid, wr, wc, Agh, Agl, Wbh, Wbl, 64, acc);

    const int bb = m0 >> 11, ss0 = m0 & (NS - 1);
    if (z == 2) {
        // transposed epilogue [b,h,64,s]
        #pragma unroll
        for (int i = 0; i < 2; i++)
            #pragma unroll
            for (int j = 0; j < 2; j++)
                wmma::store_matrix_sync(
                    Csm + (wr * 32 + i * 16) + (wc * 32 + j * 16) * CLDT,
                    acc[i][j], CLDT, wmma::mem_col_major);
        __syncthreads();
        const int d = tid >> 2, sseg = (tid & 3) * 32;
        float bi = sB[d];
        const float* cs = Csm + d * CLDT + sseg;
        __nv_bfloat16* oh = pa.oh[2] + ((size_t)(bb * NH + ny) * ND + d) * NS + ss0 + sseg;
        __nv_bfloat16* ol = pa.ol[2] + ((size_t)(bb * NH + ny) * ND + d) * NS + ss0 + sseg;
        #pragma unroll
        for (int g = 0; g < 4; g++) {
            u32 hw[4], lw[4];
            #pragma unroll
            for (int q2 = 0; q2 < 4; q2++) {
                float a = cs[g * 8 + q2 * 2] + bi;
                float b = cs[g * 8 + q2 * 2 + 1] + bi;
                __nv_bfloat16 ha = __float2bfloat16(a), hb2 = __float2bfloat16(b);
                hw[q2] = (u32)__bfloat16_as_ushort(ha) | ((u32)__bfloat16_as_ushort(hb2) << 16);
                lw[q2] = pack_bf2(a - __bfloat162float(ha), b - __bfloat162float(hb2));
            }
            *(uint4*)(oh + g * 8) = make_uint4(hw[0], hw[1], hw[2], hw[3]);
            *(uint4*)(ol + g * 8) = make_uint4(lw[0], lw[1], lw[2], lw[3]);
        }
    } else {
        #pragma unroll
        for (int i = 0; i < 2; i++)
            #pragma unroll
            for (int j = 0; j < 2; j++)
                wmma::store_matrix_sync(
                    Csm + (wr * 32 + i * 16) * CLD + (wc * 32 + j * 16),
                    acc[i][j], CLD, wmma::mem_row_major);
        __syncthreads();
        const float sc = (z == 0) ? 0.125f : 1.0f;
        __nv_bfloat16* oh = pa.oh[z] + ((size_t)(bb * NH + ny) * NS + ss0) * ND;
        __nv_bfloat16* ol = pa.ol[z] + ((size_t)(bb * NH + ny) * NS + ss0) * ND;
        #pragma unroll
        for (int r = 0; r < 8; r++) {
            int u = r * 256 + tid;
            int row = u >> 4, c4 = (u & 15) << 2;
            const float* cs = Csm + row * CLD + c4;
            const float* bi = sB + c4;
            float vv[4];
            #pragma unroll
            for (int i = 0; i < 4; i++) vv[i] = (cs[i] + bi[i]) * sc;
            unsigned short hw[4], lw[4];
            #pragma unroll
            for (int i = 0; i < 4; i++) {
                __nv_bfloat16 h = __float2bfloat16(vv[i]);
                __nv_bfloat16 l = __float2bfloat16(vv[i] - __bfloat162float(h));
                hw[i] = __bfloat16_as_ushort(h);
                lw[i] = __bfloat16_as_ushort(l);
            }
            *(uint2*)(oh + (size_t)row * ND + c4) =
                make_uint2((u32)hw[0] | ((u32)hw[1] << 16), (u32)hw[2] | ((u32)hw[3] << 16));
            *(uint2*)(ol + (size_t)row * ND + c4) =
                make_uint2((u32)lw[0] | ((u32)lw[1] << 16), (u32)lw[2] | ((u32)lw[3] << 16));
        }
    }
}

// ---------------------------------------------------------------------------
// out_gemm: final C = concat @ Wo + bo (fp32 out). grid (NM/128, 8).
// ---------------------------------------------------------------------------
__global__ __launch_bounds__(256, 2) void out_gemm(
    const __nv_bfloat16* __restrict__ Ahi, const __nv_bfloat16* __restrict__ Alo,
    const __nv_bfloat16* __restrict__ Whi, const __nv_bfloat16* __restrict__ Wlo,
    const float* __restrict__ bias, float* __restrict__ out32)
{
    extern __shared__ __nv_bfloat16 smb[];
    float* Csm = (float*)smb;
    float* sB  = (float*)((char*)smb + 2 * S_STG * 2);

    const int tid = threadIdx.x;
    const int w = tid >> 5;
    const int wr = w & 3, wc = w >> 2;
    const int m0 = blockIdx.x * 128;
    const int ny = blockIdx.y;
    const int ng0 = ny * 64;

    if (tid < 64) sB[tid] = bias[ng0 + tid];

    const __nv_bfloat16* Agh = Ahi + (size_t)m0 * NFILT;
    const __nv_bfloat16* Agl = Alo + (size_t)m0 * NFILT;
    const __nv_bfloat16* Wbh = Whi + ng0;
    const __nv_bfloat16* Wbl = Wlo + ng0;

    wmma::fragment<wmma::accumulator, 16, 16, 16, float> acc[2][2];
    #pragma unroll
    for (int i = 0; i < 2; i++)
        #pragma unroll
        for (int j = 0; j < 2; j++) wmma::fill_fragment(acc[i][j], 0.0f);

    gemm_mainloop(smb, tid, wr, wc, Agh, Agl, Wbh, Wbl, 512, acc);

    #pragma unroll
    for (int i = 0; i < 2; i++)
        #pragma unroll
        for (int j = 0; j < 2; j++)
            wmma::store_matrix_sync(
                Csm + (wr * 32 + i * 16) * CLD + (wc * 32 + j * 16),
                acc[i][j], CLD, wmma::mem_row_major);
    __syncthreads();

    float* ob = out32 + (size_t)m0 * NFILT + ng0;
    #pragma unroll
    for (int r = 0; r < 8; r++) {
        int u = r * 256 + tid;
        int row = u >> 4, c4 = (u & 15) << 2;
        const float* cs = Csm + row * CLD + c4;
        const float* bi = sB + c4;
        *(float4*)(ob + (size_t)row * NFILT + c4) =
            make_float4(cs[0] + bi[0], cs[1] + bi[1], cs[2] + bi[2], cs[3] + bi[3]);
    }
}

// ---------------------------------------------------------------------------
// attn_fa2: FlashAttention-2, raw mma.m16n8k16, register P & O, cp.async
// double-buffered K/V stages, ONE sync per tile.
// ---------------------------------------------------------------------------
#define TSTG 18432   // bf16 elems per stage
#define ATTN_BYTES (2 * TSTG * 2)

__global__ __launch_bounds__(256, 2) void attn_fa2(
    const __nv_bfloat16* __restrict__ qh, const __nv_bfloat16* __restrict__ ql,
    const __nv_bfloat16* __restrict__ kh, const __nv_bfloat16* __restrict__ kl,
    const __nv_bfloat16* __restrict__ vth, const __nv_bfloat16* __restrict__ vtl,
    __nv_bfloat16* __restrict__ chi, __nv_bfloat16* __restrict__ clo)
{
    extern __shared__ __nv_bfloat16 smb[];

    const int tid = threadIdx.x;
    const int w = tid >> 5, lane = tid & 31;
    const int g = lane >> 2, t = lane & 3;
    const int bh = blockIdx.y, bb = bh >> 3, hh = bh & 7;
    const int s0 = blockIdx.x * 128;
    const int qr0 = s0 + w * 16;

    const __nv_bfloat16* khb = kh + (size_t)bh * NS * ND;
    const __nv_bfloat16* klb = kl + (size_t)bh * NS * ND;
    const __nv_bfloat16* vhb = vth + (size_t)bh * ND * NS;  // [d][s]
    const __nv_bfloat16* vlb = vtl + (size_t)bh * ND * NS;

    const int r1 = tid >> 3, c1 = (tid & 7) * 8;
    const int r2 = r1 + 32;

    {
        __nv_bfloat16* sKh = smb; __nv_bfloat16* sKl = smb + 4608;
        __nv_bfloat16* sVh = smb + 9216; __nv_bfloat16* sVl = smb + 13824;
        cp16(sKh + r1 * 72 + c1, khb + (size_t)r1 * ND + c1);
        cp16(sKh + r2 * 72 + c1, khb + (size_t)r2 * ND + c1);
        cp16(sKl + r1 * 72 + c1, klb + (size_t)r1 * ND + c1);
        cp16(sKl + r2 * 72 + c1, klb + (size_t)r2 * ND + c1);
        cp16(sVh + r1 * 72 + c1, vhb + (size_t)r1 * NS + c1);
        cp16(sVh + r2 * 72 + c1, vhb + (size_t)r2 * NS + c1);
        cp16(sVl + r1 * 72 + c1, vlb + (size_t)r1 * NS + c1);
        cp16(sVl + r2 * 72 + c1, vlb + (size_t)r2 * NS + c1);
        CP_COMMIT();
    }

    u32 aqh[4][4], aql[4][4];
    {
        const __nv_bfloat16* q0h = qh + ((size_t)bh * NS + qr0 + g) * ND;
        const __nv_bfloat16* q8h = q0h + (size_t)8 * ND;
        const __nv_bfloat16* q0l = ql + ((size_t)bh * NS + qr0 + g) * ND;
        const __nv_bfloat16* q8l = q0l + (size_t)8 * ND;
        #pragma unroll
        for (int s = 0; s < 4; s++) {
            int c0 = 16 * s + 2 * t;
            aqh[s][0] = *(const u32*)(q0h + c0);
            aqh[s][1] = *(const u32*)(q8h + c0);
            aqh[s][2] = *(const u32*)(q0h + c0 + 8);
            aqh[s][3] = *(const u32*)(q8h + c0 + 8);
            aql[s][0] = *(const u32*)(q0l + c0);
            aql[s][1] = *(const u32*)(q8l + c0);
            aql[s][2] = *(const u32*)(q0l + c0 + 8);
            aql[s][3] = *(const u32*)(q8l + c0 + 8);
        }
    }

    float O[8][4];
    #pragma unroll
    for (int j = 0; j < 8; j++) { O[j][0] = O[j][1] = O[j][2] = O[j][3] = 0.0f; }
    float m0 = -1e30f, m1 = -1e30f, l0 = 0.0f, l1 = 0.0f;

    for (int kt = 0; kt < NS; kt += 64) {
        const int st = (kt >> 6) & 1;
        CP_WAIT0();
        __syncthreads();     // single sync per tile: all prior reads + cp arrivals done
        if (kt + 64 < NS) {
            __nv_bfloat16* nb = smb + (st ^ 1) * TSTG;
            __nv_bfloat16* sKh = nb; __nv_bfloat16* sKl = nb + 4608;
            __nv_bfloat16* sVh = nb + 9216; __nv_bfloat16* sVl = nb + 13824;
            int kn = kt + 64;
            cp16(sKh + r1 * 72 + c1, khb + (size_t)(kn + r1) * ND + c1);
            cp16(sKh + r2 * 72 + c1, khb + (size_t)(kn + r2) * ND + c1);
            cp16(sKl + r1 * 72 + c1, klb + (size_t)(kn + r1) * ND + c1);
            cp16(sKl + r2 * 72 + c1, klb + (size_t)(kn + r2) * ND + c1);
            cp16(sVh + r1 * 72 + c1, vhb + (size_t)r1 * NS + kn + c1);
            cp16(sVh + r2 * 72 + c1, vhb + (size_t)r2 * NS + kn + c1);
            cp16(sVl + r1 * 72 + c1, vlb + (size_t)r1 * NS + kn + c1);
            cp16(sVl + r2 * 72 + c1, vlb + (size_t)r2 * NS + kn + c1);
            CP_COMMIT();
        }
        const __nv_bfloat16* cbs = smb + st * TSTG;
        const __nv_bfloat16* sKh = cbs; const __nv_bfloat16* sKl = cbs + 4608;
        const __nv_bfloat16* sVh = cbs + 9216; const __nv_bfloat16* sVl = cbs + 13824;

        float c[8][4];
        #pragma unroll
        for (int j = 0; j < 8; j++) { c[j][0] = c[j][1] = c[j][2] = c[j][3] = 0.0f; }
        #pragma unroll
        for (int j = 0; j < 8; j++) {
            const __nv_bfloat16* krh = sKh + (8 * j + g) * 72;
            const __nv_bfloat16* krl = sKl + (8 * j + g) * 72;
            #pragma unroll
            for (int s = 0; s < 4; s++) {
                int c0 = 16 * s + 2 * t;
                u32 bh0 = *(const u32*)(krh + c0);
                u32 bh1 = *(const u32*)(krh + c0 + 8);
                u32 bl0 = *(const u32*)(krl + c0);
                u32 bl1 = *(const u32*)(krl + c0 + 8);
                mma16816(c[j], aqh[s], bh0, bh1);
                mma16816(c[j], aqh[s], bl0, bl1);
                mma16816(c[j], aql[s], bh0, bh1);
            }
        }

        float mx0 = c[0][0], mx1 = c[0][2];
        #pragma unroll
        for (int j = 0; j < 8; j++) {
            mx0 = fmaxf(mx0, fmaxf(c[j][0], c[j][1]));
            mx1 = fmaxf(mx1, fmaxf(c[j][2], c[j][3]));
        }
        mx0 = fmaxf(mx0, __shfl_xor_sync(0xffffffffu, mx0, 1));
        mx0 = fmaxf(mx0, __shfl_xor_sync(0xffffffffu, mx0, 2));
        mx1 = fmaxf(mx1, __shfl_xor_sync(0xffffffffu, mx1, 1));
        mx1 = fmaxf(mx1, __shfl_xor_sync(0xffffffffu, mx1, 2));
        float mn0 = fmaxf(m0, mx0), mn1 = fmaxf(m1, mx1);
        float al0 = __expf(m0 - mn0), al1 = __expf(m1 - mn1);
        m0 = mn0; m1 = mn1;
        float s0r = 0.0f, s1r = 0.0f;
        #pragma unroll
        for (int j = 0; j < 8; j++) {
            c[j][0] = __expf(c[j][0] - mn0); s0r += c[j][0];
            c[j][1] = __expf(c[j][1] - mn0); s0r += c[j][1];
            c[j][2] = __expf(c[j][2] - mn1); s1r += c[j][2];
            c[j][3] = __expf(c[j][3] - mn1); s1r += c[j][3];
        }
        s0r += __shfl_xor_sync(0xffffffffu, s0r, 1);
        s0r += __shfl_xor_sync(0xffffffffu, s0r, 2);
        s1r += __shfl_xor_sync(0xffffffffu, s1r, 1);
        s1r += __shfl_xor_sync(0xffffffffu, s1r, 2);
        l0 = l0 * al0 + s0r;
        l1 = l1 * al1 + s1r;
        #pragma unroll
        for (int j = 0; j < 8; j++) {
            O[j][0] *= al0; O[j][1] *= al0; O[j][2] *= al1; O[j][3] *= al1;
        }

        u32 ph[4][4], pl[4][4];
        #pragma unroll
        for (int s = 0; s < 4; s++) {
            #pragma unroll
            for (int hcell = 0; hcell < 2; hcell++) {
                int j = 2 * s + hcell;
                float p0 = c[j][0], p1 = c[j][1], p2 = c[j][2], p3 = c[j][3];
                __nv_bfloat16 h0 = __float2bfloat16(p0), h1 = __float2bfloat16(p1);
                __nv_bfloat16 h2 = __float2bfloat16(p2), h3 = __float2bfloat16(p3);
                ph[s][2 * hcell]     = (u32)__bfloat16_as_ushort(h0) | ((u32)__bfloat16_as_ushort(h1) << 16);
                ph[s][2 * hcell + 1] = (u32)__bfloat16_as_ushort(h2) | ((u32)__bfloat16_as_ushort(h3) << 16);
                pl[s][2 * hcell]     = pack_bf2(p0 - __bfloat162float(h0), p1 - __bfloat162float(h1));
                pl[s][2 * hcell + 1] = pack_bf2(p2 - __bfloat162float(h2), p3 - __bfloat162float(h3));
            }
        }

        #pragma unroll
        for (int j = 0; j < 8; j++) {
            const __nv_bfloat16* vrh = sVh + (8 * j + g) * 72;
            const __nv_bfloat16* vrl = sVl + (8 * j + g) * 72;
            #pragma unroll
            for (int s = 0; s < 4; s++) {
                int c0 = 16 * s + 2 * t;
                u32 vh0 = *(const u32*)(vrh + c0);
                u32 vh1 = *(const u32*)(vrh + c0 + 8);
                u32 vl0 = *(const u32*)(vrl + c0);
                u32 vl1 = *(const u32*)(vrl + c0 + 8);
                mma16816(O[j], ph[s], vh0, vh1);
                mma16816(O[j], ph[s], vl0, vl1);
                mma16816(O[j], pl[s], vh0, vh1);
            }
        }
    }

    float inv0 = 1.0f / l0, inv1 = 1.0f / l1;
    size_t r0off = ((size_t)bb * NS + qr0 + g) * NFILT + hh * ND;
    size_t r8off = r0off + (size_t)8 * NFILT;
    #pragma unroll
    for (int j = 0; j < 8; j++) {
        int col = 8 * j + 2 * t;
        float v0 = O[j][0] * inv0, v1 = O[j][1] * inv0;
        float v2 = O[j][2] * inv1, v3 = O[j][3] * inv1;
        __nv_bfloat16 h0 = __float2bfloat16(v0), h1 = __float2bfloat16(v1);
        __nv_bfloat16 h2 = __float2bfloat16(v2), h3 = __float2bfloat16(v3);
        *(u32*)(chi + r0off + col) = (u32)__bfloat16_as_ushort(h0) | ((u32)__bfloat16_as_ushort(h1) << 16);
        *(u32*)(chi + r8off + col) = (u32)__bfloat16_as_ushort(h2) | ((u32)__bfloat16_as_ushort(h3) << 16);
        *(u32*)(clo + r0off + col) = pack_bf2(v0 - __bfloat162float(h0), v1 - __bfloat162float(h1));
        *(u32*)(clo + r8off + col) = pack_bf2(v2 - __bfloat162float(h2), v3 - __bfloat162float(h3));
    }
}

// ---------------------------------------------------------------------------
extern "C" void kernel_launch(void* const* d_in, const int* in_sizes, int n_in,
                              void* d_out, int out_size)
{
    (void)in_sizes; (void)n_in; (void)out_size;
    const float* x_q = (const float*)d_in[0];
    const float* x_k = (const float*)d_in[1];
    const float* x_v = (const float*)d_in[2];
    const float* Wq  = (const float*)d_in[3];
    const float* bq  = (const float*)d_in[4];
    const float* Wk  = (const float*)d_in[5];
    const float* bk  = (const float*)d_in[6];
    const float* Wv  = (const float*)d_in[7];
    const float* bv  = (const float*)d_in[8];
    const float* Wo  = (const float*)d_in[9];
    const float* bo  = (const float*)d_in[10];
    float* out = (float*)d_out;

    __nv_bfloat16 *qh, *ql, *kh, *kl, *vth, *vtl, *chi, *clo, *xh, *xl, *wh, *wl;
    cudaGetSymbolAddress((void**)&qh, g_qh);
    cudaGetSymbolAddress((void**)&ql, g_ql);
    cudaGetSymbolAddress((void**)&kh, g_kh);
    cudaGetSymbolAddress((void**)&kl, g_kl);
    cudaGetSymbolAddress((void**)&vth, g_vth);
    cudaGetSymbolAddress((void**)&vtl, g_vtl);
    cudaGetSymbolAddress((void**)&chi, g_chi);
    cudaGetSymbolAddress((void**)&clo, g_clo);
    cudaGetSymbolAddress((void**)&xh, g_xh);
    cudaGetSymbolAddress((void**)&xl, g_xl);
    cudaGetSymbolAddress((void**)&wh, g_wh);
    cudaGetSymbolAddress((void**)&wl, g_wl);

    const size_t XSZ = (size_t)NM * NF;
    const size_t WSZ = (size_t)512 * 512;

    static int once = 0;
    if (!once) {
        cudaFuncSetAttribute(attn_fa2,
                             cudaFuncAttributeMaxDynamicSharedMemorySize, ATTN_BYTES);
        cudaFuncSetAttribute(proj_gemm,
                             cudaFuncAttributeMaxDynamicSharedMemorySize, GEMM_BYTES);
        cudaFuncSetAttribute(out_gemm,
                             cudaFuncAttributeMaxDynamicSharedMemorySize, GEMM_BYTES);
        once = 1;
    }

    // ---- one split launch for all 7 inputs (3*4096 + 4*256 = 13312 blocks) ----
    SplitArgs sa;
    sa.src[0] = x_q; sa.src[1] = x_k; sa.src[2] = x_v;
    sa.src[3] = Wq;  sa.src[4] = Wk;  sa.src[5] = Wv; sa.src[6] = Wo;
    for (int i = 0; i < 3; i++) { sa.hi[i] = xh + i * XSZ; sa.lo[i] = xl + i * XSZ; }
    for (int i = 0; i < 4; i++) { sa.hi[3 + i] = wh + i * WSZ; sa.lo[3 + i] = wl + i * WSZ; }
    split_all<<<13312, 256>>>(sa);

    // ---- merged projections ----
    ProjArgs pa;
    for (int i = 0; i < 3; i++) {
        pa.xh[i] = xh + i * XSZ; pa.xl[i] = xl + i * XSZ;
        pa.wh[i] = wh + i * WSZ; pa.wl[i] = wl + i * WSZ;
    }
    pa.bias[0] = bq; pa.bias[1] = bk; pa.bias[2] = bv;
    pa.oh[0] = qh;  pa.ol[0] = ql;
    pa.oh[1] = kh;  pa.ol[1] = kl;
    pa.oh[2] = vth; pa.ol[2] = vtl;
    proj_gemm<<<dim3(NM / 128, 8, 3), 256, GEMM_BYTES>>>(pa);

    attn_fa2<<<dim3(NS / 128, NB * NH), 256, ATTN_BYTES>>>(qh, ql, kh, kl, vth, vtl, chi, clo);

    out_gemm<<<dim3(NM / 128, 8), 256, GEMM_BYTES>>>(chi, clo, wh + 3 * WSZ, wl + 3 * WSZ, bo, out);
}

// round 12
// speedup vs baseline: 2.1476x; 1.0098x over previous
#include <cuda_runtime.h>
#include <cuda_bf16.h>
#include <mma.h>

using namespace nvcuda;

typedef unsigned long long u64;
typedef unsigned int u32;

#define NB 4
#define NS 2048
#define NF 512
#define NH 8
#define ND 64
#define NFILT 512
#define NM (NB*NS)

// ---------------- scratch (device globals; no allocation allowed) ----------
__device__ __nv_bfloat16 g_qh[(size_t)NB*NH*NS*ND];  // q hi [B,H,S,D] (pre-scaled 1/8)
__device__ __nv_bfloat16 g_ql[(size_t)NB*NH*NS*ND];
__device__ __nv_bfloat16 g_kh[(size_t)NB*NH*NS*ND];  // k hi [B,H,S,D]
__device__ __nv_bfloat16 g_kl[(size_t)NB*NH*NS*ND];
__device__ __nv_bfloat16 g_vth[(size_t)NB*NH*NS*ND]; // v hi TRANSPOSED [B,H,D,S]
__device__ __nv_bfloat16 g_vtl[(size_t)NB*NH*NS*ND];
__device__ __nv_bfloat16 g_chi[(size_t)NM*NFILT];    // concat hi [B,S,H*D]
__device__ __nv_bfloat16 g_clo[(size_t)NM*NFILT];
__device__ __nv_bfloat16 g_xh[3][(size_t)NM*NF];     // x_q/x_k/x_v hi
__device__ __nv_bfloat16 g_xl[3][(size_t)NM*NF];
__device__ __nv_bfloat16 g_wh[4][(size_t)512*512];   // Wq/Wk/Wv/Wo hi
__device__ __nv_bfloat16 g_wl[4][(size_t)512*512];

__device__ __forceinline__ u32 pack_bf2(float a, float b) {
    __nv_bfloat16 ha = __float2bfloat16(a), hb = __float2bfloat16(b);
    return (u32)__bfloat16_as_ushort(ha) | ((u32)__bfloat16_as_ushort(hb) << 16);
}

// mma.m16n8k16 row.col f32 += bf16*bf16
__device__ __forceinline__ void mma16816(float* c, const u32* a, u32 b0, u32 b1) {
    asm volatile(
        "mma.sync.aligned.m16n8k16.row.col.f32.bf16.bf16.f32 "
        "{%0,%1,%2,%3}, {%4,%5,%6,%7}, {%8,%9}, {%0,%1,%2,%3};"
        : "+f"(c[0]), "+f"(c[1]), "+f"(c[2]), "+f"(c[3])
        : "r"(a[0]), "r"(a[1]), "r"(a[2]), "r"(a[3]), "r"(b0), "r"(b1));
}

// cp.async 16B
__device__ __forceinline__ void cp16(void* sm, const void* gm) {
    u32 sa = (u32)__cvta_generic_to_shared(sm);
    asm volatile("cp.async.cg.shared.global [%0], [%1], 16;" :: "r"(sa), "l"(gm));
}
#define CP_COMMIT() asm volatile("cp.async.commit_group;" ::: "memory")
#define CP_WAIT0()  asm volatile("cp.async.wait_group 0;" ::: "memory")
#define CP_WAIT1()  asm volatile("cp.async.wait_group 1;" ::: "memory")

// ---------------------------------------------------------------------------
// split_all: one launch splits all 7 fp32 inputs into hi/lo bf16.
// segments 0..2: x (4096 blocks each), 3..6: W (256 blocks each). grid 13312.
// ---------------------------------------------------------------------------
struct SplitArgs {
    const float* src[7];
    __nv_bfloat16* hi[7];
    __nv_bfloat16* lo[7];
};

__global__ __launch_bounds__(256) void split_all(SplitArgs a)
{
    int b = blockIdx.x, seg, i;
    if (b < 12288) { seg = b >> 12; i = (b & 4095) * 256 + threadIdx.x; }
    else           { seg = 3 + ((b - 12288) >> 8); i = ((b - 12288) & 255) * 256 + threadIdx.x; }
    float4 x = ((const float4*)a.src[seg])[i];
    float xv[4] = {x.x, x.y, x.z, x.w};
    unsigned short hw[4], lw[4];
    #pragma unroll
    for (int j = 0; j < 4; j++) {
        __nv_bfloat16 h = __float2bfloat16(xv[j]);
        __nv_bfloat16 l = __float2bfloat16(xv[j] - __bfloat162float(h));
        hw[j] = __bfloat16_as_ushort(h);
        lw[j] = __bfloat16_as_ushort(l);
    }
    ((uint2*)a.hi[seg])[i] = make_uint2((u32)hw[0] | ((u32)hw[1] << 16),
                                        (u32)hw[2] | ((u32)hw[3] << 16));
    ((uint2*)a.lo[seg])[i] = make_uint2((u32)lw[0] | ((u32)lw[1] << 16),
                                        (u32)lw[2] | ((u32)lw[3] << 16));
}

// ---------------------------------------------------------------------------
// GEMM core: 128x64 CTA tile, K-chunk 32, THREE-stage cp.async, wait_group 1.
// dyn smem stage (bf16 elems): Ah[128][40], Al, Bh[32][72], Bl
// ---------------------------------------------------------------------------
#define ALD2 40
#define BLD 72
#define CLD 72
#define CLDT 132
#define S_AH 0
#define S_AL 5120
#define S_BH 10240
#define S_BL 12544
#define S_STG 14848                  // stage stride (elems)
#define GEMM_BYTES (3*S_STG*2 + 256) // 89344

// prefetch one K=32 stage (one commit)
__device__ __forceinline__ void gemm_prefetch(
    __nv_bfloat16* stg, int tid,
    const __nv_bfloat16* Agh, const __nv_bfloat16* Agl,
    const __nv_bfloat16* Wbh, const __nv_bfloat16* Wbl,
    int k0, int ldw)
{
    int r = tid >> 1, off = (tid & 1) * 16;
    cp16(stg + S_AH + r * ALD2 + off,     Agh + (size_t)r * NF + k0 + off);
    cp16(stg + S_AH + r * ALD2 + off + 8, Agh + (size_t)r * NF + k0 + off + 8);
    cp16(stg + S_AL + r * ALD2 + off,     Agl + (size_t)r * NF + k0 + off);
    cp16(stg + S_AL + r * ALD2 + off + 8, Agl + (size_t)r * NF + k0 + off + 8);
    int rB = tid >> 3, u = (tid & 7) * 8;
    cp16(stg + S_BH + rB * BLD + u, Wbh + (size_t)(k0 + rB) * ldw + u);
    cp16(stg + S_BL + rB * BLD + u, Wbl + (size_t)(k0 + rB) * ldw + u);
    CP_COMMIT();
}

// mainloop: 3 stages; one sync + wait_group(1) per stage; empty-group commits
// in the tail keep the accounting aligned. Leaves smem free after final sync.
__device__ __forceinline__ void gemm_mainloop(
    __nv_bfloat16* smb, int tid, int wr, int wc,
    const __nv_bfloat16* Agh, const __nv_bfloat16* Agl,
    const __nv_bfloat16* Wbh, const __nv_bfloat16* Wbl, int ldw,
    wmma::fragment<wmma::accumulator, 16, 16, 16, float> (&acc)[2][2])
{
    gemm_prefetch(smb,         tid, Agh, Agl, Wbh, Wbl, 0,  ldw);   // G0 -> stage 0
    gemm_prefetch(smb + S_STG, tid, Agh, Agl, Wbh, Wbl, 32, ldw);   // G1 -> stage 1
    int st = 0;
    for (int k0 = 0; k0 < NF; k0 += 32) {
        CP_WAIT1();            // retire group for stage st (<=1 newer outstanding)
        __syncthreads();       // all reads of stage (st+1)%3 from prev iter done
        if (k0 + 64 < NF) {
            int stn = st + 2; if (stn >= 3) stn -= 3;
            gemm_prefetch(smb + stn * S_STG, tid, Agh, Agl, Wbh, Wbl, k0 + 64, ldw);
        } else {
            CP_COMMIT();       // empty group keeps wait_group(1) semantics aligned
        }
        const __nv_bfloat16* cb = smb + st * S_STG;
        #pragma unroll
        for (int kk = 0; kk < 2; kk++) {
            wmma::fragment<wmma::matrix_a, 16, 16, 16, __nv_bfloat16, wmma::row_major> a_hi[2], a_lo[2];
            wmma::fragment<wmma::matrix_b, 16, 16, 16, __nv_bfloat16, wmma::row_major> b_hi[2], b_lo[2];
            #pragma unroll
            for (int i = 0; i < 2; i++) {
                wmma::load_matrix_sync(a_hi[i], cb + S_AH + (wr * 32 + i * 16) * ALD2 + kk * 16, ALD2);
                wmma::load_matrix_sync(a_lo[i], cb + S_AL + (wr * 32 + i * 16) * ALD2 + kk * 16, ALD2);
                wmma::load_matrix_sync(b_hi[i], cb + S_BH + (kk * 16) * BLD + wc * 32 + i * 16, BLD);
                wmma::load_matrix_sync(b_lo[i], cb + S_BL + (kk * 16) * BLD + wc * 32 + i * 16, BLD);
            }
            #pragma unroll
            for (int i = 0; i < 2; i++)
                #pragma unroll
                for (int j = 0; j < 2; j++) {
                    wmma::mma_sync(acc[i][j], a_hi[i], b_hi[j], acc[i][j]);
                    wmma::mma_sync(acc[i][j], a_hi[i], b_lo[j], acc[i][j]);
                    wmma::mma_sync(acc[i][j], a_lo[i], b_hi[j], acc[i][j]);
                }
        }
        if (++st == 3) st = 0;
    }
    __syncthreads();   // stages retire before Csm alias writes
}

// ---------------------------------------------------------------------------
// proj_gemm: merged q/k/v projections. grid (NM/128, 8, 3), block 256.
// z=0: q (scale 1/8, [b,h,s,64]); z=1: k ([b,h,s,64]); z=2: v transposed.
// ---------------------------------------------------------------------------
struct ProjArgs {
    const __nv_bfloat16 *xh[3], *xl[3], *wh[3], *wl[3];
    const float* bias[3];
    __nv_bfloat16 *oh[3], *ol[3];
};

__global__ __launch_bounds__(256, 2) void proj_gemm(ProjArgs pa)
{
    extern __shared__ __nv_bfloat16 smb[];
    float* Csm = (float*)smb;
    float* sB  = (float*)((char*)smb + 3 * S_STG * 2);

    const int tid = threadIdx.x;
    const int w = tid >> 5;
    const int wr = w & 3, wc = w >> 2;
    const int m0 = blockIdx.x * 128;
    const int ny = blockIdx.y;
    const int z  = blockIdx.z;
    const int ng0 = ny * 64;

    if (tid < 64) sB[tid] = pa.bias[z][ng0 + tid];

    const __nv_bfloat16* Agh = pa.xh[z] + (size_t)m0 * NF;
    const __nv_bfloat16* Agl = pa.xl[z] + (size_t)m0 * NF;
    const __nv_bfloat16* Wbh = pa.wh[z] + (size_t)ny * 512 * 64;
    const __nv_bfloat16* Wbl = pa.wl[z] + (size_t)ny * 512 * 64;

    wmma::fragment<wmma::accumulator, 16, 16, 16, float> acc[2][2];
    #pragma unroll
    for (int i = 0; i < 2; i++)
        #pragma unroll
        for (int j = 0; j < 2; j++) wmma::fill_fragment(acc[i][j], 0.0f);

    gemm_mainloop(smb, tid, wr, wc, Agh, Agl, Wbh, Wbl, 64, acc);

    const int bb = m0 >> 11, ss0 = m0 & (NS - 1);
    if (z == 2) {
        // transposed epilogue [b,h,64,s]
        #pragma unroll
        for (int i = 0; i < 2; i++)
            #pragma unroll
            for (int j = 0; j < 2; j++)
                wmma::store_matrix_sync(
                    Csm + (wr * 32 + i * 16) + (wc * 32 + j * 16) * CLDT,
                    acc[i][j], CLDT, wmma::mem_col_major);
        __syncthreads();
        const int d = tid >> 2, sseg = (tid & 3) * 32;
        float bi = sB[d];
        const float* cs = Csm + d * CLDT + sseg;
        __nv_bfloat16* oh = pa.oh[2] + ((size_t)(bb * NH + ny) * ND + d) * NS + ss0 + sseg;
        __nv_bfloat16* ol = pa.ol[2] + ((size_t)(bb * NH + ny) * ND + d) * NS + ss0 + sseg;
        #pragma unroll
        for (int g = 0; g < 4; g++) {
            u32 hw[4], lw[4];
            #pragma unroll
            for (int q2 = 0; q2 < 4; q2++) {
                float a = cs[g * 8 + q2 * 2] + bi;
                float b = cs[g * 8 + q2 * 2 + 1] + bi;
                __nv_bfloat16 ha = __float2bfloat16(a), hb2 = __float2bfloat16(b);
                hw[q2] = (u32)__bfloat16_as_ushort(ha) | ((u32)__bfloat16_as_ushort(hb2) << 16);
                lw[q2] = pack_bf2(a - __bfloat162float(ha), b - __bfloat162float(hb2));
            }
            *(uint4*)(oh + g * 8) = make_uint4(hw[0], hw[1], hw[2], hw[3]);
            *(uint4*)(ol + g * 8) = make_uint4(lw[0], lw[1], lw[2], lw[3]);
        }
    } else {
        #pragma unroll
        for (int i = 0; i < 2; i++)
            #pragma unroll
            for (int j = 0; j < 2; j++)
                wmma::store_matrix_sync(
                    Csm + (wr * 32 + i * 16) * CLD + (wc * 32 + j * 16),
                    acc[i][j], CLD, wmma::mem_row_major);
        __syncthreads();
        const float sc = (z == 0) ? 0.125f : 1.0f;
        __nv_bfloat16* oh = pa.oh[z] + ((size_t)(bb * NH + ny) * NS + ss0) * ND;
        __nv_bfloat16* ol = pa.ol[z] + ((size_t)(bb * NH + ny) * NS + ss0) * ND;
        #pragma unroll
        for (int r = 0; r < 8; r++) {
            int u = r * 256 + tid;
            int row = u >> 4, c4 = (u & 15) << 2;
            const float* cs = Csm + row * CLD + c4;
            const float* bi = sB + c4;
            float vv[4];
            #pragma unroll
            for (int i = 0; i < 4; i++) vv[i] = (cs[i] + bi[i]) * sc;
            unsigned short hw[4], lw[4];
            #pragma unroll
            for (int i = 0; i < 4; i++) {
                __nv_bfloat16 h = __float2bfloat16(vv[i]);
                __nv_bfloat16 l = __float2bfloat16(vv[i] - __bfloat162float(h));
                hw[i] = __bfloat16_as_ushort(h);
                lw[i] = __bfloat16_as_ushort(l);
            }
            *(uint2*)(oh + (size_t)row * ND + c4) =
                make_uint2((u32)hw[0] | ((u32)hw[1] << 16), (u32)hw[2] | ((u32)hw[3] << 16));
            *(uint2*)(ol + (size_t)row * ND + c4) =
                make_uint2((u32)lw[0] | ((u32)lw[1] << 16), (u32)lw[2] | ((u32)lw[3] << 16));
        }
    }
}

// ---------------------------------------------------------------------------
// out_gemm: final C = concat @ Wo + bo (fp32 out). grid (NM/128, 8).
// ---------------------------------------------------------------------------
__global__ __launch_bounds__(256, 2) void out_gemm(
    const __nv_bfloat16* __restrict__ Ahi, const __nv_bfloat16* __restrict__ Alo,
    const __nv_bfloat16* __restrict__ Whi, const __nv_bfloat16* __restrict__ Wlo,
    const float* __restrict__ bias, float* __restrict__ out32)
{
    extern __shared__ __nv_bfloat16 smb[];
    float* Csm = (float*)smb;
    float* sB  = (float*)((char*)smb + 3 * S_STG * 2);

    const int tid = threadIdx.x;
    const int w = tid >> 5;
    const int wr = w & 3, wc = w >> 2;
    const int m0 = blockIdx.x * 128;
    const int ny = blockIdx.y;
    const int ng0 = ny * 64;

    if (tid < 64) sB[tid] = bias[ng0 + tid];

    const __nv_bfloat16* Agh = Ahi + (size_t)m0 * NFILT;
    const __nv_bfloat16* Agl = Alo + (size_t)m0 * NFILT;
    const __nv_bfloat16* Wbh = Whi + ng0;
    const __nv_bfloat16* Wbl = Wlo + ng0;

    wmma::fragment<wmma::accumulator, 16, 16, 16, float> acc[2][2];
    #pragma unroll
    for (int i = 0; i < 2; i++)
        #pragma unroll
        for (int j = 0; j < 2; j++) wmma::fill_fragment(acc[i][j], 0.0f);

    gemm_mainloop(smb, tid, wr, wc, Agh, Agl, Wbh, Wbl, 512, acc);

    #pragma unroll
    for (int i = 0; i < 2; i++)
        #pragma unroll
        for (int j = 0; j < 2; j++)
            wmma::store_matrix_sync(
                Csm + (wr * 32 + i * 16) * CLD + (wc * 32 + j * 16),
                acc[i][j], CLD, wmma::mem_row_major);
    __syncthreads();

    float* ob = out32 + (size_t)m0 * NFILT + ng0;
    #pragma unroll
    for (int r = 0; r < 8; r++) {
        int u = r * 256 + tid;
        int row = u >> 4, c4 = (u & 15) << 2;
        const float* cs = Csm + row * CLD + c4;
        const float* bi = sB + c4;
        *(float4*)(ob + (size_t)row * NFILT + c4) =
            make_float4(cs[0] + bi[0], cs[1] + bi[1], cs[2] + bi[2], cs[3] + bi[3]);
    }
}

// ---------------------------------------------------------------------------
// attn_fa2: FlashAttention-2, raw mma.m16n8k16, register P & O, cp.async
// double-buffered K/V stages, ONE sync per tile. (unchanged from R11)
// ---------------------------------------------------------------------------
#define TSTG 18432   // bf16 elems per stage
#define ATTN_BYTES (2 * TSTG * 2)

__global__ __launch_bounds__(256, 2) void attn_fa2(
    const __nv_bfloat16* __restrict__ qh, const __nv_bfloat16* __restrict__ ql,
    const __nv_bfloat16* __restrict__ kh, const __nv_bfloat16* __restrict__ kl,
    const __nv_bfloat16* __restrict__ vth, const __nv_bfloat16* __restrict__ vtl,
    __nv_bfloat16* __restrict__ chi, __nv_bfloat16* __restrict__ clo)
{
    extern __shared__ __nv_bfloat16 smb[];

    const int tid = threadIdx.x;
    const int w = tid >> 5, lane = tid & 31;
    const int g = lane >> 2, t = lane & 3;
    const int bh = blockIdx.y, bb = bh >> 3, hh = bh & 7;
    const int s0 = blockIdx.x * 128;
    const int qr0 = s0 + w * 16;

    const __nv_bfloat16* khb = kh + (size_t)bh * NS * ND;
    const __nv_bfloat16* klb = kl + (size_t)bh * NS * ND;
    const __nv_bfloat16* vhb = vth + (size_t)bh * ND * NS;  // [d][s]
    const __nv_bfloat16* vlb = vtl + (size_t)bh * ND * NS;

    const int r1 = tid >> 3, c1 = (tid & 7) * 8;
    const int r2 = r1 + 32;

    {
        __nv_bfloat16* sKh = smb; __nv_bfloat16* sKl = smb + 4608;
        __nv_bfloat16* sVh = smb + 9216; __nv_bfloat16* sVl = smb + 13824;
        cp16(sKh + r1 * 72 + c1, khb + (size_t)r1 * ND + c1);
        cp16(sKh + r2 * 72 + c1, khb + (size_t)r2 * ND + c1);
        cp16(sKl + r1 * 72 + c1, klb + (size_t)r1 * ND + c1);
        cp16(sKl + r2 * 72 + c1, klb + (size_t)r2 * ND + c1);
        cp16(sVh + r1 * 72 + c1, vhb + (size_t)r1 * NS + c1);
        cp16(sVh + r2 * 72 + c1, vhb + (size_t)r2 * NS + c1);
        cp16(sVl + r1 * 72 + c1, vlb + (size_t)r1 * NS + c1);
        cp16(sVl + r2 * 72 + c1, vlb + (size_t)r2 * NS + c1);
        CP_COMMIT();
    }

    u32 aqh[4][4], aql[4][4];
    {
        const __nv_bfloat16* q0h = qh + ((size_t)bh * NS + qr0 + g) * ND;
        const __nv_bfloat16* q8h = q0h + (size_t)8 * ND;
        const __nv_bfloat16* q0l = ql + ((size_t)bh * NS + qr0 + g) * ND;
        const __nv_bfloat16* q8l = q0l + (size_t)8 * ND;
        #pragma unroll
        for (int s = 0; s < 4; s++) {
            int c0 = 16 * s + 2 * t;
            aqh[s][0] = *(const u32*)(q0h + c0);
            aqh[s][1] = *(const u32*)(q8h + c0);
            aqh[s][2] = *(const u32*)(q0h + c0 + 8);
            aqh[s][3] = *(const u32*)(q8h + c0 + 8);
            aql[s][0] = *(const u32*)(q0l + c0);
            aql[s][1] = *(const u32*)(q8l + c0);
            aql[s][2] = *(const u32*)(q0l + c0 + 8);
            aql[s][3] = *(const u32*)(q8l + c0 + 8);
        }
    }

    float O[8][4];
    #pragma unroll
    for (int j = 0; j < 8; j++) { O[j][0] = O[j][1] = O[j][2] = O[j][3] = 0.0f; }
    float m0 = -1e30f, m1 = -1e30f, l0 = 0.0f, l1 = 0.0f;

    for (int kt = 0; kt < NS; kt += 64) {
        const int st = (kt >> 6) & 1;
        CP_WAIT0();
        __syncthreads();
        if (kt + 64 < NS) {
            __nv_bfloat16* nb = smb + (st ^ 1) * TSTG;
            __nv_bfloat16* sKh = nb; __nv_bfloat16* sKl = nb + 4608;
            __nv_bfloat16* sVh = nb + 9216; __nv_bfloat16* sVl = nb + 13824;
            int kn = kt + 64;
            cp16(sKh + r1 * 72 + c1, khb + (size_t)(kn + r1) * ND + c1);
            cp16(sKh + r2 * 72 + c1, khb + (size_t)(kn + r2) * ND + c1);
            cp16(sKl + r1 * 72 + c1, klb + (size_t)(kn + r1) * ND + c1);
            cp16(sKl + r2 * 72 + c1, klb + (size_t)(kn + r2) * ND + c1);
            cp16(sVh + r1 * 72 + c1, vhb + (size_t)r1 * NS + kn + c1);
            cp16(sVh + r2 * 72 + c1, vhb + (size_t)r2 * NS + kn + c1);
            cp16(sVl + r1 * 72 + c1, vlb + (size_t)r1 * NS + kn + c1);
            cp16(sVl + r2 * 72 + c1, vlb + (size_t)r2 * NS + kn + c1);
            CP_COMMIT();
        }
        const __nv_bfloat16* cbs = smb + st * TSTG;
        const __nv_bfloat16* sKh = cbs; const __nv_bfloat16* sKl = cbs + 4608;
        const __nv_bfloat16* sVh = cbs + 9216; const __nv_bfloat16* sVl = cbs + 13824;

        float c[8][4];
        #pragma unroll
        for (int j = 0; j < 8; j++) { c[j][0] = c[j][1] = c[j][2] = c[j][3] = 0.0f; }
        #pragma unroll
        for (int j = 0; j < 8; j++) {
            const __nv_bfloat16* krh = sKh + (8 * j + g) * 72;
            const __nv_bfloat16* krl = sKl + (8 * j + g) * 72;
            #pragma unroll
            for (int s = 0; s < 4; s++) {
                int c0 = 16 * s + 2 * t;
                u32 bh0 = *(const u32*)(krh + c0);
                u32 bh1 = *(const u32*)(krh + c0 + 8);
                u32 bl0 = *(const u32*)(krl + c0);
                u32 bl1 = *(const u32*)(krl + c0 + 8);
                mma16816(c[j], aqh[s], bh0, bh1);
                mma16816(c[j], aqh[s], bl0, bl1);
                mma16816(c[j], aql[s], bh0, bh1);
            }
        }

        float mx0 = c[0][0], mx1 = c[0][2];
        #pragma unroll
        for (int j = 0; j < 8; j++) {
            mx0 = fmaxf(mx0, fmaxf(c[j][0], c[j][1]));
            mx1 = fmaxf(mx1, fmaxf(c[j][2], c[j][3]));
        }
        mx0 = fmaxf(mx0, __shfl_xor_sync(0xffffffffu, mx0, 1));
        mx0 = fmaxf(mx0, __shfl_xor_sync(0xffffffffu, mx0, 2));
        mx1 = fmaxf(mx1, __shfl_xor_sync(0xffffffffu, mx1, 1));
        mx1 = fmaxf(mx1, __shfl_xor_sync(0xffffffffu, mx1, 2));
        float mn0 = fmaxf(m0, mx0), mn1 = fmaxf(m1, mx1);
        float al0 = __expf(m0 - mn0), al1 = __expf(m1 - mn1);
        m0 = mn0; m1 = mn1;
        float s0r = 0.0f, s1r = 0.0f;
        #pragma unroll
        for (int j = 0; j < 8; j++) {
            c[j][0] = __expf(c[j][0] - mn0); s0r += c[j][0];
            c[j][1] = __expf(c[j][1] - mn0); s0r += c[j][1];
            c[j][2] = __expf(c[j][2] - mn1); s1r += c[j][2];
            c[j][3] = __expf(c[j][3] - mn1); s1r += c[j][3];
        }
        s0r += __shfl_xor_sync(0xffffffffu, s0r, 1);
        s0r += __shfl_xor_sync(0xffffffffu, s0r, 2);
        s1r += __shfl_xor_sync(0xffffffffu, s1r, 1);
        s1r += __shfl_xor_sync(0xffffffffu, s1r, 2);
        l0 = l0 * al0 + s0r;
        l1 = l1 * al1 + s1r;
        #pragma unroll
        for (int j = 0; j < 8; j++) {
            O[j][0] *= al0; O[j][1] *= al0; O[j][2] *= al1; O[j][3] *= al1;
        }

        u32 ph[4][4], pl[4][4];
        #pragma unroll
        for (int s = 0; s < 4; s++) {
            #pragma unroll
            for (int hcell = 0; hcell < 2; hcell++) {
                int j = 2 * s + hcell;
                float p0 = c[j][0], p1 = c[j][1], p2 = c[j][2], p3 = c[j][3];
                __nv_bfloat16 h0 = __float2bfloat16(p0), h1 = __float2bfloat16(p1);
                __nv_bfloat16 h2 = __float2bfloat16(p2), h3 = __float2bfloat16(p3);
                ph[s][2 * hcell]     = (u32)__bfloat16_as_ushort(h0) | ((u32)__bfloat16_as_ushort(h1) << 16);
                ph[s][2 * hcell + 1] = (u32)__bfloat16_as_ushort(h2) | ((u32)__bfloat16_as_ushort(h3) << 16);
                pl[s][2 * hcell]     = pack_bf2(p0 - __bfloat162float(h0), p1 - __bfloat162float(h1));
                pl[s][2 * hcell + 1] = pack_bf2(p2 - __bfloat162float(h2), p3 - __bfloat162float(h3));
            }
        }

        #pragma unroll
        for (int j = 0; j < 8; j++) {
            const __nv_bfloat16* vrh = sVh + (8 * j + g) * 72;
            const __nv_bfloat16* vrl = sVl + (8 * j + g) * 72;
            #pragma unroll
            for (int s = 0; s < 4; s++) {
                int c0 = 16 * s + 2 * t;
                u32 vh0 = *(const u32*)(vrh + c0);
                u32 vh1 = *(const u32*)(vrh + c0 + 8);
                u32 vl0 = *(const u32*)(vrl + c0);
                u32 vl1 = *(const u32*)(vrl + c0 + 8);
                mma16816(O[j], ph[s], vh0, vh1);
                mma16816(O[j], ph[s], vl0, vl1);
                mma16816(O[j], pl[s], vh0, vh1);
            }
        }
    }

    float inv0 = 1.0f / l0, inv1 = 1.0f / l1;
    size_t r0off = ((size_t)bb * NS + qr0 + g) * NFILT + hh * ND;
    size_t r8off = r0off + (size_t)8 * NFILT;
    #pragma unroll
    for (int j = 0; j < 8; j++) {
        int col = 8 * j + 2 * t;
        float v0 = O[j][0] * inv0, v1 = O[j][1] * inv0;
        float v2 = O[j][2] * inv1, v3 = O[j][3] * inv1;
        __nv_bfloat16 h0 = __float2bfloat16(v0), h1 = __float2bfloat16(v1);
        __nv_bfloat16 h2 = __float2bfloat16(v2), h3 = __float2bfloat16(v3);
        *(u32*)(chi + r0off + col) = (u32)__bfloat16_as_ushort(h0) | ((u32)__bfloat16_as_ushort(h1) << 16);
        *(u32*)(chi + r8off + col) = (u32)__bfloat16_as_ushort(h2) | ((u32)__bfloat16_as_ushort(h3) << 16);
        *(u32*)(clo + r0off + col) = pack_bf2(v0 - __bfloat162float(h0), v1 - __bfloat162float(h1));
        *(u32*)(clo + r8off + col) = pack_bf2(v2 - __bfloat162float(h2), v3 - __bfloat162float(h3));
    }
}

// ---------------------------------------------------------------------------
extern "C" void kernel_launch(void* const* d_in, const int* in_sizes, int n_in,
                              void* d_out, int out_size)
{
    (void)in_sizes; (void)n_in; (void)out_size;
    const float* x_q = (const float*)d_in[0];
    const float* x_k = (const float*)d_in[1];
    const float* x_v = (const float*)d_in[2];
    const float* Wq  = (const float*)d_in[3];
    const float* bq  = (const float*)d_in[4];
    const float* Wk  = (const float*)d_in[5];
    const float* bk  = (const float*)d_in[6];
    const float* Wv  = (const float*)d_in[7];
    const float* bv  = (const float*)d_in[8];
    const float* Wo  = (const float*)d_in[9];
    const float* bo  = (const float*)d_in[10];
    float* out = (float*)d_out;

    __nv_bfloat16 *qh, *ql, *kh, *kl, *vth, *vtl, *chi, *clo, *xh, *xl, *wh, *wl;
    cudaGetSymbolAddress((void**)&qh, g_qh);
    cudaGetSymbolAddress((void**)&ql, g_ql);
    cudaGetSymbolAddress((void**)&kh, g_kh);
    cudaGetSymbolAddress((void**)&kl, g_kl);
    cudaGetSymbolAddress((void**)&vth, g_vth);
    cudaGetSymbolAddress((void**)&vtl, g_vtl);
    cudaGetSymbolAddress((void**)&chi, g_chi);
    cudaGetSymbolAddress((void**)&clo, g_clo);
    cudaGetSymbolAddress((void**)&xh, g_xh);
    cudaGetSymbolAddress((void**)&xl, g_xl);
    cudaGetSymbolAddress((void**)&wh, g_wh);
    cudaGetSymbolAddress((void**)&wl, g_wl);

    const size_t XSZ = (size_t)NM * NF;
    const size_t WSZ = (size_t)512 * 512;

    static int once = 0;
    if (!once) {
        cudaFuncSetAttribute(attn_fa2,
                             cudaFuncAttributeMaxDynamicSharedMemorySize, ATTN_BYTES);
        cudaFuncSetAttribute(proj_gemm,
                             cudaFuncAttributeMaxDynamicSharedMemorySize, GEMM_BYTES);
        cudaFuncSetAttribute(out_gemm,
                             cudaFuncAttributeMaxDynamicSharedMemorySize, GEMM_BYTES);
        once = 1;
    }

    // ---- one split launch for all 7 inputs (3*4096 + 4*256 = 13312 blocks) ----
    SplitArgs sa;
    sa.src[0] = x_q; sa.src[1] = x_k; sa.src[2] = x_v;
    sa.src[3] = Wq;  sa.src[4] = Wk;  sa.src[5] = Wv; sa.src[6] = Wo;
    for (int i = 0; i < 3; i++) { sa.hi[i] = xh + i * XSZ; sa.lo[i] = xl + i * XSZ; }
    for (int i = 0; i < 4; i++) { sa.hi[3 + i] = wh + i * WSZ; sa.lo[3 + i] = wl + i * WSZ; }
    split_all<<<13312, 256>>>(sa);

    // ---- merged projections ----
    ProjArgs pa;
    for (int i = 0; i < 3; i++) {
        pa.xh[i] = xh + i * XSZ; pa.xl[i] = xl + i * XSZ;
        pa.wh[i] = wh + i * WSZ; pa.wl[i] = wl + i * WSZ;
    }
    pa.bias[0] = bq; pa.bias[1] = bk; pa.bias[2] = bv;
    pa.oh[0] = qh;  pa.ol[0] = ql;
    pa.oh[1] = kh;  pa.ol[1] = kl;
    pa.oh[2] = vth; pa.ol[2] = vtl;
    proj_gemm<<<dim3(NM / 128, 8, 3), 256, GEMM_BYTES>>>(pa);

    attn_fa2<<<dim3(NS / 128, NB * NH), 256, ATTN_BYTES>>>(qh, ql, kh, kl, vth, vtl, chi, clo);

    out_gemm<<<dim3(NM / 128, 8), 256, GEMM_BYTES>>>(chi, clo, wh + 3 * WSZ, wl + 3 * WSZ, bo, out);
}

// round 13
// speedup vs baseline: 2.1952x; 1.0222x over previous
#include <cuda_runtime.h>
#include <cuda_bf16.h>
#include <mma.h>

using namespace nvcuda;

typedef unsigned long long u64;
typedef unsigned int u32;

#define NB 4
#define NS 2048
#define NF 512
#define NH 8
#define ND 64
#define NFILT 512
#define NM (NB*NS)

// ---------------- scratch (device globals; no allocation allowed) ----------
__device__ __nv_bfloat16 g_qh[(size_t)NB*NH*NS*ND];  // q hi [B,H,S,D] (pre-scaled 1/8)
__device__ __nv_bfloat16 g_ql[(size_t)NB*NH*NS*ND];
__device__ __nv_bfloat16 g_kh[(size_t)NB*NH*NS*ND];  // k hi [B,H,S,D]
__device__ __nv_bfloat16 g_kl[(size_t)NB*NH*NS*ND];
__device__ __nv_bfloat16 g_vth[(size_t)NB*NH*NS*ND]; // v hi TRANSPOSED [B,H,D,S]
__device__ __nv_bfloat16 g_vtl[(size_t)NB*NH*NS*ND];
__device__ __nv_bfloat16 g_chi[(size_t)NM*NFILT];    // concat hi [B,S,H*D]
__device__ __nv_bfloat16 g_clo[(size_t)NM*NFILT];
__device__ __nv_bfloat16 g_xh[3][(size_t)NM*NF];     // x_q/x_k/x_v hi
__device__ __nv_bfloat16 g_xl[3][(size_t)NM*NF];
__device__ __nv_bfloat16 g_wh[4][(size_t)512*512];   // Wq/Wk/Wv/Wo hi
__device__ __nv_bfloat16 g_wl[4][(size_t)512*512];

__device__ __forceinline__ u32 pack_bf2(float a, float b) {
    __nv_bfloat16 ha = __float2bfloat16(a), hb = __float2bfloat16(b);
    return (u32)__bfloat16_as_ushort(ha) | ((u32)__bfloat16_as_ushort(hb) << 16);
}

// mma.m16n8k16 row.col f32 += bf16*bf16
__device__ __forceinline__ void mma16816(float* c, const u32* a, u32 b0, u32 b1) {
    asm volatile(
        "mma.sync.aligned.m16n8k16.row.col.f32.bf16.bf16.f32 "
        "{%0,%1,%2,%3}, {%4,%5,%6,%7}, {%8,%9}, {%0,%1,%2,%3};"
        : "+f"(c[0]), "+f"(c[1]), "+f"(c[2]), "+f"(c[3])
        : "r"(a[0]), "r"(a[1]), "r"(a[2]), "r"(a[3]), "r"(b0), "r"(b1));
}

// ldmatrix x4 (four 8x8 b16 matrices)
__device__ __forceinline__ void ldsm4(u32& r0, u32& r1, u32& r2, u32& r3, u32 addr) {
    asm volatile("ldmatrix.sync.aligned.m8n8.x4.shared.b16 {%0,%1,%2,%3}, [%4];"
                 : "=r"(r0), "=r"(r1), "=r"(r2), "=r"(r3) : "r"(addr));
}

// cp.async 16B
__device__ __forceinline__ void cp16(void* sm, const void* gm) {
    u32 sa = (u32)__cvta_generic_to_shared(sm);
    asm volatile("cp.async.cg.shared.global [%0], [%1], 16;" :: "r"(sa), "l"(gm));
}
#define CP_COMMIT() asm volatile("cp.async.commit_group;" ::: "memory")
#define CP_WAIT0()  asm volatile("cp.async.wait_group 0;" ::: "memory")
#define CP_WAIT1()  asm volatile("cp.async.wait_group 1;" ::: "memory")

// ---------------------------------------------------------------------------
// split_all: one launch splits all 7 fp32 inputs into hi/lo bf16.
// segments 0..2: x (4096 blocks each), 3..6: W (256 blocks each). grid 13312.
// ---------------------------------------------------------------------------
struct SplitArgs {
    const float* src[7];
    __nv_bfloat16* hi[7];
    __nv_bfloat16* lo[7];
};

__global__ __launch_bounds__(256) void split_all(SplitArgs a)
{
    int b = blockIdx.x, seg, i;
    if (b < 12288) { seg = b >> 12; i = (b & 4095) * 256 + threadIdx.x; }
    else           { seg = 3 + ((b - 12288) >> 8); i = ((b - 12288) & 255) * 256 + threadIdx.x; }
    float4 x = ((const float4*)a.src[seg])[i];
    float xv[4] = {x.x, x.y, x.z, x.w};
    unsigned short hw[4], lw[4];
    #pragma unroll
    for (int j = 0; j < 4; j++) {
        __nv_bfloat16 h = __float2bfloat16(xv[j]);
        __nv_bfloat16 l = __float2bfloat16(xv[j] - __bfloat162float(h));
        hw[j] = __bfloat16_as_ushort(h);
        lw[j] = __bfloat16_as_ushort(l);
    }
    ((uint2*)a.hi[seg])[i] = make_uint2((u32)hw[0] | ((u32)hw[1] << 16),
                                        (u32)hw[2] | ((u32)hw[3] << 16));
    ((uint2*)a.lo[seg])[i] = make_uint2((u32)lw[0] | ((u32)lw[1] << 16),
                                        (u32)lw[2] | ((u32)lw[3] << 16));
}

// ---------------------------------------------------------------------------
// GEMM core: 128x64 CTA tile, K-chunk 32, 3-stage cp.async, wait_group 1.
// ---------------------------------------------------------------------------
#define ALD2 40
#define BLD 72
#define CLD 72
#define CLDT 132
#define S_AH 0
#define S_AL 5120
#define S_BH 10240
#define S_BL 12544
#define S_STG 14848                  // stage stride (elems)
#define GEMM_BYTES (3*S_STG*2 + 256) // 89344

__device__ __forceinline__ void gemm_prefetch(
    __nv_bfloat16* stg, int tid,
    const __nv_bfloat16* Agh, const __nv_bfloat16* Agl,
    const __nv_bfloat16* Wbh, const __nv_bfloat16* Wbl,
    int k0, int ldw)
{
    int r = tid >> 1, off = (tid & 1) * 16;
    cp16(stg + S_AH + r * ALD2 + off,     Agh + (size_t)r * NF + k0 + off);
    cp16(stg + S_AH + r * ALD2 + off + 8, Agh + (size_t)r * NF + k0 + off + 8);
    cp16(stg + S_AL + r * ALD2 + off,     Agl + (size_t)r * NF + k0 + off);
    cp16(stg + S_AL + r * ALD2 + off + 8, Agl + (size_t)r * NF + k0 + off + 8);
    int rB = tid >> 3, u = (tid & 7) * 8;
    cp16(stg + S_BH + rB * BLD + u, Wbh + (size_t)(k0 + rB) * ldw + u);
    cp16(stg + S_BL + rB * BLD + u, Wbl + (size_t)(k0 + rB) * ldw + u);
    CP_COMMIT();
}

__device__ __forceinline__ void gemm_mainloop(
    __nv_bfloat16* smb, int tid, int wr, int wc,
    const __nv_bfloat16* Agh, const __nv_bfloat16* Agl,
    const __nv_bfloat16* Wbh, const __nv_bfloat16* Wbl, int ldw,
    wmma::fragment<wmma::accumulator, 16, 16, 16, float> (&acc)[2][2])
{
    gemm_prefetch(smb,         tid, Agh, Agl, Wbh, Wbl, 0,  ldw);
    gemm_prefetch(smb + S_STG, tid, Agh, Agl, Wbh, Wbl, 32, ldw);
    int st = 0;
    for (int k0 = 0; k0 < NF; k0 += 32) {
        CP_WAIT1();
        __syncthreads();
        if (k0 + 64 < NF) {
            int stn = st + 2; if (stn >= 3) stn -= 3;
            gemm_prefetch(smb + stn * S_STG, tid, Agh, Agl, Wbh, Wbl, k0 + 64, ldw);
        } else {
            CP_COMMIT();
        }
        const __nv_bfloat16* cb = smb + st * S_STG;
        #pragma unroll
        for (int kk = 0; kk < 2; kk++) {
            wmma::fragment<wmma::matrix_a, 16, 16, 16, __nv_bfloat16, wmma::row_major> a_hi[2], a_lo[2];
            wmma::fragment<wmma::matrix_b, 16, 16, 16, __nv_bfloat16, wmma::row_major> b_hi[2], b_lo[2];
            #pragma unroll
            for (int i = 0; i < 2; i++) {
                wmma::load_matrix_sync(a_hi[i], cb + S_AH + (wr * 32 + i * 16) * ALD2 + kk * 16, ALD2);
                wmma::load_matrix_sync(a_lo[i], cb + S_AL + (wr * 32 + i * 16) * ALD2 + kk * 16, ALD2);
                wmma::load_matrix_sync(b_hi[i], cb + S_BH + (kk * 16) * BLD + wc * 32 + i * 16, BLD);
                wmma::load_matrix_sync(b_lo[i], cb + S_BL + (kk * 16) * BLD + wc * 32 + i * 16, BLD);
            }
            #pragma unroll
            for (int i = 0; i < 2; i++)
                #pragma unroll
                for (int j = 0; j < 2; j++) {
                    wmma::mma_sync(acc[i][j], a_hi[i], b_hi[j], acc[i][j]);
                    wmma::mma_sync(acc[i][j], a_hi[i], b_lo[j], acc[i][j]);
                    wmma::mma_sync(acc[i][j], a_lo[i], b_hi[j], acc[i][j]);
                }
        }
        if (++st == 3) st = 0;
    }
    __syncthreads();
}

// ---------------------------------------------------------------------------
// proj_gemm: merged q/k/v projections. grid (NM/128, 8, 3), block 256.
// ---------------------------------------------------------------------------
struct ProjArgs {
    const __nv_bfloat16 *xh[3], *xl[3], *wh[3], *wl[3];
    const float* bias[3];
    __nv_bfloat16 *oh[3], *ol[3];
};

__global__ __launch_bounds__(256, 2) void proj_gemm(ProjArgs pa)
{
    extern __shared__ __nv_bfloat16 smb[];
    float* Csm = (float*)smb;
    float* sB  = (float*)((char*)smb + 3 * S_STG * 2);

    const int tid = threadIdx.x;
    const int w = tid >> 5;
    const int wr = w & 3, wc = w >> 2;
    const int m0 = blockIdx.x * 128;
    const int ny = blockIdx.y;
    const int z  = blockIdx.z;
    const int ng0 = ny * 64;

    if (tid < 64) sB[tid] = pa.bias[z][ng0 + tid];

    const __nv_bfloat16* Agh = pa.xh[z] + (size_t)m0 * NF;
    const __nv_bfloat16* Agl = pa.xl[z] + (size_t)m0 * NF;
    const __nv_bfloat16* Wbh = pa.wh[z] + (size_t)ny * 512 * 64;
    const __nv_bfloat16* Wbl = pa.wl[z] + (size_t)ny * 512 * 64;

    wmma::fragment<wmma::accumulator, 16, 16, 16, float> acc[2][2];
    #pragma unroll
    for (int i = 0; i < 2; i++)
        #pragma unroll
        for (int j = 0; j < 2; j++) wmma::fill_fragment(acc[i][j], 0.0f);

    gemm_mainloop(smb, tid, wr, wc, Agh, Agl, Wbh, Wbl, 64, acc);

    const int bb = m0 >> 11, ss0 = m0 & (NS - 1);
    if (z == 2) {
        #pragma unroll
        for (int i = 0; i < 2; i++)
            #pragma unroll
            for (int j = 0; j < 2; j++)
                wmma::store_matrix_sync(
                    Csm + (wr * 32 + i * 16) + (wc * 32 + j * 16) * CLDT,
                    acc[i][j], CLDT, wmma::mem_col_major);
        __syncthreads();
        const int d = tid >> 2, sseg = (tid & 3) * 32;
        float bi = sB[d];
        const float* cs = Csm + d * CLDT + sseg;
        __nv_bfloat16* oh = pa.oh[2] + ((size_t)(bb * NH + ny) * ND + d) * NS + ss0 + sseg;
        __nv_bfloat16* ol = pa.ol[2] + ((size_t)(bb * NH + ny) * ND + d) * NS + ss0 + sseg;
        #pragma unroll
        for (int g = 0; g < 4; g++) {
            u32 hw[4], lw[4];
            #pragma unroll
            for (int q2 = 0; q2 < 4; q2++) {
                float a = cs[g * 8 + q2 * 2] + bi;
                float b = cs[g * 8 + q2 * 2 + 1] + bi;
                __nv_bfloat16 ha = __float2bfloat16(a), hb2 = __float2bfloat16(b);
                hw[q2] = (u32)__bfloat16_as_ushort(ha) | ((u32)__bfloat16_as_ushort(hb2) << 16);
                lw[q2] = pack_bf2(a - __bfloat162float(ha), b - __bfloat162float(hb2));
            }
            *(uint4*)(oh + g * 8) = make_uint4(hw[0], hw[1], hw[2], hw[3]);
            *(uint4*)(ol + g * 8) = make_uint4(lw[0], lw[1], lw[2], lw[3]);
        }
    } else {
        #pragma unroll
        for (int i = 0; i < 2; i++)
            #pragma unroll
            for (int j = 0; j < 2; j++)
                wmma::store_matrix_sync(
                    Csm + (wr * 32 + i * 16) * CLD + (wc * 32 + j * 16),
                    acc[i][j], CLD, wmma::mem_row_major);
        __syncthreads();
        const float sc = (z == 0) ? 0.125f : 1.0f;
        __nv_bfloat16* oh = pa.oh[z] + ((size_t)(bb * NH + ny) * NS + ss0) * ND;
        __nv_bfloat16* ol = pa.ol[z] + ((size_t)(bb * NH + ny) * NS + ss0) * ND;
        #pragma unroll
        for (int r = 0; r < 8; r++) {
            int u = r * 256 + tid;
            int row = u >> 4, c4 = (u & 15) << 2;
            const float* cs = Csm + row * CLD + c4;
            const float* bi = sB + c4;
            float vv[4];
            #pragma unroll
            for (int i = 0; i < 4; i++) vv[i] = (cs[i] + bi[i]) * sc;
            unsigned short hw[4], lw[4];
            #pragma unroll
            for (int i = 0; i < 4; i++) {
                __nv_bfloat16 h = __float2bfloat16(vv[i]);
                __nv_bfloat16 l = __float2bfloat16(vv[i] - __bfloat162float(h));
                hw[i] = __bfloat16_as_ushort(h);
                lw[i] = __bfloat16_as_ushort(l);
            }
            *(uint2*)(oh + (size_t)row * ND + c4) =
                make_uint2((u32)hw[0] | ((u32)hw[1] << 16), (u32)hw[2] | ((u32)hw[3] << 16));
            *(uint2*)(ol + (size_t)row * ND + c4) =
                make_uint2((u32)lw[0] | ((u32)lw[1] << 16), (u32)lw[2] | ((u32)lw[3] << 16));
        }
    }
}

// ---------------------------------------------------------------------------
// out_gemm: final C = concat @ Wo + bo (fp32 out). grid (NM/128, 8).
// ---------------------------------------------------------------------------
__global__ __launch_bounds__(256, 2) void out_gemm(
    const __nv_bfloat16* __restrict__ Ahi, const __nv_bfloat16* __restrict__ Alo,
    const __nv_bfloat16* __restrict__ Whi, const __nv_bfloat16* __restrict__ Wlo,
    const float* __restrict__ bias, float* __restrict__ out32)
{
    extern __shared__ __nv_bfloat16 smb[];
    float* Csm = (float*)smb;
    float* sB  = (float*)((char*)smb + 3 * S_STG * 2);

    const int tid = threadIdx.x;
    const int w = tid >> 5;
    const int wr = w & 3, wc = w >> 2;
    const int m0 = blockIdx.x * 128;
    const int ny = blockIdx.y;
    const int ng0 = ny * 64;

    if (tid < 64) sB[tid] = bias[ng0 + tid];

    const __nv_bfloat16* Agh = Ahi + (size_t)m0 * NFILT;
    const __nv_bfloat16* Agl = Alo + (size_t)m0 * NFILT;
    const __nv_bfloat16* Wbh = Whi + ng0;
    const __nv_bfloat16* Wbl = Wlo + ng0;

    wmma::fragment<wmma::accumulator, 16, 16, 16, float> acc[2][2];
    #pragma unroll
    for (int i = 0; i < 2; i++)
        #pragma unroll
        for (int j = 0; j < 2; j++) wmma::fill_fragment(acc[i][j], 0.0f);

    gemm_mainloop(smb, tid, wr, wc, Agh, Agl, Wbh, Wbl, 512, acc);

    #pragma unroll
    for (int i = 0; i < 2; i++)
        #pragma unroll
        for (int j = 0; j < 2; j++)
            wmma::store_matrix_sync(
                Csm + (wr * 32 + i * 16) * CLD + (wc * 32 + j * 16),
                acc[i][j], CLD, wmma::mem_row_major);
    __syncthreads();

    float* ob = out32 + (size_t)m0 * NFILT + ng0;
    #pragma unroll
    for (int r = 0; r < 8; r++) {
        int u = r * 256 + tid;
        int row = u >> 4, c4 = (u & 15) << 2;
        const float* cs = Csm + row * CLD + c4;
        const float* bi = sB + c4;
        *(float4*)(ob + (size_t)row * NFILT + c4) =
            make_float4(cs[0] + bi[0], cs[1] + bi[1], cs[2] + bi[2], cs[3] + bi[3]);
    }
}

// ---------------------------------------------------------------------------
// attn_fa2: FlashAttention-2, raw mma.m16n8k16, register P & O, cp.async
// double-buffered K/V stages, ldmatrix.x4 fragment loads.
// smem byte offsets within a stage: Kh 0, Kl 9216, Vh 18432, Vl 27648.
// ---------------------------------------------------------------------------
#define TSTG 18432   // bf16 elems per stage
#define ATTN_BYTES (2 * TSTG * 2)

__global__ __launch_bounds__(256, 2) void attn_fa2(
    const __nv_bfloat16* __restrict__ qh, const __nv_bfloat16* __restrict__ ql,
    const __nv_bfloat16* __restrict__ kh, const __nv_bfloat16* __restrict__ kl,
    const __nv_bfloat16* __restrict__ vth, const __nv_bfloat16* __restrict__ vtl,
    __nv_bfloat16* __restrict__ chi, __nv_bfloat16* __restrict__ clo)
{
    extern __shared__ __nv_bfloat16 smb[];
    const u32 smb_u = (u32)__cvta_generic_to_shared(smb);

    const int tid = threadIdx.x;
    const int w = tid >> 5, lane = tid & 31;
    const int g = lane >> 2, t = lane & 3;
    const int bh = blockIdx.y, bb = bh >> 3, hh = bh & 7;
    const int s0 = blockIdx.x * 128;
    const int qr0 = s0 + w * 16;

    // ldmatrix per-thread address component: row (lane&7) within matrix,
    // matrix index (lane>>3) selects 16B k-column group.
    const u32 ro = (u32)((lane & 7) * 144 + (lane >> 3) * 16);

    const __nv_bfloat16* khb = kh + (size_t)bh * NS * ND;
    const __nv_bfloat16* klb = kl + (size_t)bh * NS * ND;
    const __nv_bfloat16* vhb = vth + (size_t)bh * ND * NS;  // [d][s]
    const __nv_bfloat16* vlb = vtl + (size_t)bh * ND * NS;

    const int r1 = tid >> 3, c1 = (tid & 7) * 8;
    const int r2 = r1 + 32;

    {
        __nv_bfloat16* sKh = smb; __nv_bfloat16* sKl = smb + 4608;
        __nv_bfloat16* sVh = smb + 9216; __nv_bfloat16* sVl = smb + 13824;
        cp16(sKh + r1 * 72 + c1, khb + (size_t)r1 * ND + c1);
        cp16(sKh + r2 * 72 + c1, khb + (size_t)r2 * ND + c1);
        cp16(sKl + r1 * 72 + c1, klb + (size_t)r1 * ND + c1);
        cp16(sKl + r2 * 72 + c1, klb + (size_t)r2 * ND + c1);
        cp16(sVh + r1 * 72 + c1, vhb + (size_t)r1 * NS + c1);
        cp16(sVh + r2 * 72 + c1, vhb + (size_t)r2 * NS + c1);
        cp16(sVl + r1 * 72 + c1, vlb + (size_t)r1 * NS + c1);
        cp16(sVl + r2 * 72 + c1, vlb + (size_t)r2 * NS + c1);
        CP_COMMIT();
    }

    u32 aqh[4][4], aql[4][4];
    {
        const __nv_bfloat16* q0h = qh + ((size_t)bh * NS + qr0 + g) * ND;
        const __nv_bfloat16* q8h = q0h + (size_t)8 * ND;
        const __nv_bfloat16* q0l = ql + ((size_t)bh * NS + qr0 + g) * ND;
        const __nv_bfloat16* q8l = q0l + (size_t)8 * ND;
        #pragma unroll
        for (int s = 0; s < 4; s++) {
            int c0 = 16 * s + 2 * t;
            aqh[s][0] = *(const u32*)(q0h + c0);
            aqh[s][1] = *(const u32*)(q8h + c0);
            aqh[s][2] = *(const u32*)(q0h + c0 + 8);
            aqh[s][3] = *(const u32*)(q8h + c0 + 8);
            aql[s][0] = *(const u32*)(q0l + c0);
            aql[s][1] = *(const u32*)(q8l + c0);
            aql[s][2] = *(const u32*)(q0l + c0 + 8);
            aql[s][3] = *(const u32*)(q8l + c0 + 8);
        }
    }

    float O[8][4];
    #pragma unroll
    for (int j = 0; j < 8; j++) { O[j][0] = O[j][1] = O[j][2] = O[j][3] = 0.0f; }
    float m0 = -1e30f, m1 = -1e30f, l0 = 0.0f, l1 = 0.0f;

    for (int kt = 0; kt < NS; kt += 64) {
        const int st = (kt >> 6) & 1;
        CP_WAIT0();
        __syncthreads();
        if (kt + 64 < NS) {
            __nv_bfloat16* nb = smb + (st ^ 1) * TSTG;
            __nv_bfloat16* sKh = nb; __nv_bfloat16* sKl = nb + 4608;
            __nv_bfloat16* sVh = nb + 9216; __nv_bfloat16* sVl = nb + 13824;
            int kn = kt + 64;
            cp16(sKh + r1 * 72 + c1, khb + (size_t)(kn + r1) * ND + c1);
            cp16(sKh + r2 * 72 + c1, khb + (size_t)(kn + r2) * ND + c1);
            cp16(sKl + r1 * 72 + c1, klb + (size_t)(kn + r1) * ND + c1);
            cp16(sKl + r2 * 72 + c1, klb + (size_t)(kn + r2) * ND + c1);
            cp16(sVh + r1 * 72 + c1, vhb + (size_t)r1 * NS + kn + c1);
            cp16(sVh + r2 * 72 + c1, vhb + (size_t)r2 * NS + kn + c1);
            cp16(sVl + r1 * 72 + c1, vlb + (size_t)r1 * NS + kn + c1);
            cp16(sVl + r2 * 72 + c1, vlb + (size_t)r2 * NS + kn + c1);
            CP_COMMIT();
        }
        const u32 cb_u = smb_u + (u32)(st * TSTG * 2);
        const u32 kh_u = cb_u,          kl_u = cb_u + 9216;
        const u32 vh_u = cb_u + 18432,  vl_u = cb_u + 27648;

        // ---- S = Q @ K^T (bf16x3), K frags via ldmatrix.x4 ----
        float c[8][4];
        #pragma unroll
        for (int j = 0; j < 8; j++) { c[j][0] = c[j][1] = c[j][2] = c[j][3] = 0.0f; }
        #pragma unroll
        for (int j = 0; j < 8; j++) {
            const u32 jb = (u32)(j * 1152) + ro;   // 8 rows * 144B per j
            u32 bhr[8], blr[8];
            ldsm4(bhr[0], bhr[1], bhr[2], bhr[3], kh_u + jb);
            ldsm4(bhr[4], bhr[5], bhr[6], bhr[7], kh_u + jb + 64);
            ldsm4(blr[0], blr[1], blr[2], blr[3], kl_u + jb);
            ldsm4(blr[4], blr[5], blr[6], blr[7], kl_u + jb + 64);
            #pragma unroll
            for (int s = 0; s < 4; s++) {
                mma16816(c[j], aqh[s], bhr[2*s], bhr[2*s+1]);
                mma16816(c[j], aqh[s], blr[2*s], blr[2*s+1]);
                mma16816(c[j], aql[s], bhr[2*s], bhr[2*s+1]);
            }
        }

        // ---- softmax in registers ----
        float mx0 = c[0][0], mx1 = c[0][2];
        #pragma unroll
        for (int j = 0; j < 8; j++) {
            mx0 = fmaxf(mx0, fmaxf(c[j][0], c[j][1]));
            mx1 = fmaxf(mx1, fmaxf(c[j][2], c[j][3]));
        }
        mx0 = fmaxf(mx0, __shfl_xor_sync(0xffffffffu, mx0, 1));
        mx0 = fmaxf(mx0, __shfl_xor_sync(0xffffffffu, mx0, 2));
        mx1 = fmaxf(mx1, __shfl_xor_sync(0xffffffffu, mx1, 1));
        mx1 = fmaxf(mx1, __shfl_xor_sync(0xffffffffu, mx1, 2));
        float mn0 = fmaxf(m0, mx0), mn1 = fmaxf(m1, mx1);
        float al0 = __expf(m0 - mn0), al1 = __expf(m1 - mn1);
        m0 = mn0; m1 = mn1;
        float s0r = 0.0f, s1r = 0.0f;
        #pragma unroll
        for (int j = 0; j < 8; j++) {
            c[j][0] = __expf(c[j][0] - mn0); s0r += c[j][0];
            c[j][1] = __expf(c[j][1] - mn0); s0r += c[j][1];
            c[j][2] = __expf(c[j][2] - mn1); s1r += c[j][2];
            c[j][3] = __expf(c[j][3] - mn1); s1r += c[j][3];
        }
        s0r += __shfl_xor_sync(0xffffffffu, s0r, 1);
        s0r += __shfl_xor_sync(0xffffffffu, s0r, 2);
        s1r += __shfl_xor_sync(0xffffffffu, s1r, 1);
        s1r += __shfl_xor_sync(0xffffffffu, s1r, 2);
        l0 = l0 * al0 + s0r;
        l1 = l1 * al1 + s1r;
        #pragma unroll
        for (int j = 0; j < 8; j++) {
            O[j][0] *= al0; O[j][1] *= al0; O[j][2] *= al1; O[j][3] *= al1;
        }

        // ---- P fragments (A-layout == C-layout) ----
        u32 ph[4][4], pl[4][4];
        #pragma unroll
        for (int s = 0; s < 4; s++) {
            #pragma unroll
            for (int hcell = 0; hcell < 2; hcell++) {
                int j = 2 * s + hcell;
                float p0 = c[j][0], p1 = c[j][1], p2 = c[j][2], p3 = c[j][3];
                __nv_bfloat16 h0 = __float2bfloat16(p0), h1 = __float2bfloat16(p1);
                __nv_bfloat16 h2 = __float2bfloat16(p2), h3 = __float2bfloat16(p3);
                ph[s][2 * hcell]     = (u32)__bfloat16_as_ushort(h0) | ((u32)__bfloat16_as_ushort(h1) << 16);
                ph[s][2 * hcell + 1] = (u32)__bfloat16_as_ushort(h2) | ((u32)__bfloat16_as_ushort(h3) << 16);
                pl[s][2 * hcell]     = pack_bf2(p0 - __bfloat162float(h0), p1 - __bfloat162float(h1));
                pl[s][2 * hcell + 1] = pack_bf2(p2 - __bfloat162float(h2), p3 - __bfloat162float(h3));
            }
        }

        // ---- O += P @ V (bf16x3), V frags via ldmatrix.x4 ----
        #pragma unroll
        for (int j = 0; j < 8; j++) {
            const u32 jb = (u32)(j * 1152) + ro;
            u32 vhr[8], vlr[8];
            ldsm4(vhr[0], vhr[1], vhr[2], vhr[3], vh_u + jb);
            ldsm4(vhr[4], vhr[5], vhr[6], vhr[7], vh_u + jb + 64);
            ldsm4(vlr[0], vlr[1], vlr[2], vlr[3], vl_u + jb);
            ldsm4(vlr[4], vlr[5], vlr[6], vlr[7], vl_u + jb + 64);
            #pragma unroll
            for (int s = 0; s < 4; s++) {
                mma16816(O[j], ph[s], vhr[2*s], vhr[2*s+1]);
                mma16816(O[j], ph[s], vlr[2*s], vlr[2*s+1]);
                mma16816(O[j], pl[s], vhr[2*s], vhr[2*s+1]);
            }
        }
    }

    float inv0 = 1.0f / l0, inv1 = 1.0f / l1;
    size_t r0off = ((size_t)bb * NS + qr0 + g) * NFILT + hh * ND;
    size_t r8off = r0off + (size_t)8 * NFILT;
    #pragma unroll
    for (int j = 0; j < 8; j++) {
        int col = 8 * j + 2 * t;
        float v0 = O[j][0] * inv0, v1 = O[j][1] * inv0;
        float v2 = O[j][2] * inv1, v3 = O[j][3] * inv1;
        __nv_bfloat16 h0 = __float2bfloat16(v0), h1 = __float2bfloat16(v1);
        __nv_bfloat16 h2 = __float2bfloat16(v2), h3 = __float2bfloat16(v3);
        *(u32*)(chi + r0off + col) = (u32)__bfloat16_as_ushort(h0) | ((u32)__bfloat16_as_ushort(h1) << 16);
        *(u32*)(chi + r8off + col) = (u32)__bfloat16_as_ushort(h2) | ((u32)__bfloat16_as_ushort(h3) << 16);
        *(u32*)(clo + r0off + col) = pack_bf2(v0 - __bfloat162float(h0), v1 - __bfloat162float(h1));
        *(u32*)(clo + r8off + col) = pack_bf2(v2 - __bfloat162float(h2), v3 - __bfloat162float(h3));
    }
}

// ---------------------------------------------------------------------------
extern "C" void kernel_launch(void* const* d_in, const int* in_sizes, int n_in,
                              void* d_out, int out_size)
{
    (void)in_sizes; (void)n_in; (void)out_size;
    const float* x_q = (const float*)d_in[0];
    const float* x_k = (const float*)d_in[1];
    const float* x_v = (const float*)d_in[2];
    const float* Wq  = (const float*)d_in[3];
    const float* bq  = (const float*)d_in[4];
    const float* Wk  = (const float*)d_in[5];
    const float* bk  = (const float*)d_in[6];
    const float* Wv  = (const float*)d_in[7];
    const float* bv  = (const float*)d_in[8];
    const float* Wo  = (const float*)d_in[9];
    const float* bo  = (const float*)d_in[10];
    float* out = (float*)d_out;

    __nv_bfloat16 *qh, *ql, *kh, *kl, *vth, *vtl, *chi, *clo, *xh, *xl, *wh, *wl;
    cudaGetSymbolAddress((void**)&qh, g_qh);
    cudaGetSymbolAddress((void**)&ql, g_ql);
    cudaGetSymbolAddress((void**)&kh, g_kh);
    cudaGetSymbolAddress((void**)&kl, g_kl);
    cudaGetSymbolAddress((void**)&vth, g_vth);
    cudaGetSymbolAddress((void**)&vtl, g_vtl);
    cudaGetSymbolAddress((void**)&chi, g_chi);
    cudaGetSymbolAddress((void**)&clo, g_clo);
    cudaGetSymbolAddress((void**)&xh, g_xh);
    cudaGetSymbolAddress((void**)&xl, g_xl);
    cudaGetSymbolAddress((void**)&wh, g_wh);
    cudaGetSymbolAddress((void**)&wl, g_wl);

    const size_t XSZ = (size_t)NM * NF;
    const size_t WSZ = (size_t)512 * 512;

    static int once = 0;
    if (!once) {
        cudaFuncSetAttribute(attn_fa2,
                             cudaFuncAttributeMaxDynamicSharedMemorySize, ATTN_BYTES);
        cudaFuncSetAttribute(proj_gemm,
                             cudaFuncAttributeMaxDynamicSharedMemorySize, GEMM_BYTES);
        cudaFuncSetAttribute(out_gemm,
                             cudaFuncAttributeMaxDynamicSharedMemorySize, GEMM_BYTES);
        once = 1;
    }

    SplitArgs sa;
    sa.src[0] = x_q; sa.src[1] = x_k; sa.src[2] = x_v;
    sa.src[3] = Wq;  sa.src[4] = Wk;  sa.src[5] = Wv; sa.src[6] = Wo;
    for (int i = 0; i < 3; i++) { sa.hi[i] = xh + i * XSZ; sa.lo[i] = xl + i * XSZ; }
    for (int i = 0; i < 4; i++) { sa.hi[3 + i] = wh + i * WSZ; sa.lo[3 + i] = wl + i * WSZ; }
    split_all<<<13312, 256>>>(sa);

    ProjArgs pa;
    for (int i = 0; i < 3; i++) {
        pa.xh[i] = xh + i * XSZ; pa.xl[i] = xl + i * XSZ;
        pa.wh[i] = wh + i * WSZ; pa.wl[i] = wl + i * WSZ;
    }
    pa.bias[0] = bq; pa.bias[1] = bk; pa.bias[2] = bv;
    pa.oh[0] = qh;  pa.ol[0] = ql;
    pa.oh[1] = kh;  pa.ol[1] = kl;
    pa.oh[2] = vth; pa.ol[2] = vtl;
    proj_gemm<<<dim3(NM / 128, 8, 3), 256, GEMM_BYTES>>>(pa);

    attn_fa2<<<dim3(NS / 128, NB * NH), 256, ATTN_BYTES>>>(qh, ql, kh, kl, vth, vtl, chi, clo);

    out_gemm<<<dim3(NM / 128, 8), 256, GEMM_BYTES>>>(chi, clo, wh + 3 * WSZ, wl + 3 * WSZ, bo, out);
}